// round 2
// baseline (speedup 1.0000x reference)
#include <cuda_runtime.h>
#include <math.h>

#define S_LEN 256
#define BATCH 64
#define FEAT  256
#define HID   768
#define GATES 3072
#define TLEN  32
#define OUT_ENC_OFF (TLEN*BATCH*FEAT)

static __device__ float g_xg[(size_t)S_LEN*BATCH*GATES]; // 201 MB scratch (static, no alloc)
static __device__ float g_h[2][BATCH*HID];
static __device__ float g_c[2][BATCH*HID];
static __device__ float g_h1[BATCH*HID];
static __device__ float g_hd[2][HID];

__device__ __forceinline__ float sigf(float x){ return 1.0f/(1.0f+expf(-x)); }

__global__ void k_init() {
    int i = blockIdx.x*blockDim.x + threadIdx.x;
    if (i < BATCH*HID) { g_h[0][i] = 0.f; g_c[0][i] = 0.f; }
    if (i < HID) g_hd[0][i] = 0.f;
}

// xg[t*B+b][r] = sum_k x[t*B+b][k]*Wih0[r][k] + bih0[r]+bhh0[r]
// M=16384, N=3072, K=256 ; BM=BN=128, BK=8, 256 threads, 8x8/thread
__global__ __launch_bounds__(256) void k_xgates(
    const float* __restrict__ X, const float* __restrict__ W,
    const float* __restrict__ b1, const float* __restrict__ b2)
{
    __shared__ float As[8][128];
    __shared__ float Bs[8][128];
    const int bm = blockIdx.y * 128;
    const int bn = blockIdx.x * 128;
    const int tid = threadIdx.x;
    const int tr = (tid >> 4) << 3;
    const int tc = (tid & 15) << 3;
    const int lr = tid >> 1;
    const int lc = (tid & 1) << 2;
    float acc[8][8];
#pragma unroll
    for (int i = 0; i < 8; i++)
#pragma unroll
        for (int j = 0; j < 8; j++) acc[i][j] = 0.f;

    for (int k0 = 0; k0 < FEAT; k0 += 8) {
        float4 a4 = *(const float4*)(X + (size_t)(bm + lr) * FEAT + k0 + lc);
        float4 b4 = *(const float4*)(W + (size_t)(bn + lr) * FEAT + k0 + lc);
        As[lc+0][lr]=a4.x; As[lc+1][lr]=a4.y; As[lc+2][lr]=a4.z; As[lc+3][lr]=a4.w;
        Bs[lc+0][lr]=b4.x; Bs[lc+1][lr]=b4.y; Bs[lc+2][lr]=b4.z; Bs[lc+3][lr]=b4.w;
        __syncthreads();
#pragma unroll
        for (int k = 0; k < 8; k++) {
            float ar[8], br[8];
            *(float4*)(ar)   = *(const float4*)&As[k][tr];
            *(float4*)(ar+4) = *(const float4*)&As[k][tr+4];
            *(float4*)(br)   = *(const float4*)&Bs[k][tc];
            *(float4*)(br+4) = *(const float4*)&Bs[k][tc+4];
#pragma unroll
            for (int i = 0; i < 8; i++)
#pragma unroll
                for (int j = 0; j < 8; j++)
                    acc[i][j] = fmaf(ar[i], br[j], acc[i][j]);
        }
        __syncthreads();
    }
    float biasv[8];
#pragma unroll
    for (int j = 0; j < 8; j++) biasv[j] = b1[bn+tc+j] + b2[bn+tc+j];
#pragma unroll
    for (int i = 0; i < 8; i++) {
        float4 o0, o1;
        o0.x = acc[i][0]+biasv[0]; o0.y = acc[i][1]+biasv[1];
        o0.z = acc[i][2]+biasv[2]; o0.w = acc[i][3]+biasv[3];
        o1.x = acc[i][4]+biasv[4]; o1.y = acc[i][5]+biasv[5];
        o1.z = acc[i][6]+biasv[6]; o1.w = acc[i][7]+biasv[7];
        float* dst = &g_xg[(size_t)(bm+tr+i)*GATES + bn+tc];
        *(float4*)dst = o0;
        *(float4*)(dst+4) = o1;
    }
}

// One LSTM cell step for B=64: gates = h_in @ W^T (+ xg row or +b1+b2), fused cell.
// Each block owns 8 hidden units = 32 gate rows (gate = col>>3, unit = u0 + (col&7)).
// Grid 96 blocks x 256 threads. Thread: col tc=tid&31, M-tile 8 rows (tr=tid>>5).
__global__ __launch_bounds__(256) void k_cell(
    const float* __restrict__ h_in, const float* __restrict__ W,
    const float* __restrict__ xg,
    const float* __restrict__ b1, const float* __restrict__ b2,
    const float* __restrict__ c_in,
    float* __restrict__ h_out, float* __restrict__ c_out,
    float* __restrict__ h_copy)
{
    __shared__ float hs[64][36];
    __shared__ float ws[32][36];
    __shared__ float gex[32][65];
    const int tid = threadIdx.x;
    const int u0 = blockIdx.x * 8;
    const int tc = tid & 31;
    const int tr = tid >> 5;
    const int row_c = (tc >> 3) * HID + u0 + (tc & 7);

    const int hb = tid >> 2;
    const int hk = (tid & 3) << 3;
    const int wc = tid >> 3;
    const int wk = (tid & 7) << 2;
    const int row_w = (wc >> 3) * HID + u0 + (wc & 7);

    float acc[8];
#pragma unroll
    for (int i = 0; i < 8; i++) acc[i] = 0.f;

    for (int k0 = 0; k0 < HID; k0 += 32) {
        float4 hv0 = *(const float4*)(h_in + (size_t)hb * HID + k0 + hk);
        float4 hv1 = *(const float4*)(h_in + (size_t)hb * HID + k0 + hk + 4);
        float4 wv  = *(const float4*)(W + (size_t)row_w * HID + k0 + wk);
        *(float4*)&hs[hb][hk]     = hv0;
        *(float4*)&hs[hb][hk + 4] = hv1;
        *(float4*)&ws[wc][wk]     = wv;
        __syncthreads();
#pragma unroll
        for (int kk = 0; kk < 32; kk += 4) {
            float4 w4 = *(const float4*)&ws[tc][kk];
#pragma unroll
            for (int i = 0; i < 8; i++) {
                float4 h4 = *(const float4*)&hs[tr*8 + i][kk];
                acc[i] = fmaf(h4.x, w4.x, acc[i]);
                acc[i] = fmaf(h4.y, w4.y, acc[i]);
                acc[i] = fmaf(h4.z, w4.z, acc[i]);
                acc[i] = fmaf(h4.w, w4.w, acc[i]);
            }
        }
        __syncthreads();
    }

    if (xg) {
#pragma unroll
        for (int i = 0; i < 8; i++)
            acc[i] += xg[(size_t)(tr*8 + i) * GATES + row_c];
    } else {
        float bb = b1[row_c] + b2[row_c];
#pragma unroll
        for (int i = 0; i < 8; i++) acc[i] += bb;
    }
#pragma unroll
    for (int i = 0; i < 8; i++) gex[tc][tr*8 + i] = acc[i];
    __syncthreads();

    for (int it = tid; it < 512; it += 256) {
        int b = it >> 3, ul = it & 7;
        float iv = gex[ul][b];
        float fv = gex[8 + ul][b];
        float gv = gex[16 + ul][b];
        float ov = gex[24 + ul][b];
        float cp = c_in ? c_in[b * HID + u0 + ul] : 0.f;
        float cn = sigf(fv) * cp + sigf(iv) * tanhf(gv);
        float hn = sigf(ov) * tanhf(cn);
        int idx = b * HID + u0 + ul;
        h_out[idx] = hn;
        if (c_out) c_out[idx] = cn;
        if (h_copy) h_copy[idx] = hn;
    }
}

// Decoder step (batch-invariant, batch=1): gates(3072) = W @ h(768) + b ; cell with c_prev=0.
__global__ __launch_bounds__(256) void k_dec(
    const float* __restrict__ h_in, const float* __restrict__ W,
    const float* __restrict__ b1, const float* __restrict__ b2,
    float* __restrict__ h_out)
{
    const int tid = threadIdx.x;
    const int u0 = blockIdx.x * 8;
    const int rl = tid >> 3;
    const int s  = tid & 7;
    const int row = (rl >> 3) * HID + u0 + (rl & 7);
    const float4* W4 = (const float4*)(W + (size_t)row * HID);
    const float4* h4 = (const float4*)h_in;
    float sum = 0.f;
#pragma unroll
    for (int j = 0; j < 24; j++) {
        float4 w = W4[s + (j << 3)];
        float4 h = h4[s + (j << 3)];
        sum += w.x*h.x + w.y*h.y + w.z*h.z + w.w*h.w;
    }
#pragma unroll
    for (int off = 4; off > 0; off >>= 1)
        sum += __shfl_down_sync(0xffffffffu, sum, off, 8);
    __shared__ float gs[32];
    if (s == 0) gs[rl] = sum + b1[row] + b2[row];
    __syncthreads();
    if (tid < 8) {
        float iv = gs[tid], gv = gs[16+tid], ov = gs[24+tid];
        float cn = sigf(iv) * tanhf(gv);         // c_prev = 0 -> forget term drops
        float hn = sigf(ov) * tanhf(cn);
        h_out[u0 + tid] = hn;
    }
}

// out_t[b][f] = h . lin_W[f] + lin_b[f], broadcast over b (decoder is batch-invariant)
__global__ __launch_bounds__(256) void k_dec_out(
    const float* __restrict__ h, const float* __restrict__ linW,
    const float* __restrict__ linb, float* __restrict__ out_t)
{
    const int tid = threadIdx.x;
    const int f0 = blockIdx.x * 8;
    const int fl = tid >> 5;
    const int lane = tid & 31;
    const int f = f0 + fl;
    const float4* W4 = (const float4*)(linW + (size_t)f * HID);
    const float4* h4 = (const float4*)h;
    float sum = 0.f;
#pragma unroll
    for (int j = 0; j < 6; j++) {
        float4 w = W4[lane + (j << 5)];
        float4 hv = h4[lane + (j << 5)];
        sum += w.x*hv.x + w.y*hv.y + w.z*hv.z + w.w*hv.w;
    }
#pragma unroll
    for (int off = 16; off > 0; off >>= 1)
        sum += __shfl_down_sync(0xffffffffu, sum, off);
    __shared__ float os[8];
    if (lane == 0) os[fl] = sum + linb[f];
    __syncthreads();
    {
        int b = tid >> 3;
        int j = tid & 7;
        float v = os[j];
        out_t[b * FEAT + f0 + j] = v;
        out_t[(b + 32) * FEAT + f0 + j] = v;
    }
}

extern "C" void kernel_launch(void* const* d_in, const int* in_sizes, int n_in,
                              void* d_out, int out_size)
{
    const float* x     = (const float*)d_in[0];
    const float* Wih0  = (const float*)d_in[1];
    const float* bih0  = (const float*)d_in[3];
    const float* bhh0  = (const float*)d_in[4];
    const float* eWih  = (const float*)d_in[5];
    const float* ebih  = (const float*)d_in[7];
    const float* ebhh  = (const float*)d_in[8];
    const float* dWih  = (const float*)d_in[9];
    const float* dbih  = (const float*)d_in[11];
    const float* dbhh  = (const float*)d_in[12];
    const float* linW  = (const float*)d_in[13];
    const float* linb  = (const float*)d_in[14];
    const float* Whh0  = (const float*)d_in[2];
    float* out = (float*)d_out;

    float *p_xg, *p_h, *p_c, *p_h1, *p_hd;
    cudaGetSymbolAddress((void**)&p_xg, g_xg);
    cudaGetSymbolAddress((void**)&p_h,  g_h);
    cudaGetSymbolAddress((void**)&p_c,  g_c);
    cudaGetSymbolAddress((void**)&p_h1, g_h1);
    cudaGetSymbolAddress((void**)&p_hd, g_hd);

    k_init<<<192, 256>>>();
    k_xgates<<<dim3(24, 128), 256>>>(x, Wih0, bih0, bhh0);

    for (int t = 0; t < S_LEN; t++) {
        k_cell<<<96, 256>>>(p_h + (t & 1) * BATCH * HID, Whh0,
                            p_xg + (size_t)t * BATCH * GATES,
                            nullptr, nullptr,
                            p_c + (t & 1) * BATCH * HID,
                            p_h + ((t + 1) & 1) * BATCH * HID,
                            p_c + ((t + 1) & 1) * BATCH * HID,
                            nullptr);
    }
    // final h is in buffer 0; it is encoder_hidden layer 0
    cudaMemcpyAsync(out + OUT_ENC_OFF, p_h, BATCH * HID * sizeof(float),
                    cudaMemcpyDeviceToDevice);
    // encoder layer 1 (zero state -> Whh term vanishes)
    k_cell<<<96, 256>>>(p_h, eWih, nullptr, ebih, ebhh, nullptr,
                        p_h1, nullptr, out + OUT_ENC_OFF + BATCH * HID);
    // encoder layer 2
    k_cell<<<96, 256>>>(p_h1, eWih + (size_t)GATES * HID, nullptr,
                        ebih + GATES, ebhh + GATES, nullptr,
                        p_h + BATCH * HID, nullptr,
                        out + OUT_ENC_OFF + 2 * BATCH * HID);

    // decoder: batch-invariant, only last layer matters, initial hidden = zeros
    const float* W2  = dWih + (size_t)2 * GATES * HID;
    const float* db1 = dbih + 2 * GATES;
    const float* db2 = dbhh + 2 * GATES;
    for (int t = 0; t < TLEN; t++) {
        k_dec<<<96, 256>>>(p_hd + (t & 1) * HID, W2, db1, db2,
                           p_hd + ((t + 1) & 1) * HID);
        k_dec_out<<<32, 256>>>(p_hd + ((t + 1) & 1) * HID, linW, linb,
                               out + (size_t)t * BATCH * FEAT);
    }
}

// round 3
// speedup vs baseline: 1.7454x; 1.7454x over previous
#include <cuda_runtime.h>
#include <math.h>
#include <stdint.h>

#define S_LEN 256
#define BATCH 64
#define FEAT  256
#define HID   768
#define GATES 3072
#define TLEN  32
#define OUT_ENC_OFF (TLEN*BATCH*FEAT)

#define NB   128   // persistent blocks (1 per SM, <=148)
#define UPB  6     // hidden units per block (128*6 = 768)
#define RPB  24    // gate rows per block (4 gates * 6 units)
#define CHK  128   // K-chunk of h
#define NCH  6     // 768 / 128

static __device__ float g_xg[(size_t)S_LEN*BATCH*GATES]; // 201 MB scratch
static __device__ float g_h[2][BATCH*HID];
static __device__ float g_h1[BATCH*HID];
static __device__ float g_hd[2][HID];
static __device__ unsigned g_bar;

__device__ __forceinline__ float sigf(float x){ return 1.0f/(1.0f+expf(-x)); }

__global__ void k_init() {
    int i = blockIdx.x*blockDim.x + threadIdx.x;
    if (i < BATCH*HID) g_h[0][i] = 0.f;
    if (i < HID) g_hd[0][i] = 0.f;
    if (i == 0) g_bar = 0u;
}

// xg[t*B+b][r] = x[t*B+b]·Wih0[r] + bih0[r]+bhh0[r]; M=16384,N=3072,K=256
__global__ __launch_bounds__(256) void k_xgates(
    const float* __restrict__ X, const float* __restrict__ W,
    const float* __restrict__ b1, const float* __restrict__ b2)
{
    __shared__ float As[8][128];
    __shared__ float Bs[8][128];
    const int bm = blockIdx.y * 128;
    const int bn = blockIdx.x * 128;
    const int tid = threadIdx.x;
    const int tr = (tid >> 4) << 3;
    const int tc = (tid & 15) << 3;
    const int lr = tid >> 1;
    const int lc = (tid & 1) << 2;
    float acc[8][8];
#pragma unroll
    for (int i = 0; i < 8; i++)
#pragma unroll
        for (int j = 0; j < 8; j++) acc[i][j] = 0.f;

    for (int k0 = 0; k0 < FEAT; k0 += 8) {
        float4 a4 = *(const float4*)(X + (size_t)(bm + lr) * FEAT + k0 + lc);
        float4 b4 = *(const float4*)(W + (size_t)(bn + lr) * FEAT + k0 + lc);
        As[lc+0][lr]=a4.x; As[lc+1][lr]=a4.y; As[lc+2][lr]=a4.z; As[lc+3][lr]=a4.w;
        Bs[lc+0][lr]=b4.x; Bs[lc+1][lr]=b4.y; Bs[lc+2][lr]=b4.z; Bs[lc+3][lr]=b4.w;
        __syncthreads();
#pragma unroll
        for (int k = 0; k < 8; k++) {
            float ar[8], br[8];
            *(float4*)(ar)   = *(const float4*)&As[k][tr];
            *(float4*)(ar+4) = *(const float4*)&As[k][tr+4];
            *(float4*)(br)   = *(const float4*)&Bs[k][tc];
            *(float4*)(br+4) = *(const float4*)&Bs[k][tc+4];
#pragma unroll
            for (int i = 0; i < 8; i++)
#pragma unroll
                for (int j = 0; j < 8; j++)
                    acc[i][j] = fmaf(ar[i], br[j], acc[i][j]);
        }
        __syncthreads();
    }
    float biasv[8];
#pragma unroll
    for (int j = 0; j < 8; j++) biasv[j] = b1[bn+tc+j] + b2[bn+tc+j];
#pragma unroll
    for (int i = 0; i < 8; i++) {
        float4 o0, o1;
        o0.x = acc[i][0]+biasv[0]; o0.y = acc[i][1]+biasv[1];
        o0.z = acc[i][2]+biasv[2]; o0.w = acc[i][3]+biasv[3];
        o1.x = acc[i][4]+biasv[4]; o1.y = acc[i][5]+biasv[5];
        o1.z = acc[i][6]+biasv[6]; o1.w = acc[i][7]+biasv[7];
        float* dst = &g_xg[(size_t)(bm+tr+i)*GATES + bn+tc];
        *(float4*)dst = o0;
        *(float4*)(dst+4) = o1;
    }
}

// ---------------- persistent encoder layer-0 LSTM ----------------
// Block b owns units u0=6b..6b+5 (24 gate rows). Whh slice resident in smem.
// Per step: gates = Whh_slice @ h_prev^T (+xg), fused cell, grid barrier.
__device__ __forceinline__ void issue_chunk(const float* __restrict__ h_in,
                                            int c, float* buf, int tid) {
    uint32_t s0 = (uint32_t)__cvta_generic_to_shared(buf);
#pragma unroll
    for (int i = 0; i < 8; i++) {
        int e = tid + i * 256;
        int b = e >> 5, q = e & 31;
        int qs = q ^ (b & 7);                       // SW swizzle for conflict-free reads
        uint32_t dst = s0 + (uint32_t)((b * 32 + qs) * 16);
        const float* src = h_in + (size_t)b * HID + c * CHK + q * 4;
        asm volatile("cp.async.cg.shared.global [%0], [%1], 16;" :: "r"(dst), "l"(src));
    }
}

__global__ __launch_bounds__(256) void k_enc(const float* __restrict__ Whh)
{
    extern __shared__ float sm[];
    float* Ws  = sm;                        // 24*768   = 18432 f
    float* hs  = Ws + RPB * HID;            // 2*64*128 = 16384 f
    float* gex = hs + 2 * BATCH * CHK;      // 24*65    = 1560 f
    float* c_s = gex + RPB * 65;            // 6*64     = 384 f

    const int tid  = threadIdx.x;
    const int w    = tid >> 5;
    const int lane = tid & 31;
    const int u0   = blockIdx.x * UPB;
    const int r0   = 3 * w;                 // this warp's 3 local rows

    // load resident weight slice: local row r = g*6+j  <->  global row g*768+u0+j
    for (int e = tid; e < RPB * (HID / 4); e += 256) {
        int r = e / (HID / 4), c4 = e % (HID / 4);
        int grow = (r / UPB) * HID + u0 + (r % UPB);
        ((float4*)Ws)[e] = ((const float4*)(Whh + (size_t)grow * HID))[c4];
    }
    for (int e = tid; e < UPB * BATCH; e += 256) c_s[e] = 0.f;

    int growr[3];
#pragma unroll
    for (int i = 0; i < 3; i++)
        growr[i] = ((r0 + i) / UPB) * HID + u0 + ((r0 + i) % UPB);

    __syncthreads();

    for (int t = 0; t < S_LEN; t++) {
        const float* h_in  = g_h[t & 1];
        float*       h_out = g_h[(t + 1) & 1];
        const float* xg    = g_xg + (size_t)t * BATCH * GATES;

        // prefetch this thread's 6 xg values early (DRAM stream)
        float xv[3][2];
#pragma unroll
        for (int i = 0; i < 3; i++) {
            xv[i][0] = __ldcg(xg + (size_t)lane * GATES + growr[i]);
            xv[i][1] = __ldcg(xg + (size_t)(lane + 32) * GATES + growr[i]);
        }

        float a00=0.f,a01=0.f,a10=0.f,a11=0.f,a20=0.f,a21=0.f;

        issue_chunk(h_in, 0, hs, tid);
        asm volatile("cp.async.commit_group;");

        for (int c = 0; c < NCH; c++) {
            if (c + 1 < NCH) {
                issue_chunk(h_in, c + 1, hs + ((c + 1) & 1) * BATCH * CHK, tid);
                asm volatile("cp.async.commit_group;");
                asm volatile("cp.async.wait_group 1;");
            } else {
                asm volatile("cp.async.wait_group 0;");
            }
            __syncthreads();
            const float4* h4  = (const float4*)(hs + (c & 1) * BATCH * CHK);
            const float4* w4a = (const float4*)(Ws + (r0 + 0) * HID + c * CHK);
            const float4* w4b = (const float4*)(Ws + (r0 + 1) * HID + c * CHK);
            const float4* w4c = (const float4*)(Ws + (r0 + 2) * HID + c * CHK);
            const int sw = lane & 7;
#pragma unroll 8
            for (int q = 0; q < 32; q++) {
                int qs = q ^ sw;
                float4 h0 = h4[lane * 32 + qs];
                float4 h1 = h4[(lane + 32) * 32 + qs];
                float4 wa = w4a[q];
                float4 wb = w4b[q];
                float4 wc = w4c[q];
                a00 = fmaf(wa.x,h0.x,fmaf(wa.y,h0.y,fmaf(wa.z,h0.z,fmaf(wa.w,h0.w,a00))));
                a01 = fmaf(wa.x,h1.x,fmaf(wa.y,h1.y,fmaf(wa.z,h1.z,fmaf(wa.w,h1.w,a01))));
                a10 = fmaf(wb.x,h0.x,fmaf(wb.y,h0.y,fmaf(wb.z,h0.z,fmaf(wb.w,h0.w,a10))));
                a11 = fmaf(wb.x,h1.x,fmaf(wb.y,h1.y,fmaf(wb.z,h1.z,fmaf(wb.w,h1.w,a11))));
                a20 = fmaf(wc.x,h0.x,fmaf(wc.y,h0.y,fmaf(wc.z,h0.z,fmaf(wc.w,h0.w,a20))));
                a21 = fmaf(wc.x,h1.x,fmaf(wc.y,h1.y,fmaf(wc.z,h1.z,fmaf(wc.w,h1.w,a21))));
            }
            __syncthreads();
        }

        gex[(r0+0)*65 + lane]      = a00 + xv[0][0];
        gex[(r0+0)*65 + lane + 32] = a01 + xv[0][1];
        gex[(r0+1)*65 + lane]      = a10 + xv[1][0];
        gex[(r0+1)*65 + lane + 32] = a11 + xv[1][1];
        gex[(r0+2)*65 + lane]      = a20 + xv[2][0];
        gex[(r0+2)*65 + lane + 32] = a21 + xv[2][1];
        __syncthreads();

        // fused cell for this block's 6 units x 64 batches
        for (int e = tid; e < UPB * BATCH; e += 256) {
            int u = e % UPB, b = e / UPB;
            float iv = gex[(u)      * 65 + b];
            float fv = gex[(6 + u)  * 65 + b];
            float gv = gex[(12 + u) * 65 + b];
            float ov = gex[(18 + u) * 65 + b];
            float cp = c_s[u * BATCH + b];
            float cn = sigf(fv) * cp + sigf(iv) * tanhf(gv);
            float hn = sigf(ov) * tanhf(cn);
            c_s[u * BATCH + b] = cn;
            __stcg(&h_out[b * HID + u0 + u], hn);
        }

        // grid barrier
        __threadfence();
        __syncthreads();
        if (tid == 0) {
            atomicAdd(&g_bar, 1u);
            unsigned target = (unsigned)(t + 1) * NB;
            while (*((volatile unsigned*)&g_bar) < target) {}
        }
        __syncthreads();
    }
}

// One LSTM cell step for B=64 (used for encoder layers 1-2; zero state).
__global__ __launch_bounds__(256) void k_cell(
    const float* __restrict__ h_in, const float* __restrict__ W,
    const float* __restrict__ xg,
    const float* __restrict__ b1, const float* __restrict__ b2,
    const float* __restrict__ c_in,
    float* __restrict__ h_out, float* __restrict__ c_out,
    float* __restrict__ h_copy)
{
    __shared__ float hs[64][36];
    __shared__ float ws[32][36];
    __shared__ float gexs[32][65];
    const int tid = threadIdx.x;
    const int u0 = blockIdx.x * 8;
    const int tc = tid & 31;
    const int tr = tid >> 5;
    const int row_c = (tc >> 3) * HID + u0 + (tc & 7);

    const int hb = tid >> 2;
    const int hk = (tid & 3) << 3;
    const int wcc = tid >> 3;
    const int wk = (tid & 7) << 2;
    const int row_w = (wcc >> 3) * HID + u0 + (wcc & 7);

    float acc[8];
#pragma unroll
    for (int i = 0; i < 8; i++) acc[i] = 0.f;

    for (int k0 = 0; k0 < HID; k0 += 32) {
        float4 hv0 = *(const float4*)(h_in + (size_t)hb * HID + k0 + hk);
        float4 hv1 = *(const float4*)(h_in + (size_t)hb * HID + k0 + hk + 4);
        float4 wv  = *(const float4*)(W + (size_t)row_w * HID + k0 + wk);
        *(float4*)&hs[hb][hk]     = hv0;
        *(float4*)&hs[hb][hk + 4] = hv1;
        *(float4*)&ws[wcc][wk]    = wv;
        __syncthreads();
#pragma unroll
        for (int kk = 0; kk < 32; kk += 4) {
            float4 w4 = *(const float4*)&ws[tc][kk];
#pragma unroll
            for (int i = 0; i < 8; i++) {
                float4 h4 = *(const float4*)&hs[tr*8 + i][kk];
                acc[i] = fmaf(h4.x, w4.x, acc[i]);
                acc[i] = fmaf(h4.y, w4.y, acc[i]);
                acc[i] = fmaf(h4.z, w4.z, acc[i]);
                acc[i] = fmaf(h4.w, w4.w, acc[i]);
            }
        }
        __syncthreads();
    }

    if (xg) {
#pragma unroll
        for (int i = 0; i < 8; i++)
            acc[i] += xg[(size_t)(tr*8 + i) * GATES + row_c];
    } else {
        float bb = b1[row_c] + b2[row_c];
#pragma unroll
        for (int i = 0; i < 8; i++) acc[i] += bb;
    }
#pragma unroll
    for (int i = 0; i < 8; i++) gexs[tc][tr*8 + i] = acc[i];
    __syncthreads();

    for (int it = tid; it < 512; it += 256) {
        int b = it >> 3, ul = it & 7;
        float iv = gexs[ul][b];
        float fv = gexs[8 + ul][b];
        float gv = gexs[16 + ul][b];
        float ov = gexs[24 + ul][b];
        float cp = c_in ? c_in[b * HID + u0 + ul] : 0.f;
        float cn = sigf(fv) * cp + sigf(iv) * tanhf(gv);
        float hn = sigf(ov) * tanhf(cn);
        int idx = b * HID + u0 + ul;
        h_out[idx] = hn;
        if (c_out) c_out[idx] = cn;
        if (h_copy) h_copy[idx] = hn;
    }
}

// Decoder step (batch-invariant): gates(3072) = W @ h(768) + b ; cell with c_prev=0.
__global__ __launch_bounds__(256) void k_dec(
    const float* __restrict__ h_in, const float* __restrict__ W,
    const float* __restrict__ b1, const float* __restrict__ b2,
    float* __restrict__ h_out)
{
    const int tid = threadIdx.x;
    const int u0 = blockIdx.x * 8;
    const int rl = tid >> 3;
    const int s  = tid & 7;
    const int row = (rl >> 3) * HID + u0 + (rl & 7);
    const float4* W4 = (const float4*)(W + (size_t)row * HID);
    const float4* h4 = (const float4*)h_in;
    float sum = 0.f;
#pragma unroll
    for (int j = 0; j < 24; j++) {
        float4 w = W4[s + (j << 3)];
        float4 h = h4[s + (j << 3)];
        sum += w.x*h.x + w.y*h.y + w.z*h.z + w.w*h.w;
    }
#pragma unroll
    for (int off = 4; off > 0; off >>= 1)
        sum += __shfl_down_sync(0xffffffffu, sum, off, 8);
    __shared__ float gs[32];
    if (s == 0) gs[rl] = sum + b1[row] + b2[row];
    __syncthreads();
    if (tid < 8) {
        float iv = gs[tid], gv = gs[16+tid], ov = gs[24+tid];
        float cn = sigf(iv) * tanhf(gv);
        float hn = sigf(ov) * tanhf(cn);
        h_out[u0 + tid] = hn;
    }
}

__global__ __launch_bounds__(256) void k_dec_out(
    const float* __restrict__ h, const float* __restrict__ linW,
    const float* __restrict__ linb, float* __restrict__ out_t)
{
    const int tid = threadIdx.x;
    const int f0 = blockIdx.x * 8;
    const int fl = tid >> 5;
    const int lane = tid & 31;
    const int f = f0 + fl;
    const float4* W4 = (const float4*)(linW + (size_t)f * HID);
    const float4* h4 = (const float4*)h;
    float sum = 0.f;
#pragma unroll
    for (int j = 0; j < 6; j++) {
        float4 w = W4[lane + (j << 5)];
        float4 hv = h4[lane + (j << 5)];
        sum += w.x*hv.x + w.y*hv.y + w.z*hv.z + w.w*hv.w;
    }
#pragma unroll
    for (int off = 16; off > 0; off >>= 1)
        sum += __shfl_down_sync(0xffffffffu, sum, off);
    __shared__ float os[8];
    if (lane == 0) os[fl] = sum + linb[f];
    __syncthreads();
    {
        int b = tid >> 3;
        int j = tid & 7;
        float v = os[j];
        out_t[b * FEAT + f0 + j] = v;
        out_t[(b + 32) * FEAT + f0 + j] = v;
    }
}

extern "C" void kernel_launch(void* const* d_in, const int* in_sizes, int n_in,
                              void* d_out, int out_size)
{
    const float* x     = (const float*)d_in[0];
    const float* Wih0  = (const float*)d_in[1];
    const float* Whh0  = (const float*)d_in[2];
    const float* bih0  = (const float*)d_in[3];
    const float* bhh0  = (const float*)d_in[4];
    const float* eWih  = (const float*)d_in[5];
    const float* ebih  = (const float*)d_in[7];
    const float* ebhh  = (const float*)d_in[8];
    const float* dWih  = (const float*)d_in[9];
    const float* dbih  = (const float*)d_in[11];
    const float* dbhh  = (const float*)d_in[12];
    const float* linW  = (const float*)d_in[13];
    const float* linb  = (const float*)d_in[14];
    float* out = (float*)d_out;

    float *p_h, *p_h1, *p_hd;
    cudaGetSymbolAddress((void**)&p_h,  g_h);
    cudaGetSymbolAddress((void**)&p_h1, g_h1);
    cudaGetSymbolAddress((void**)&p_hd, g_hd);

    static int smem_set = 0;
    if (!smem_set) {
        cudaFuncSetAttribute(k_enc, cudaFuncAttributeMaxDynamicSharedMemorySize, 150528);
        smem_set = 1;
    }

    k_init<<<192, 256>>>();
    k_xgates<<<dim3(24, 128), 256>>>(x, Wih0, bih0, bhh0);

    const int smem_bytes = (RPB*HID + 2*BATCH*CHK + RPB*65 + UPB*BATCH) * 4;
    k_enc<<<NB, 256, smem_bytes>>>(Whh0);

    // final h (encoder_hidden layer 0) is in g_h[0]
    cudaMemcpyAsync(out + OUT_ENC_OFF, p_h, BATCH * HID * sizeof(float),
                    cudaMemcpyDeviceToDevice);
    // encoder layer 1 (zero state -> Whh term vanishes)
    k_cell<<<96, 256>>>(p_h, eWih, nullptr, ebih, ebhh, nullptr,
                        p_h1, nullptr, out + OUT_ENC_OFF + BATCH * HID);
    // encoder layer 2
    k_cell<<<96, 256>>>(p_h1, eWih + (size_t)GATES * HID, nullptr,
                        ebih + GATES, ebhh + GATES, nullptr,
                        p_h + BATCH * HID, nullptr,
                        out + OUT_ENC_OFF + 2 * BATCH * HID);

    // decoder: batch-invariant, only last layer matters, initial hidden = zeros
    const float* W2  = dWih + (size_t)2 * GATES * HID;
    const float* db1 = dbih + 2 * GATES;
    const float* db2 = dbhh + 2 * GATES;
    for (int t = 0; t < TLEN; t++) {
        k_dec<<<96, 256>>>(p_hd + (t & 1) * HID, W2, db1, db2,
                           p_hd + ((t + 1) & 1) * HID);
        k_dec_out<<<32, 256>>>(p_hd + ((t + 1) & 1) * HID, linW, linb,
                               out + (size_t)t * BATCH * FEAT);
    }
}

// round 4
// speedup vs baseline: 1.8283x; 1.0475x over previous
#include <cuda_runtime.h>
#include <math.h>
#include <stdint.h>

#define S_LEN 256
#define BATCH 64
#define FEAT  256
#define HID   768
#define GATES 3072
#define TLEN  32
#define OUT_ENC_OFF (TLEN*BATCH*FEAT)

#define NB   128   // persistent blocks (1 per SM)
#define UPB  6     // hidden units per block
#define RPB  24    // gate rows per block
#define CHK  128   // K-chunk staged per phase per half
#define KHALF 384

static __device__ float g_xg[(size_t)S_LEN*BATCH*GATES];
static __device__ float g_h[2][BATCH*HID];
static __device__ float g_h1[BATCH*HID];
static __device__ float g_hd[2][HID];
static __device__ unsigned g_bar;

__device__ __forceinline__ float sigf(float x){ return 1.0f/(1.0f+expf(-x)); }

__device__ __forceinline__ void ffma2(unsigned long long &d, unsigned long long a, unsigned long long b){
    asm("fma.rn.f32x2 %0, %1, %2, %0;" : "+l"(d) : "l"(a), "l"(b));
}
__device__ __forceinline__ void pack2(unsigned long long &d, float a){
    asm("mov.b64 %0, {%1, %1};" : "=l"(d) : "f"(a));
}
__device__ __forceinline__ void unpack2(float &lo, float &hi, unsigned long long v){
    asm("mov.b64 {%0, %1}, %2;" : "=f"(lo), "=f"(hi) : "l"(v));
}
__device__ __forceinline__ void lds2u64(unsigned long long &a, unsigned long long &b, uint32_t addr){
    asm volatile("ld.shared.v2.u64 {%0, %1}, [%2];" : "=l"(a), "=l"(b) : "r"(addr));
}

__global__ void k_init() {
    int i = blockIdx.x*blockDim.x + threadIdx.x;
    if (i < BATCH*HID) g_h[0][i] = 0.f;
    if (i < HID) g_hd[0][i] = 0.f;
    if (i == 0) g_bar = 0u;
}

// xg = X @ Wih0^T + b ; M=16384, N=3072, K=256 ; FFMA2 inner product
__global__ __launch_bounds__(256) void k_xgates(
    const float* __restrict__ X, const float* __restrict__ W,
    const float* __restrict__ b1, const float* __restrict__ b2)
{
    __shared__ float As[8][128];
    __shared__ float Bs[8][128];
    const int bm = blockIdx.y * 128;
    const int bn = blockIdx.x * 128;
    const int tid = threadIdx.x;
    const int tr = (tid >> 4) << 3;
    const int tc = (tid & 15) << 3;
    const int lr = tid >> 1;
    const int lc = (tid & 1) << 2;
    uint32_t bs_base = (uint32_t)__cvta_generic_to_shared(&Bs[0][0]);

    unsigned long long acc2[8][4];
#pragma unroll
    for (int i = 0; i < 8; i++)
#pragma unroll
        for (int j = 0; j < 4; j++) acc2[i][j] = 0ull;

    for (int k0 = 0; k0 < FEAT; k0 += 8) {
        float4 a4 = *(const float4*)(X + (size_t)(bm + lr) * FEAT + k0 + lc);
        float4 b4 = *(const float4*)(W + (size_t)(bn + lr) * FEAT + k0 + lc);
        As[lc+0][lr]=a4.x; As[lc+1][lr]=a4.y; As[lc+2][lr]=a4.z; As[lc+3][lr]=a4.w;
        Bs[lc+0][lr]=b4.x; Bs[lc+1][lr]=b4.y; Bs[lc+2][lr]=b4.z; Bs[lc+3][lr]=b4.w;
        __syncthreads();
#pragma unroll
        for (int k = 0; k < 8; k++) {
            float ar[8];
            *(float4*)(ar)   = *(const float4*)&As[k][tr];
            *(float4*)(ar+4) = *(const float4*)&As[k][tr+4];
            unsigned long long c0,c1,c2,c3;
            lds2u64(c0, c1, bs_base + (uint32_t)((k*128 + tc) * 4));
            lds2u64(c2, c3, bs_base + (uint32_t)((k*128 + tc) * 4 + 16));
#pragma unroll
            for (int i = 0; i < 8; i++) {
                unsigned long long ad; pack2(ad, ar[i]);
                ffma2(acc2[i][0], ad, c0);
                ffma2(acc2[i][1], ad, c1);
                ffma2(acc2[i][2], ad, c2);
                ffma2(acc2[i][3], ad, c3);
            }
        }
        __syncthreads();
    }
    float biasv[8];
#pragma unroll
    for (int j = 0; j < 8; j++) biasv[j] = b1[bn+tc+j] + b2[bn+tc+j];
#pragma unroll
    for (int i = 0; i < 8; i++) {
        float v[8];
#pragma unroll
        for (int j = 0; j < 4; j++) unpack2(v[2*j], v[2*j+1], acc2[i][j]);
        float4 o0, o1;
        o0.x=v[0]+biasv[0]; o0.y=v[1]+biasv[1]; o0.z=v[2]+biasv[2]; o0.w=v[3]+biasv[3];
        o1.x=v[4]+biasv[4]; o1.y=v[5]+biasv[5]; o1.z=v[6]+biasv[6]; o1.w=v[7]+biasv[7];
        float* dst = &g_xg[(size_t)(bm+tr+i)*GATES + bn+tc];
        *(float4*)dst = o0;
        *(float4*)(dst+4) = o1;
    }
}

// ---------------- persistent encoder layer-0 LSTM (FFMA2, K-split-2) -------
// Warp w: kh=w&1 (K half), rg=w>>1 (gate). Thread: 6 rows x 2 batches x 384 K.
__device__ __forceinline__ void issue_pair(const float* __restrict__ h_in,
                                           int ph, int parity,
                                           uint32_t hs_base, int tid) {
#pragma unroll
    for (int i = 0; i < 16; i++) {
        int sel = i >> 3;                 // K half
        int e = tid + (i & 7) * 256;      // 0..2047
        int b = e >> 5, q = e & 31;
        int qs = q ^ (b & 7);
        uint32_t dst = hs_base + (uint32_t)(((sel*2 + parity) * 2048 + b*32 + qs) * 16);
        const float* src = h_in + (size_t)b*HID + sel*KHALF + ph*CHK + q*4;
        asm volatile("cp.async.cg.shared.global [%0], [%1], 16;" :: "r"(dst), "l"(src));
    }
}

__global__ __launch_bounds__(256) void k_enc(const float* __restrict__ Whh)
{
    extern __shared__ float sm[];
    float* Ws  = sm;                          // 24*768 = 18432
    float* hs  = Ws + RPB*HID;                // 4*64*128 = 32768
    float* gA  = hs + 4*BATCH*CHK;            // 24*66 = 1584
    float* gB  = gA + RPB*66;                 // 1584
    float* c_s = gB + RPB*66;                 // 384

    const int tid  = threadIdx.x;
    const int w    = tid >> 5;
    const int lane = tid & 31;
    const int kh   = w & 1;
    const int rg   = w >> 1;                  // gate 0..3
    const int u0   = blockIdx.x * UPB;

    for (int e = tid; e < RPB*(HID/4); e += 256) {
        int r = e / (HID/4), c4 = e % (HID/4);
        int grow = (r/UPB)*HID + u0 + (r%UPB);
        ((float4*)Ws)[e] = ((const float4*)(Whh + (size_t)grow*HID))[c4];
    }
    for (int e = tid; e < UPB*BATCH; e += 256) c_s[e] = 0.f;

    uint32_t hs_base = (uint32_t)__cvta_generic_to_shared(hs);
    uint32_t ws_base = (uint32_t)__cvta_generic_to_shared(Ws);
    const int sw = lane & 7;

    __syncthreads();

    for (int t = 0; t < S_LEN; t++) {
        const float* h_in  = g_h[t & 1];
        float*       h_out = g_h[(t + 1) & 1];
        const float* xg    = g_xg + (size_t)t * BATCH * GATES;

        float xv[UPB][2];
        if (kh == 0) {
#pragma unroll
            for (int j = 0; j < UPB; j++) {
                int grow = rg*HID + u0 + j;
                xv[j][0] = __ldcg(xg + (size_t)lane * GATES + grow);
                xv[j][1] = __ldcg(xg + (size_t)(lane + 32) * GATES + grow);
            }
        }

        unsigned long long acc[UPB][2];
#pragma unroll
        for (int j = 0; j < UPB; j++) { acc[j][0] = 0ull; acc[j][1] = 0ull; }

        issue_pair(h_in, 0, 0, hs_base, tid);
        asm volatile("cp.async.commit_group;");

        for (int ph = 0; ph < 3; ph++) {
            if (ph < 2) {
                issue_pair(h_in, ph + 1, (ph + 1) & 1, hs_base, tid);
                asm volatile("cp.async.commit_group;");
                asm volatile("cp.async.wait_group 1;");
            } else {
                asm volatile("cp.async.wait_group 0;");
            }
            __syncthreads();
            uint32_t hb  = hs_base + (uint32_t)((kh*2 + (ph & 1)) * 32768);
            uint32_t ha0 = hb + (uint32_t)(lane * 32 * 16);
            uint32_t ha1 = hb + (uint32_t)((lane + 32) * 32 * 16);
            uint32_t wb  = ws_base + (uint32_t)(((rg*UPB)*HID + kh*KHALF + ph*CHK) * 4);
#pragma unroll 8
            for (int q = 0; q < 32; q++) {
                int qs = q ^ sw;
                unsigned long long h0a, h0b, h1a, h1b;
                lds2u64(h0a, h0b, ha0 + (uint32_t)(qs * 16));
                lds2u64(h1a, h1b, ha1 + (uint32_t)(qs * 16));
#pragma unroll
                for (int j = 0; j < UPB; j++) {
                    unsigned long long w0, w1;
                    lds2u64(w0, w1, wb + (uint32_t)(j * HID * 4 + q * 16));
                    ffma2(acc[j][0], w0, h0a); ffma2(acc[j][0], w1, h0b);
                    ffma2(acc[j][1], w0, h1a); ffma2(acc[j][1], w1, h1b);
                }
            }
            __syncthreads();
        }

        float* dst = kh ? gB : gA;
#pragma unroll
        for (int j = 0; j < UPB; j++) {
            float l0, h0, l1, h1;
            unpack2(l0, h0, acc[j][0]);
            unpack2(l1, h1, acc[j][1]);
            float f0 = l0 + h0, f1 = l1 + h1;
            if (kh == 0) { f0 += xv[j][0]; f1 += xv[j][1]; }
            dst[(rg*UPB + j)*66 + lane]      = f0;
            dst[(rg*UPB + j)*66 + lane + 32] = f1;
        }
        __syncthreads();

        for (int e = tid; e < UPB*BATCH; e += 256) {
            int u = e % UPB, b = e / UPB;
            float iv = gA[(u)       *66 + b] + gB[(u)       *66 + b];
            float fv = gA[(UPB  +u) *66 + b] + gB[(UPB  +u) *66 + b];
            float gv = gA[(2*UPB+u) *66 + b] + gB[(2*UPB+u) *66 + b];
            float ov = gA[(3*UPB+u) *66 + b] + gB[(3*UPB+u) *66 + b];
            float cp = c_s[u*BATCH + b];
            float cn = sigf(fv) * cp + sigf(iv) * tanhf(gv);
            float hn = sigf(ov) * tanhf(cn);
            c_s[u*BATCH + b] = cn;
            __stcg(&h_out[b*HID + u0 + u], hn);
        }

        __threadfence();
        __syncthreads();
        if (tid == 0) {
            atomicAdd(&g_bar, 1u);
            unsigned target = (unsigned)(t + 1) * NB;
            while (*((volatile unsigned*)&g_bar) < target) {}
        }
        __syncthreads();
    }
}

// single cell step (encoder layers 1-2, zero state)
__global__ __launch_bounds__(256) void k_cell(
    const float* __restrict__ h_in, const float* __restrict__ W,
    const float* __restrict__ b1, const float* __restrict__ b2,
    float* __restrict__ h_out, float* __restrict__ h_copy)
{
    __shared__ float hs[64][36];
    __shared__ float ws[32][36];
    __shared__ float gexs[32][65];
    const int tid = threadIdx.x;
    const int u0 = blockIdx.x * 8;
    const int tc = tid & 31;
    const int tr = tid >> 5;
    const int row_c = (tc >> 3) * HID + u0 + (tc & 7);

    const int hb = tid >> 2;
    const int hk = (tid & 3) << 3;
    const int wcc = tid >> 3;
    const int wk = (tid & 7) << 2;
    const int row_w = (wcc >> 3) * HID + u0 + (wcc & 7);

    float acc[8];
#pragma unroll
    for (int i = 0; i < 8; i++) acc[i] = 0.f;

    for (int k0 = 0; k0 < HID; k0 += 32) {
        float4 hv0 = *(const float4*)(h_in + (size_t)hb * HID + k0 + hk);
        float4 hv1 = *(const float4*)(h_in + (size_t)hb * HID + k0 + hk + 4);
        float4 wv  = *(const float4*)(W + (size_t)row_w * HID + k0 + wk);
        *(float4*)&hs[hb][hk]     = hv0;
        *(float4*)&hs[hb][hk + 4] = hv1;
        *(float4*)&ws[wcc][wk]    = wv;
        __syncthreads();
#pragma unroll
        for (int kk = 0; kk < 32; kk += 4) {
            float4 w4 = *(const float4*)&ws[tc][kk];
#pragma unroll
            for (int i = 0; i < 8; i++) {
                float4 h4 = *(const float4*)&hs[tr*8 + i][kk];
                acc[i] = fmaf(h4.x, w4.x, acc[i]);
                acc[i] = fmaf(h4.y, w4.y, acc[i]);
                acc[i] = fmaf(h4.z, w4.z, acc[i]);
                acc[i] = fmaf(h4.w, w4.w, acc[i]);
            }
        }
        __syncthreads();
    }

    float bb = b1[row_c] + b2[row_c];
#pragma unroll
    for (int i = 0; i < 8; i++) gexs[tc][tr*8 + i] = acc[i] + bb;
    __syncthreads();

    for (int it = tid; it < 512; it += 256) {
        int b = it >> 3, ul = it & 7;
        float iv = gexs[ul][b];
        float gv = gexs[16 + ul][b];
        float ov = gexs[24 + ul][b];
        float cn = sigf(iv) * tanhf(gv);
        float hn = sigf(ov) * tanhf(cn);
        int idx = b * HID + u0 + ul;
        h_out[idx] = hn;
        if (h_copy) h_copy[idx] = hn;
    }
}

// ---------------- persistent decoder (32 steps, resident weights) ----------
__global__ __launch_bounds__(256) void k_decp(
    const float* __restrict__ W2, const float* __restrict__ db1,
    const float* __restrict__ db2, const float* __restrict__ linW,
    const float* __restrict__ linb, float* __restrict__ out)
{
    extern __shared__ float sm[];
    float* W2s   = sm;               // 24*768
    float* linWs = W2s + RPB*HID;    // 2*768
    float* hbuf  = linWs + 2*HID;    // 768
    float* gs    = hbuf + HID;       // 24
    float* bs    = gs + 32;          // 24
    float* red   = bs + 32;          // 8
    float* osv   = red + 8;          // 2
    float* lbs   = osv + 2;          // 2

    const int tid = threadIdx.x;
    const int u0 = blockIdx.x * UPB;
    const int f0 = blockIdx.x * 2;

    for (int e = tid; e < RPB*(HID/4); e += 256) {
        int r = e / (HID/4), c4 = e % (HID/4);
        int grow = (r/UPB)*HID + u0 + (r%UPB);
        ((float4*)W2s)[e] = ((const float4*)(W2 + (size_t)grow*HID))[c4];
    }
    for (int e = tid; e < 2*(HID/4); e += 256)
        ((float4*)linWs)[e] = ((const float4*)(linW + (size_t)f0*HID))[e];
    if (tid < RPB) {
        int grow = (tid/UPB)*HID + u0 + (tid%UPB);
        bs[tid] = db1[grow] + db2[grow];
    }
    if (tid < 2) lbs[tid] = linb[f0 + tid];
    __syncthreads();

    for (int t = 0; t < TLEN; t++) {
        const float* h_in  = g_hd[t & 1];
        float*       h_out = g_hd[(t + 1) & 1];

        // stage h
        for (int e = tid; e < HID; e += 256) hbuf[e] = __ldcg(&h_in[e]);
        __syncthreads();

        // gates GEMV: 24 rows x 768
        if (tid < 192) {
            int r = tid >> 3, s = tid & 7;
            const float4* W4 = (const float4*)(W2s + r*HID + s*96);
            const float4* h4 = (const float4*)(hbuf + s*96);
            float sum = 0.f;
#pragma unroll
            for (int m = 0; m < 24; m++) {
                float4 wv = W4[m]; float4 hv = h4[m];
                sum += wv.x*hv.x + wv.y*hv.y + wv.z*hv.z + wv.w*hv.w;
            }
#pragma unroll
            for (int off = 4; off > 0; off >>= 1)
                sum += __shfl_down_sync(0xffffffffu, sum, off, 8);
            if (s == 0) gs[r] = sum + bs[r];
        }
        __syncthreads();
        if (tid < UPB) {
            float iv = gs[tid], gv = gs[2*UPB + tid], ov = gs[3*UPB + tid];
            float cn = sigf(iv) * tanhf(gv);
            float hn = sigf(ov) * tanhf(cn);
            __stcg(&h_out[u0 + tid], hn);
        }
        __threadfence();
        __syncthreads();
        if (tid == 0) {
            atomicAdd(&g_bar, 1u);
            unsigned target = (unsigned)(S_LEN * NB) + (unsigned)(t + 1) * NB;
            while (*((volatile unsigned*)&g_bar) < target) {}
        }
        __syncthreads();

        // head: 2 rows of linW . h_new, broadcast over 64 batches
        for (int e = tid; e < HID; e += 256) hbuf[e] = __ldcg(&h_out[e]);
        __syncthreads();
        {
            int fl = tid >> 7;
            int i  = tid & 127;
            float p = 0.f;
#pragma unroll
            for (int m = 0; m < 6; m++)
                p += linWs[fl*HID + i + 128*m] * hbuf[i + 128*m];
#pragma unroll
            for (int off = 16; off > 0; off >>= 1)
                p += __shfl_down_sync(0xffffffffu, p, off);
            if ((tid & 31) == 0) red[tid >> 5] = p;
        }
        __syncthreads();
        if (tid < 2)
            osv[tid] = red[tid*4] + red[tid*4+1] + red[tid*4+2] + red[tid*4+3] + lbs[tid];
        __syncthreads();
        if (tid < 128) {
            int b = tid & 63, fl = tid >> 6;
            out[(size_t)t*BATCH*FEAT + b*FEAT + f0 + fl] = osv[fl];
        }
        __syncthreads();
    }
}

extern "C" void kernel_launch(void* const* d_in, const int* in_sizes, int n_in,
                              void* d_out, int out_size)
{
    const float* x     = (const float*)d_in[0];
    const float* Wih0  = (const float*)d_in[1];
    const float* Whh0  = (const float*)d_in[2];
    const float* bih0  = (const float*)d_in[3];
    const float* bhh0  = (const float*)d_in[4];
    const float* eWih  = (const float*)d_in[5];
    const float* ebih  = (const float*)d_in[7];
    const float* ebhh  = (const float*)d_in[8];
    const float* dWih  = (const float*)d_in[9];
    const float* dbih  = (const float*)d_in[11];
    const float* dbhh  = (const float*)d_in[12];
    const float* linW  = (const float*)d_in[13];
    const float* linb  = (const float*)d_in[14];
    float* out = (float*)d_out;

    float *p_h, *p_h1;
    cudaGetSymbolAddress((void**)&p_h,  g_h);
    cudaGetSymbolAddress((void**)&p_h1, g_h1);

    static int smem_set = 0;
    if (!smem_set) {
        cudaFuncSetAttribute(k_enc,  cudaFuncAttributeMaxDynamicSharedMemorySize, 219008);
        cudaFuncSetAttribute(k_decp, cudaFuncAttributeMaxDynamicSharedMemorySize, 90000);
        smem_set = 1;
    }

    k_init<<<192, 256>>>();
    k_xgates<<<dim3(24, 128), 256>>>(x, Wih0, bih0, bhh0);

    k_enc<<<NB, 256, 219008>>>(Whh0);

    cudaMemcpyAsync(out + OUT_ENC_OFF, p_h, BATCH * HID * sizeof(float),
                    cudaMemcpyDeviceToDevice);
    k_cell<<<96, 256>>>(p_h, eWih, ebih, ebhh,
                        p_h1, out + OUT_ENC_OFF + BATCH * HID);
    k_cell<<<96, 256>>>(p_h1, eWih + (size_t)GATES * HID,
                        ebih + GATES, ebhh + GATES,
                        p_h + BATCH * HID, out + OUT_ENC_OFF + 2 * BATCH * HID);

    k_decp<<<NB, 256, 90000>>>(dWih + (size_t)2 * GATES * HID,
                               dbih + 2 * GATES, dbhh + 2 * GATES,
                               linW, linb, out);
}

// round 6
// speedup vs baseline: 3.1006x; 1.6959x over previous
#include <cuda_runtime.h>
#include <cuda_bf16.h>
#include <math.h>
#include <stdint.h>

#define S_LEN 256
#define BATCH 64
#define FEAT  256
#define HID   768
#define GATES 3072
#define TLEN  32
#define OUT_ENC_OFF (TLEN*BATCH*FEAT)

#define NB   128
#define UPB  6
#define RPB  24

static __device__ float g_xg[(size_t)S_LEN*BATCH*GATES];
static __device__ __nv_bfloat16 g_hhi[2][BATCH*HID];
static __device__ __nv_bfloat16 g_hlo[2][BATCH*HID];
static __device__ float g_hfin[BATCH*HID];
static __device__ float g_h1[BATCH*HID];
static __device__ float g_scr[BATCH*HID];
static __device__ float g_hd[2][HID];
static __device__ unsigned g_bar;

__device__ __forceinline__ float sigf(float x){ return 1.0f/(1.0f+expf(-x)); }

__device__ __forceinline__ void ffma2(unsigned long long &d, unsigned long long a, unsigned long long b){
    asm("fma.rn.f32x2 %0, %1, %2, %0;" : "+l"(d) : "l"(a), "l"(b));
}
__device__ __forceinline__ void pack2(unsigned long long &d, float a){
    asm("mov.b64 %0, {%1, %1};" : "=l"(d) : "f"(a));
}
__device__ __forceinline__ void unpack2(float &lo, float &hi, unsigned long long v){
    asm("mov.b64 {%0, %1}, %2;" : "=f"(lo), "=f"(hi) : "l"(v));
}
__device__ __forceinline__ void lds2u64(unsigned long long &a, unsigned long long &b, uint32_t addr){
    asm volatile("ld.shared.v2.u64 {%0, %1}, [%2];" : "=l"(a), "=l"(b) : "r"(addr));
}
__device__ __forceinline__ void mma_bf16(float* c, const uint32_t* a, uint32_t b0, uint32_t b1){
    asm volatile(
        "mma.sync.aligned.m16n8k16.row.col.f32.bf16.bf16.f32 "
        "{%0,%1,%2,%3}, {%4,%5,%6,%7}, {%8,%9}, {%0,%1,%2,%3};"
        : "+f"(c[0]), "+f"(c[1]), "+f"(c[2]), "+f"(c[3])
        : "r"(a[0]), "r"(a[1]), "r"(a[2]), "r"(a[3]), "r"(b0), "r"(b1));
}
__device__ __forceinline__ void ldsm4(uint32_t* a, uint32_t addr){
    asm volatile("ldmatrix.sync.aligned.m8n8.x4.shared.b16 {%0,%1,%2,%3}, [%4];"
        : "=r"(a[0]), "=r"(a[1]), "=r"(a[2]), "=r"(a[3]) : "r"(addr));
}

__global__ void k_init() {
    int i = blockIdx.x*blockDim.x + threadIdx.x;
    if (i < BATCH*HID/2) {
        ((uint32_t*)g_hhi[0])[i] = 0u;
        ((uint32_t*)g_hlo[0])[i] = 0u;
    }
    if (i < HID) g_hd[0][i] = 0.f;
    if (i == 0) g_bar = 0u;
}

// xg = X @ Wih0^T + b ; M=16384, N=3072, K=256 (FFMA2)
__global__ __launch_bounds__(256) void k_xgates(
    const float* __restrict__ X, const float* __restrict__ W,
    const float* __restrict__ b1, const float* __restrict__ b2)
{
    __shared__ float As[8][128];
    __shared__ float Bs[8][128];
    const int bm = blockIdx.y * 128;
    const int bn = blockIdx.x * 128;
    const int tid = threadIdx.x;
    const int tr = (tid >> 4) << 3;
    const int tc = (tid & 15) << 3;
    const int lr = tid >> 1;
    const int lc = (tid & 1) << 2;
    uint32_t bs_base = (uint32_t)__cvta_generic_to_shared(&Bs[0][0]);

    unsigned long long acc2[8][4];
#pragma unroll
    for (int i = 0; i < 8; i++)
#pragma unroll
        for (int j = 0; j < 4; j++) acc2[i][j] = 0ull;

    for (int k0 = 0; k0 < FEAT; k0 += 8) {
        float4 a4 = *(const float4*)(X + (size_t)(bm + lr) * FEAT + k0 + lc);
        float4 b4 = *(const float4*)(W + (size_t)(bn + lr) * FEAT + k0 + lc);
        As[lc+0][lr]=a4.x; As[lc+1][lr]=a4.y; As[lc+2][lr]=a4.z; As[lc+3][lr]=a4.w;
        Bs[lc+0][lr]=b4.x; Bs[lc+1][lr]=b4.y; Bs[lc+2][lr]=b4.z; Bs[lc+3][lr]=b4.w;
        __syncthreads();
#pragma unroll
        for (int k = 0; k < 8; k++) {
            float ar[8];
            *(float4*)(ar)   = *(const float4*)&As[k][tr];
            *(float4*)(ar+4) = *(const float4*)&As[k][tr+4];
            unsigned long long c0,c1,c2,c3;
            lds2u64(c0, c1, bs_base + (uint32_t)((k*128 + tc) * 4));
            lds2u64(c2, c3, bs_base + (uint32_t)((k*128 + tc) * 4 + 16));
#pragma unroll
            for (int i = 0; i < 8; i++) {
                unsigned long long ad; pack2(ad, ar[i]);
                ffma2(acc2[i][0], ad, c0);
                ffma2(acc2[i][1], ad, c1);
                ffma2(acc2[i][2], ad, c2);
                ffma2(acc2[i][3], ad, c3);
            }
        }
        __syncthreads();
    }
    float biasv[8];
#pragma unroll
    for (int j = 0; j < 8; j++) biasv[j] = b1[bn+tc+j] + b2[bn+tc+j];
#pragma unroll
    for (int i = 0; i < 8; i++) {
        float v[8];
#pragma unroll
        for (int j = 0; j < 4; j++) unpack2(v[2*j], v[2*j+1], acc2[i][j]);
        float4 o0, o1;
        o0.x=v[0]+biasv[0]; o0.y=v[1]+biasv[1]; o0.z=v[2]+biasv[2]; o0.w=v[3]+biasv[3];
        o1.x=v[4]+biasv[4]; o1.y=v[5]+biasv[5]; o1.z=v[6]+biasv[6]; o1.w=v[7]+biasv[7];
        float* dst = &g_xg[(size_t)(bm+tr+i)*GATES + bn+tc];
        *(float4*)dst = o0;
        *(float4*)(dst+4) = o1;
    }
}

// ---------------- persistent encoder layer-0 LSTM (bf16-split mma) --------
// Block: units u0..u0+5 (24 gate rows), M=64 batches, K=768.
// Warps: (mw = wid&3) batches 16mw..+15 ; (kh = wid>>2) K-half of 384.
#define WPAD 776

__global__ __launch_bounds__(256) void k_enc(const float* __restrict__ Whh)
{
    extern __shared__ char smraw[];
    __nv_bfloat16* Whi = (__nv_bfloat16*)smraw;            // 24*776
    __nv_bfloat16* Wlo = Whi + RPB*WPAD;                   // 24*776
    __nv_bfloat16* hsm = Wlo + RPB*WPAD;                   // 2*2*2*4096 = 32768
    float* gA  = (float*)(hsm + 32768);                    // 24*66
    float* gB  = gA + RPB*66;                              // 24*66
    float* c_s = gB + RPB*66;                              // 384

    const int tid  = threadIdx.x;
    const int wid  = tid >> 5;
    const int lane = tid & 31;
    const int mw   = wid & 3;
    const int kh   = wid >> 2;
    const int u0   = blockIdx.x * UPB;

    // convert resident W slice to bf16 hi/lo planes (once)
    for (int e = tid; e < RPB*HID; e += 256) {
        int r = e / HID, k = e % HID;
        int grow = (r/UPB)*HID + u0 + (r%UPB);
        float w = Whh[(size_t)grow*HID + k];
        __nv_bfloat16 hi = __float2bfloat16(w);
        __nv_bfloat16 lo = __float2bfloat16(w - __bfloat162float(hi));
        Whi[r*WPAD + k] = hi;
        Wlo[r*WPAD + k] = lo;
    }
    for (int e = tid; e < UPB*BATCH; e += 256) c_s[e] = 0.f;

    uint32_t hs_base = (uint32_t)__cvta_generic_to_shared(hsm);

    const int l4 = lane >> 2;          // 0..7
    const int l2 = lane & 3;           // 0..3
    int growx[3][2];
#pragma unroll
    for (int nt = 0; nt < 3; nt++)
#pragma unroll
        for (int jj = 0; jj < 2; jj++) {
            int row = nt*8 + 2*l2 + jj;
            growx[nt][jj] = (row/UPB)*HID + u0 + (row%UPB);
        }
    const int bx0 = 16*mw + l4;

    __syncthreads();

    for (int t = 0; t < S_LEN; t++) {
        const __nv_bfloat16* hhi = g_hhi[t & 1];
        const __nv_bfloat16* hlo = g_hlo[t & 1];
        const float* xg = g_xg + (size_t)t * BATCH * GATES;

        float xv[3][2][2];
        if (kh == 0) {
#pragma unroll
            for (int nt = 0; nt < 3; nt++)
#pragma unroll
                for (int jj = 0; jj < 2; jj++)
#pragma unroll
                    for (int ii = 0; ii < 2; ii++)
                        xv[nt][jj][ii] = __ldcg(xg + (size_t)(bx0 + 8*ii)*GATES + growx[nt][jj]);
        }

        float acc[3][4];
#pragma unroll
        for (int nt = 0; nt < 3; nt++)
#pragma unroll
            for (int j = 0; j < 4; j++) acc[nt][j] = 0.f;

        // stage phase 0: 2048 granules of 16B (8 per thread)
        // g decode: s=g&7 (16B seg in 128B row), b=(g>>3)&63, pl=(g>>9)&1, k2=g>>10
        {
#pragma unroll
            for (int i = 0; i < 8; i++) {
                int g = tid + i*256;
                int s = g & 7, b = (g >> 3) & 63, pl = (g >> 9) & 1, k2 = g >> 10;
                uint32_t dst = hs_base + (uint32_t)((k2*2 + pl)*8192 + b*128 + ((s*16) ^ ((b&7)*16)));
                const __nv_bfloat16* src = (pl ? hlo : hhi) + (size_t)b*HID + k2*384 + s*8;
                asm volatile("cp.async.cg.shared.global [%0], [%1], 16;" :: "r"(dst), "l"(src));
            }
            asm volatile("cp.async.commit_group;");
        }

        for (int ph = 0; ph < 6; ph++) {
            if (ph < 5) {
#pragma unroll
                for (int i = 0; i < 8; i++) {
                    int g = tid + i*256;
                    int s = g & 7, b = (g >> 3) & 63, pl = (g >> 9) & 1, k2 = g >> 10;
                    uint32_t dst = hs_base + (uint32_t)((((ph+1)&1)*4 + k2*2 + pl)*8192 + b*128 + ((s*16) ^ ((b&7)*16)));
                    const __nv_bfloat16* src = (pl ? hlo : hhi) + (size_t)b*HID + k2*384 + (ph+1)*64 + s*8;
                    asm volatile("cp.async.cg.shared.global [%0], [%1], 16;" :: "r"(dst), "l"(src));
                }
                asm volatile("cp.async.commit_group;");
                asm volatile("cp.async.wait_group 1;");
            } else {
                asm volatile("cp.async.wait_group 0;");
            }
            __syncthreads();

            uint32_t subhi = hs_base + (uint32_t)(((ph&1)*4 + kh*2 + 0)*8192);
            uint32_t sublo = subhi + 8192;
            const int r = lane & 15, seg = lane >> 4;
            const uint32_t rowoff = (uint32_t)((16*mw + r)*128);
            const uint32_t swz = (uint32_t)((r&7)*16);
#pragma unroll
            for (int ks = 0; ks < 4; ks++) {
                uint32_t coff = (uint32_t)(ks*32 + seg*16) ^ swz;
                uint32_t ahi[4], alo[4];
                ldsm4(ahi, subhi + rowoff + coff);
                ldsm4(alo, sublo + rowoff + coff);
                const int kcol = kh*384 + ph*64 + ks*16 + 2*l2;
#pragma unroll
                for (int nt = 0; nt < 3; nt++) {
                    const int widx = (nt*8 + l4)*WPAD + kcol;
                    uint32_t bh0 = *(const uint32_t*)&Whi[widx];
                    uint32_t bh1 = *(const uint32_t*)&Whi[widx + 8];
                    uint32_t bl0 = *(const uint32_t*)&Wlo[widx];
                    uint32_t bl1 = *(const uint32_t*)&Wlo[widx + 8];
                    mma_bf16(acc[nt], ahi, bh0, bh1);
                    mma_bf16(acc[nt], ahi, bl0, bl1);
                    mma_bf16(acc[nt], alo, bh0, bh1);
                }
            }
            __syncthreads();
        }

        // epilogue: write gate partials (kh=0 adds xg)
        float* dst = kh ? gB : gA;
#pragma unroll
        for (int nt = 0; nt < 3; nt++) {
            int r0 = nt*8 + 2*l2;
            if (kh == 0) {
                dst[(r0  )*66 + bx0    ] = acc[nt][0] + xv[nt][0][0];
                dst[(r0+1)*66 + bx0    ] = acc[nt][1] + xv[nt][1][0];
                dst[(r0  )*66 + bx0 + 8] = acc[nt][2] + xv[nt][0][1];
                dst[(r0+1)*66 + bx0 + 8] = acc[nt][3] + xv[nt][1][1];
            } else {
                dst[(r0  )*66 + bx0    ] = acc[nt][0];
                dst[(r0+1)*66 + bx0    ] = acc[nt][1];
                dst[(r0  )*66 + bx0 + 8] = acc[nt][2];
                dst[(r0+1)*66 + bx0 + 8] = acc[nt][3];
            }
        }
        __syncthreads();

        // fused cell
        __nv_bfloat16* ohi = g_hhi[(t+1)&1];
        __nv_bfloat16* olo = g_hlo[(t+1)&1];
        for (int e = tid; e < UPB*BATCH; e += 256) {
            int u = e % UPB, b = e / UPB;
            float iv = gA[(u)       *66 + b] + gB[(u)       *66 + b];
            float fv = gA[(UPB  +u) *66 + b] + gB[(UPB  +u) *66 + b];
            float gv = gA[(2*UPB+u) *66 + b] + gB[(2*UPB+u) *66 + b];
            float ov = gA[(3*UPB+u) *66 + b] + gB[(3*UPB+u) *66 + b];
            float cp = c_s[e];
            float cn = sigf(fv) * cp + sigf(iv) * tanhf(gv);
            float hn = sigf(ov) * tanhf(cn);
            c_s[e] = cn;
            __nv_bfloat16 hi = __float2bfloat16(hn);
            __nv_bfloat16 lo = __float2bfloat16(hn - __bfloat162float(hi));
            int idx = b*HID + u0 + u;
            ohi[idx] = hi;
            olo[idx] = lo;
            if (t == S_LEN-1) g_hfin[idx] = hn;
        }

        __threadfence();
        __syncthreads();
        if (tid == 0) {
            atomicAdd(&g_bar, 1u);
            unsigned target = (unsigned)(t + 1) * NB;
            while (*((volatile unsigned*)&g_bar) < target) {}
        }
        __syncthreads();
    }
}

// single cell step (encoder layers 1-2, zero state) — fp32
__global__ __launch_bounds__(256) void k_cell(
    const float* __restrict__ h_in, const float* __restrict__ W,
    const float* __restrict__ b1, const float* __restrict__ b2,
    float* __restrict__ h_out, float* __restrict__ h_copy)
{
    __shared__ float hs[64][36];
    __shared__ float ws[32][36];
    __shared__ float gexs[32][65];
    const int tid = threadIdx.x;
    const int u0 = blockIdx.x * 8;
    const int tc = tid & 31;
    const int tr = tid >> 5;
    const int row_c = (tc >> 3) * HID + u0 + (tc & 7);

    const int hb = tid >> 2;
    const int hk = (tid & 3) << 3;
    const int wcc = tid >> 3;
    const int wk = (tid & 7) << 2;
    const int row_w = (wcc >> 3) * HID + u0 + (wcc & 7);

    float acc[8];
#pragma unroll
    for (int i = 0; i < 8; i++) acc[i] = 0.f;

    for (int k0 = 0; k0 < HID; k0 += 32) {
        float4 hv0 = *(const float4*)(h_in + (size_t)hb * HID + k0 + hk);
        float4 hv1 = *(const float4*)(h_in + (size_t)hb * HID + k0 + hk + 4);
        float4 wv  = *(const float4*)(W + (size_t)row_w * HID + k0 + wk);
        *(float4*)&hs[hb][hk]     = hv0;
        *(float4*)&hs[hb][hk + 4] = hv1;
        *(float4*)&ws[wcc][wk]    = wv;
        __syncthreads();
#pragma unroll
        for (int kk = 0; kk < 32; kk += 4) {
            float4 w4 = *(const float4*)&ws[tc][kk];
#pragma unroll
            for (int i = 0; i < 8; i++) {
                float4 h4 = *(const float4*)&hs[tr*8 + i][kk];
                acc[i] = fmaf(h4.x, w4.x, acc[i]);
                acc[i] = fmaf(h4.y, w4.y, acc[i]);
                acc[i] = fmaf(h4.z, w4.z, acc[i]);
                acc[i] = fmaf(h4.w, w4.w, acc[i]);
            }
        }
        __syncthreads();
    }

    float bb = b1[row_c] + b2[row_c];
#pragma unroll
    for (int i = 0; i < 8; i++) gexs[tc][tr*8 + i] = acc[i] + bb;
    __syncthreads();

    for (int it = tid; it < 512; it += 256) {
        int b = it >> 3, ul = it & 7;
        float iv = gexs[ul][b];
        float gv = gexs[16 + ul][b];
        float ov = gexs[24 + ul][b];
        float cn = sigf(iv) * tanhf(gv);
        float hn = sigf(ov) * tanhf(cn);
        int idx = b * HID + u0 + ul;
        h_out[idx] = hn;
        if (h_copy) h_copy[idx] = hn;
    }
}

// ---------------- persistent decoder ----------------
__global__ __launch_bounds__(256) void k_decp(
    const float* __restrict__ W2, const float* __restrict__ db1,
    const float* __restrict__ db2, const float* __restrict__ linW,
    const float* __restrict__ linb, float* __restrict__ out)
{
    extern __shared__ float sm[];
    float* W2s   = sm;               // 24*768
    float* linWs = W2s + RPB*HID;    // 2*768
    float* hbuf  = linWs + 2*HID;    // 768
    float* gs    = hbuf + HID;       // 32
    float* bs    = gs + 32;          // 32
    float* red   = bs + 32;          // 8
    float* osv   = red + 8;          // 2
    float* lbs   = osv + 2;          // 2

    const int tid = threadIdx.x;
    const int u0 = blockIdx.x * UPB;
    const int f0 = blockIdx.x * 2;

    for (int e = tid; e < RPB*(HID/4); e += 256) {
        int r = e / (HID/4), c4 = e % (HID/4);
        int grow = (r/UPB)*HID + u0 + (r%UPB);
        ((float4*)W2s)[e] = ((const float4*)(W2 + (size_t)grow*HID))[c4];
    }
    for (int e = tid; e < 2*(HID/4); e += 256)
        ((float4*)linWs)[e] = ((const float4*)(linW + (size_t)f0*HID))[e];
    if (tid < RPB) {
        int grow = (tid/UPB)*HID + u0 + (tid%UPB);
        bs[tid] = db1[grow] + db2[grow];
    }
    if (tid < 2) lbs[tid] = linb[f0 + tid];
    __syncthreads();

    for (int t = 0; t < TLEN; t++) {
        const float* h_in  = g_hd[t & 1];
        float*       h_out = g_hd[(t + 1) & 1];

        for (int e = tid; e < HID; e += 256) hbuf[e] = __ldcg(&h_in[e]);
        __syncthreads();

        if (tid < 192) {
            int r = tid >> 3, s = tid & 7;
            const float4* W4 = (const float4*)(W2s + r*HID + s*96);
            const float4* h4 = (const float4*)(hbuf + s*96);
            float sum = 0.f;
#pragma unroll
            for (int m = 0; m < 24; m++) {
                float4 wv = W4[m]; float4 hv = h4[m];
                sum += wv.x*hv.x + wv.y*hv.y + wv.z*hv.z + wv.w*hv.w;
            }
#pragma unroll
            for (int off = 4; off > 0; off >>= 1)
                sum += __shfl_down_sync(0xffffffffu, sum, off, 8);
            if (s == 0) gs[r] = sum + bs[r];
        }
        __syncthreads();
        if (tid < UPB) {
            float iv = gs[tid], gv = gs[2*UPB + tid], ov = gs[3*UPB + tid];
            float cn = sigf(iv) * tanhf(gv);
            float hn = sigf(ov) * tanhf(cn);
            __stcg(&h_out[u0 + tid], hn);
        }
        __threadfence();
        __syncthreads();
        if (tid == 0) {
            atomicAdd(&g_bar, 1u);
            unsigned target = (unsigned)(S_LEN * NB) + (unsigned)(t + 1) * NB;
            while (*((volatile unsigned*)&g_bar) < target) {}
        }
        __syncthreads();

        for (int e = tid; e < HID; e += 256) hbuf[e] = __ldcg(&h_out[e]);
        __syncthreads();
        {
            int fl = tid >> 7;
            int i  = tid & 127;
            float p = 0.f;
#pragma unroll
            for (int m = 0; m < 6; m++)
                p += linWs[fl*HID + i + 128*m] * hbuf[i + 128*m];
#pragma unroll
            for (int off = 16; off > 0; off >>= 1)
                p += __shfl_down_sync(0xffffffffu, p, off);
            if ((tid & 31) == 0) red[tid >> 5] = p;
        }
        __syncthreads();
        if (tid < 2)
            osv[tid] = red[tid*4] + red[tid*4+1] + red[tid*4+2] + red[tid*4+3] + lbs[tid];
        __syncthreads();
        if (tid < 128) {
            int b = tid & 63, fl = tid >> 6;
            out[(size_t)t*BATCH*FEAT + b*FEAT + f0 + fl] = osv[fl];
        }
        __syncthreads();
    }
}

extern "C" void kernel_launch(void* const* d_in, const int* in_sizes, int n_in,
                              void* d_out, int out_size)
{
    const float* x     = (const float*)d_in[0];
    const float* Wih0  = (const float*)d_in[1];
    const float* Whh0  = (const float*)d_in[2];
    const float* bih0  = (const float*)d_in[3];
    const float* bhh0  = (const float*)d_in[4];
    const float* eWih  = (const float*)d_in[5];
    const float* ebih  = (const float*)d_in[7];
    const float* ebhh  = (const float*)d_in[8];
    const float* dWih  = (const float*)d_in[9];
    const float* dbih  = (const float*)d_in[11];
    const float* dbhh  = (const float*)d_in[12];
    const float* linW  = (const float*)d_in[13];
    const float* linb  = (const float*)d_in[14];
    float* out = (float*)d_out;

    float *p_hfin, *p_h1, *p_scr;
    cudaGetSymbolAddress((void**)&p_hfin, g_hfin);
    cudaGetSymbolAddress((void**)&p_h1,   g_h1);
    cudaGetSymbolAddress((void**)&p_scr,  g_scr);

    const int enc_smem = 2*RPB*776*2 + 65536 + 2*RPB*66*4 + UPB*BATCH*4;

    static int smem_set = 0;
    if (!smem_set) {
        cudaFuncSetAttribute(k_enc,  cudaFuncAttributeMaxDynamicSharedMemorySize, enc_smem);
        cudaFuncSetAttribute(k_decp, cudaFuncAttributeMaxDynamicSharedMemorySize, 90000);
        smem_set = 1;
    }

    k_init<<<192, 256>>>();
    k_xgates<<<dim3(24, 128), 256>>>(x, Wih0, bih0, bhh0);

    k_enc<<<NB, 256, enc_smem>>>(Whh0);

    cudaMemcpyAsync(out + OUT_ENC_OFF, p_hfin, BATCH * HID * sizeof(float),
                    cudaMemcpyDeviceToDevice);
    k_cell<<<96, 256>>>(p_hfin, eWih, ebih, ebhh,
                        p_h1, out + OUT_ENC_OFF + BATCH * HID);
    k_cell<<<96, 256>>>(p_h1, eWih + (size_t)GATES * HID,
                        ebih + GATES, ebhh + GATES,
                        p_scr, out + OUT_ENC_OFF + 2 * BATCH * HID);

    k_decp<<<NB, 256, 90000>>>(dWih + (size_t)2 * GATES * HID,
                               dbih + 2 * GATES, dbhh + 2 * GATES,
                               linW, linb, out);
}

// round 7
// speedup vs baseline: 3.4420x; 1.1101x over previous
#include <cuda_runtime.h>
#include <cuda_bf16.h>
#include <math.h>
#include <stdint.h>

#define S_LEN 256
#define BATCH 64
#define FEAT  256
#define HID   768
#define GATES 3072
#define TLEN  32
#define OUT_ENC_OFF (TLEN*BATCH*FEAT)
#define XM    (S_LEN*BATCH)   /* 16384 */

#define NB   128
#define UPB  6
#define RPB  24
#define WPAD 776

static __device__ float g_xg[(size_t)S_LEN*BATCH*GATES];
static __device__ __nv_bfloat16 g_xhi[(size_t)XM*FEAT];
static __device__ __nv_bfloat16 g_xlo[(size_t)XM*FEAT];
static __device__ __nv_bfloat16 g_whi[(size_t)GATES*FEAT];
static __device__ __nv_bfloat16 g_wlo[(size_t)GATES*FEAT];
static __device__ __nv_bfloat16 g_hhi[2][BATCH*HID];
static __device__ __nv_bfloat16 g_hlo[2][BATCH*HID];
static __device__ float g_hfin[BATCH*HID];
static __device__ float g_h1[BATCH*HID];
static __device__ float g_scr[BATCH*HID];
static __device__ float g_hd[2][HID];
static __device__ unsigned g_bar;

__device__ __forceinline__ float sigf(float x){ return 1.0f/(1.0f+expf(-x)); }

__device__ __forceinline__ void mma_bf16(float* c, const uint32_t* a, uint32_t b0, uint32_t b1){
    asm volatile(
        "mma.sync.aligned.m16n8k16.row.col.f32.bf16.bf16.f32 "
        "{%0,%1,%2,%3}, {%4,%5,%6,%7}, {%8,%9}, {%0,%1,%2,%3};"
        : "+f"(c[0]), "+f"(c[1]), "+f"(c[2]), "+f"(c[3])
        : "r"(a[0]), "r"(a[1]), "r"(a[2]), "r"(a[3]), "r"(b0), "r"(b1));
}
__device__ __forceinline__ void ldsm4(uint32_t* a, uint32_t addr){
    asm volatile("ldmatrix.sync.aligned.m8n8.x4.shared.b16 {%0,%1,%2,%3}, [%4];"
        : "=r"(a[0]), "=r"(a[1]), "=r"(a[2]), "=r"(a[3]) : "r"(addr));
}

__global__ void k_init() {
    int i = blockIdx.x*blockDim.x + threadIdx.x;
    if (i < BATCH*HID/2) {
        ((uint32_t*)g_hhi[0])[i] = 0u;
        ((uint32_t*)g_hlo[0])[i] = 0u;
    }
    if (i < HID) g_hd[0][i] = 0.f;
    if (i == 0) g_bar = 0u;
}

// split fp32 -> bf16 hi/lo planes
__global__ void k_cvt(const float* __restrict__ src,
                      __nv_bfloat16* __restrict__ dhi,
                      __nv_bfloat16* __restrict__ dlo, int n) {
    int i = blockIdx.x*blockDim.x + threadIdx.x;
    if (i < n) {
        float v = src[i];
        __nv_bfloat16 hi = __float2bfloat16(v);
        dhi[i] = hi;
        dlo[i] = __float2bfloat16(v - __bfloat162float(hi));
    }
}

// ---------------- tensor-core xg GEMM: xg = X @ Wih0^T + b -----------------
// M=16384, N=3072, K=256. Block tile 128x128, 2 K-phases of 128.
// Warps: mw=wid&3 (M 32-slice), nw=wid>>2 (N 64-slice). bf16-split (3 MMA).
__global__ __launch_bounds__(256) void k_xg_mma(
    const float* __restrict__ b1, const float* __restrict__ b2)
{
    extern __shared__ char smraw[];
    // Xs: [pl][128 rows][256B], Ws: same, then bias[128]
    uint32_t xs_base = (uint32_t)__cvta_generic_to_shared(smraw);
    uint32_t ws_base = xs_base + 65536;
    float* sbias = (float*)(smraw + 131072);

    const int tid  = threadIdx.x;
    const int wid  = tid >> 5;
    const int lane = tid & 31;
    const int mw   = wid & 3;
    const int nw   = wid >> 2;
    const int bn   = blockIdx.x * 128;
    const int bm   = blockIdx.y * 128;
    const int l4 = lane >> 2;
    const int l2 = lane & 3;
    const int r  = lane & 15;
    const int seg = lane >> 4;

    if (tid < 128) sbias[tid] = b1[bn+tid] + b2[bn+tid];

    float acc[2][8][4];
#pragma unroll
    for (int mt = 0; mt < 2; mt++)
#pragma unroll
        for (int nt = 0; nt < 8; nt++)
#pragma unroll
            for (int j = 0; j < 4; j++) acc[mt][nt][j] = 0.f;

    for (int ph = 0; ph < 2; ph++) {
        __syncthreads();
        // stage X: 4096 granules (16/thread): s=g&15, row=(g>>4)&127, pl=g>>11
#pragma unroll
        for (int i = 0; i < 16; i++) {
            int g = tid + i*256;
            int s = g & 15, row = (g >> 4) & 127, pl = g >> 11;
            uint32_t dst = xs_base + (uint32_t)(pl*32768 + row*256 + ((s ^ (row&7))*16));
            const __nv_bfloat16* src = (pl ? g_xlo : g_xhi) + (size_t)(bm+row)*FEAT + ph*128 + s*8;
            asm volatile("cp.async.cg.shared.global [%0], [%1], 16;" :: "r"(dst), "l"(src));
        }
        // stage W
#pragma unroll
        for (int i = 0; i < 16; i++) {
            int g = tid + i*256;
            int s = g & 15, row = (g >> 4) & 127, pl = g >> 11;
            uint32_t dst = ws_base + (uint32_t)(pl*32768 + row*256 + ((s ^ (row&7))*16));
            const __nv_bfloat16* src = (pl ? g_wlo : g_whi) + (size_t)(bn+row)*FEAT + ph*128 + s*8;
            asm volatile("cp.async.cg.shared.global [%0], [%1], 16;" :: "r"(dst), "l"(src));
        }
        asm volatile("cp.async.commit_group;");
        asm volatile("cp.async.wait_group 0;");
        __syncthreads();

#pragma unroll
        for (int ks = 0; ks < 8; ks++) {
            uint32_t ahi[2][4], alo[2][4];
#pragma unroll
            for (int mt = 0; mt < 2; mt++) {
                uint32_t rowoff = (uint32_t)((mw*32 + mt*16 + r)*256);
                uint32_t coff = (uint32_t)((ks*32 + seg*16) ^ ((r&7)*16));
                ldsm4(ahi[mt], xs_base + rowoff + coff);
                ldsm4(alo[mt], xs_base + 32768 + rowoff + coff);
            }
#pragma unroll
            for (int nt = 0; nt < 8; nt++) {
                int wrow = nw*64 + nt*8 + l4;
                uint32_t wb = ws_base + (uint32_t)(wrow*256 + 4*l2);
                uint32_t s0 = (uint32_t)(((ks*2  ) ^ (wrow&7))*16);
                uint32_t s1 = (uint32_t)(((ks*2+1) ^ (wrow&7))*16);
                uint32_t bh0 = *(const uint32_t*)__cvta_shared_to_generic((size_t)(wb + s0));
                uint32_t bh1 = *(const uint32_t*)__cvta_shared_to_generic((size_t)(wb + s1));
                uint32_t bl0 = *(const uint32_t*)__cvta_shared_to_generic((size_t)(wb + 32768 + s0));
                uint32_t bl1 = *(const uint32_t*)__cvta_shared_to_generic((size_t)(wb + 32768 + s1));
#pragma unroll
                for (int mt = 0; mt < 2; mt++) {
                    mma_bf16(acc[mt][nt], ahi[mt], bh0, bh1);
                    mma_bf16(acc[mt][nt], ahi[mt], bl0, bl1);
                    mma_bf16(acc[mt][nt], alo[mt], bh0, bh1);
                }
            }
        }
    }

    // epilogue: add bias, store float2 pairs
#pragma unroll
    for (int mt = 0; mt < 2; mt++) {
#pragma unroll
        for (int nt = 0; nt < 8; nt++) {
            int nloc = nw*64 + nt*8 + 2*l2;
            int n0 = bn + nloc;
            int m0 = bm + mw*32 + mt*16 + l4;
            float2 o0, o1;
            o0.x = acc[mt][nt][0] + sbias[nloc];
            o0.y = acc[mt][nt][1] + sbias[nloc+1];
            o1.x = acc[mt][nt][2] + sbias[nloc];
            o1.y = acc[mt][nt][3] + sbias[nloc+1];
            *(float2*)&g_xg[(size_t)m0*GATES + n0] = o0;
            *(float2*)&g_xg[(size_t)(m0+8)*GATES + n0] = o1;
        }
    }
}

// ---------------- persistent encoder layer-0 LSTM (bf16-split mma) --------
// Block: units u0..u0+5 (24 gate rows), M=64 batches, K=768, CHK=128, 3 phases.
__global__ __launch_bounds__(256) void k_enc(const float* __restrict__ Whh)
{
    extern __shared__ char smraw[];
    __nv_bfloat16* Whi = (__nv_bfloat16*)smraw;            // 24*776
    __nv_bfloat16* Wlo = Whi + RPB*WPAD;                   // 24*776
    __nv_bfloat16* hsm = Wlo + RPB*WPAD;                   // 8 subtiles * 16KB = 131072B
    float* gA  = (float*)(hsm + 65536);                    // 24*66
    float* gB  = gA + RPB*66;
    float* c_s = gB + RPB*66;                              // 384

    const int tid  = threadIdx.x;
    const int wid  = tid >> 5;
    const int lane = tid & 31;
    const int mw   = wid & 3;
    const int kh   = wid >> 2;
    const int u0   = blockIdx.x * UPB;

    for (int e = tid; e < RPB*HID; e += 256) {
        int rr = e / HID, k = e % HID;
        int grow = (rr/UPB)*HID + u0 + (rr%UPB);
        float w = Whh[(size_t)grow*HID + k];
        __nv_bfloat16 hi = __float2bfloat16(w);
        __nv_bfloat16 lo = __float2bfloat16(w - __bfloat162float(hi));
        Whi[rr*WPAD + k] = hi;
        Wlo[rr*WPAD + k] = lo;
    }
    for (int e = tid; e < UPB*BATCH; e += 256) c_s[e] = 0.f;

    uint32_t hs_base = (uint32_t)__cvta_generic_to_shared(hsm);

    const int l4 = lane >> 2;
    const int l2 = lane & 3;
    int growx[3][2];
#pragma unroll
    for (int nt = 0; nt < 3; nt++)
#pragma unroll
        for (int jj = 0; jj < 2; jj++) {
            int row = nt*8 + 2*l2 + jj;
            growx[nt][jj] = (row/UPB)*HID + u0 + (row%UPB);
        }
    const int bx0 = 16*mw + l4;

    __syncthreads();

    for (int t = 0; t < S_LEN; t++) {
        const __nv_bfloat16* hhi = g_hhi[t & 1];
        const __nv_bfloat16* hlo = g_hlo[t & 1];
        const float* xg = g_xg + (size_t)t * BATCH * GATES;

        float xv[3][2][2];
        if (kh == 0) {
#pragma unroll
            for (int nt = 0; nt < 3; nt++)
#pragma unroll
                for (int jj = 0; jj < 2; jj++)
#pragma unroll
                    for (int ii = 0; ii < 2; ii++)
                        xv[nt][jj][ii] = __ldcg(xg + (size_t)(bx0 + 8*ii)*GATES + growx[nt][jj]);
        }

        float acc[3][4];
#pragma unroll
        for (int nt = 0; nt < 3; nt++)
#pragma unroll
            for (int j = 0; j < 4; j++) acc[nt][j] = 0.f;

        // stage phase 0: 4096 granules (16/thread)
        // decode: s=g&15, b=(g>>4)&63, pl=(g>>10)&1, k2=g>>11
        {
#pragma unroll
            for (int i = 0; i < 16; i++) {
                int g = tid + i*256;
                int s = g & 15, b = (g >> 4) & 63, pl = (g >> 10) & 1, k2 = g >> 11;
                uint32_t dst = hs_base + (uint32_t)((k2*2 + pl)*16384 + b*256 + ((s ^ (b&7))*16));
                const __nv_bfloat16* src = (pl ? hlo : hhi) + (size_t)b*HID + k2*384 + s*8;
                asm volatile("cp.async.cg.shared.global [%0], [%1], 16;" :: "r"(dst), "l"(src));
            }
            asm volatile("cp.async.commit_group;");
        }

        for (int ph = 0; ph < 3; ph++) {
            if (ph < 2) {
#pragma unroll
                for (int i = 0; i < 16; i++) {
                    int g = tid + i*256;
                    int s = g & 15, b = (g >> 4) & 63, pl = (g >> 10) & 1, k2 = g >> 11;
                    uint32_t dst = hs_base + (uint32_t)((((ph+1)&1)*4 + k2*2 + pl)*16384 + b*256 + ((s ^ (b&7))*16));
                    const __nv_bfloat16* src = (pl ? hlo : hhi) + (size_t)b*HID + k2*384 + (ph+1)*128 + s*8;
                    asm volatile("cp.async.cg.shared.global [%0], [%1], 16;" :: "r"(dst), "l"(src));
                }
                asm volatile("cp.async.commit_group;");
                asm volatile("cp.async.wait_group 1;");
            } else {
                asm volatile("cp.async.wait_group 0;");
            }
            __syncthreads();

            uint32_t subhi = hs_base + (uint32_t)(((ph&1)*4 + kh*2)*16384);
            uint32_t sublo = subhi + 16384;
            const int rr = lane & 15, sg = lane >> 4;
            const uint32_t rowoff = (uint32_t)((16*mw + rr)*256);
            const uint32_t swz = (uint32_t)((rr&7)*16);
#pragma unroll
            for (int ks = 0; ks < 8; ks++) {
                uint32_t coff = (uint32_t)(ks*32 + sg*16) ^ swz;
                uint32_t ahi[4], alo[4];
                ldsm4(ahi, subhi + rowoff + coff);
                ldsm4(alo, sublo + rowoff + coff);
                const int kcol = kh*384 + ph*128 + ks*16 + 2*l2;
#pragma unroll
                for (int nt = 0; nt < 3; nt++) {
                    const int widx = (nt*8 + l4)*WPAD + kcol;
                    uint32_t bh0 = *(const uint32_t*)&Whi[widx];
                    uint32_t bh1 = *(const uint32_t*)&Whi[widx + 8];
                    uint32_t bl0 = *(const uint32_t*)&Wlo[widx];
                    uint32_t bl1 = *(const uint32_t*)&Wlo[widx + 8];
                    mma_bf16(acc[nt], ahi, bh0, bh1);
                    mma_bf16(acc[nt], ahi, bl0, bl1);
                    mma_bf16(acc[nt], alo, bh0, bh1);
                }
            }
            __syncthreads();
        }

        float* dst = kh ? gB : gA;
#pragma unroll
        for (int nt = 0; nt < 3; nt++) {
            int r0 = nt*8 + 2*l2;
            if (kh == 0) {
                dst[(r0  )*66 + bx0    ] = acc[nt][0] + xv[nt][0][0];
                dst[(r0+1)*66 + bx0    ] = acc[nt][1] + xv[nt][1][0];
                dst[(r0  )*66 + bx0 + 8] = acc[nt][2] + xv[nt][0][1];
                dst[(r0+1)*66 + bx0 + 8] = acc[nt][3] + xv[nt][1][1];
            } else {
                dst[(r0  )*66 + bx0    ] = acc[nt][0];
                dst[(r0+1)*66 + bx0    ] = acc[nt][1];
                dst[(r0  )*66 + bx0 + 8] = acc[nt][2];
                dst[(r0+1)*66 + bx0 + 8] = acc[nt][3];
            }
        }
        __syncthreads();

        __nv_bfloat16* ohi = g_hhi[(t+1)&1];
        __nv_bfloat16* olo = g_hlo[(t+1)&1];
        for (int e = tid; e < UPB*BATCH; e += 256) {
            int u = e % UPB, b = e / UPB;
            float iv = gA[(u)       *66 + b] + gB[(u)       *66 + b];
            float fv = gA[(UPB  +u) *66 + b] + gB[(UPB  +u) *66 + b];
            float gv = gA[(2*UPB+u) *66 + b] + gB[(2*UPB+u) *66 + b];
            float ov = gA[(3*UPB+u) *66 + b] + gB[(3*UPB+u) *66 + b];
            float cp = c_s[e];
            float cn = sigf(fv) * cp + sigf(iv) * tanhf(gv);
            float hn = sigf(ov) * tanhf(cn);
            c_s[e] = cn;
            __nv_bfloat16 hi = __float2bfloat16(hn);
            __nv_bfloat16 lo = __float2bfloat16(hn - __bfloat162float(hi));
            int idx = b*HID + u0 + u;
            ohi[idx] = hi;
            olo[idx] = lo;
            if (t == S_LEN-1) g_hfin[idx] = hn;
        }

        __threadfence();
        __syncthreads();
        if (tid == 0) {
            atomicAdd(&g_bar, 1u);
            unsigned target = (unsigned)(t + 1) * NB;
            while (*((volatile unsigned*)&g_bar) < target) {}
        }
        __syncthreads();
    }
}

// single cell step (encoder layers 1-2, zero state) — fp32
__global__ __launch_bounds__(256) void k_cell(
    const float* __restrict__ h_in, const float* __restrict__ W,
    const float* __restrict__ b1, const float* __restrict__ b2,
    float* __restrict__ h_out, float* __restrict__ h_copy)
{
    __shared__ float hs[64][36];
    __shared__ float ws[32][36];
    __shared__ float gexs[32][65];
    const int tid = threadIdx.x;
    const int u0 = blockIdx.x * 8;
    const int tc = tid & 31;
    const int tr = tid >> 5;
    const int row_c = (tc >> 3) * HID + u0 + (tc & 7);

    const int hb = tid >> 2;
    const int hk = (tid & 3) << 3;
    const int wcc = tid >> 3;
    const int wk = (tid & 7) << 2;
    const int row_w = (wcc >> 3) * HID + u0 + (wcc & 7);

    float acc[8];
#pragma unroll
    for (int i = 0; i < 8; i++) acc[i] = 0.f;

    for (int k0 = 0; k0 < HID; k0 += 32) {
        float4 hv0 = *(const float4*)(h_in + (size_t)hb * HID + k0 + hk);
        float4 hv1 = *(const float4*)(h_in + (size_t)hb * HID + k0 + hk + 4);
        float4 wv  = *(const float4*)(W + (size_t)row_w * HID + k0 + wk);
        *(float4*)&hs[hb][hk]     = hv0;
        *(float4*)&hs[hb][hk + 4] = hv1;
        *(float4*)&ws[wcc][wk]    = wv;
        __syncthreads();
#pragma unroll
        for (int kk = 0; kk < 32; kk += 4) {
            float4 w4 = *(const float4*)&ws[tc][kk];
#pragma unroll
            for (int i = 0; i < 8; i++) {
                float4 h4 = *(const float4*)&hs[tr*8 + i][kk];
                acc[i] = fmaf(h4.x, w4.x, acc[i]);
                acc[i] = fmaf(h4.y, w4.y, acc[i]);
                acc[i] = fmaf(h4.z, w4.z, acc[i]);
                acc[i] = fmaf(h4.w, w4.w, acc[i]);
            }
        }
        __syncthreads();
    }

    float bb = b1[row_c] + b2[row_c];
#pragma unroll
    for (int i = 0; i < 8; i++) gexs[tc][tr*8 + i] = acc[i] + bb;
    __syncthreads();

    for (int it = tid; it < 512; it += 256) {
        int b = it >> 3, ul = it & 7;
        float iv = gexs[ul][b];
        float gv = gexs[16 + ul][b];
        float ov = gexs[24 + ul][b];
        float cn = sigf(iv) * tanhf(gv);
        float hn = sigf(ov) * tanhf(cn);
        int idx = b * HID + u0 + ul;
        h_out[idx] = hn;
        if (h_copy) h_copy[idx] = hn;
    }
}

// ---------------- persistent decoder ----------------
__global__ __launch_bounds__(256) void k_decp(
    const float* __restrict__ W2, const float* __restrict__ db1,
    const float* __restrict__ db2, const float* __restrict__ linW,
    const float* __restrict__ linb, float* __restrict__ out)
{
    extern __shared__ float sm[];
    float* W2s   = sm;
    float* linWs = W2s + RPB*HID;
    float* hbuf  = linWs + 2*HID;
    float* gs    = hbuf + HID;
    float* bs    = gs + 32;
    float* red   = bs + 32;
    float* osv   = red + 8;
    float* lbs   = osv + 2;

    const int tid = threadIdx.x;
    const int u0 = blockIdx.x * UPB;
    const int f0 = blockIdx.x * 2;

    for (int e = tid; e < RPB*(HID/4); e += 256) {
        int r = e / (HID/4), c4 = e % (HID/4);
        int grow = (r/UPB)*HID + u0 + (r%UPB);
        ((float4*)W2s)[e] = ((const float4*)(W2 + (size_t)grow*HID))[c4];
    }
    for (int e = tid; e < 2*(HID/4); e += 256)
        ((float4*)linWs)[e] = ((const float4*)(linW + (size_t)f0*HID))[e];
    if (tid < RPB) {
        int grow = (tid/UPB)*HID + u0 + (tid%UPB);
        bs[tid] = db1[grow] + db2[grow];
    }
    if (tid < 2) lbs[tid] = linb[f0 + tid];
    __syncthreads();

    for (int t = 0; t < TLEN; t++) {
        const float* h_in  = g_hd[t & 1];
        float*       h_out = g_hd[(t + 1) & 1];

        for (int e = tid; e < HID; e += 256) hbuf[e] = __ldcg(&h_in[e]);
        __syncthreads();

        if (tid < 192) {
            int r = tid >> 3, s = tid & 7;
            const float4* W4 = (const float4*)(W2s + r*HID + s*96);
            const float4* h4 = (const float4*)(hbuf + s*96);
            float sum = 0.f;
#pragma unroll
            for (int m = 0; m < 24; m++) {
                float4 wv = W4[m]; float4 hv = h4[m];
                sum += wv.x*hv.x + wv.y*hv.y + wv.z*hv.z + wv.w*hv.w;
            }
#pragma unroll
            for (int off = 4; off > 0; off >>= 1)
                sum += __shfl_down_sync(0xffffffffu, sum, off, 8);
            if (s == 0) gs[r] = sum + bs[r];
        }
        __syncthreads();
        if (tid < UPB) {
            float iv = gs[tid], gv = gs[2*UPB + tid], ov = gs[3*UPB + tid];
            float cn = sigf(iv) * tanhf(gv);
            float hn = sigf(ov) * tanhf(cn);
            __stcg(&h_out[u0 + tid], hn);
        }
        __threadfence();
        __syncthreads();
        if (tid == 0) {
            atomicAdd(&g_bar, 1u);
            unsigned target = (unsigned)(S_LEN * NB) + (unsigned)(t + 1) * NB;
            while (*((volatile unsigned*)&g_bar) < target) {}
        }
        __syncthreads();

        for (int e = tid; e < HID; e += 256) hbuf[e] = __ldcg(&h_out[e]);
        __syncthreads();
        {
            int fl = tid >> 7;
            int i  = tid & 127;
            float p = 0.f;
#pragma unroll
            for (int m = 0; m < 6; m++)
                p += linWs[fl*HID + i + 128*m] * hbuf[i + 128*m];
#pragma unroll
            for (int off = 16; off > 0; off >>= 1)
                p += __shfl_down_sync(0xffffffffu, p, off);
            if ((tid & 31) == 0) red[tid >> 5] = p;
        }
        __syncthreads();
        if (tid < 2)
            osv[tid] = red[tid*4] + red[tid*4+1] + red[tid*4+2] + red[tid*4+3] + lbs[tid];
        __syncthreads();
        if (tid < 128) {
            int b = tid & 63, fl = tid >> 6;
            out[(size_t)t*BATCH*FEAT + b*FEAT + f0 + fl] = osv[fl];
        }
        __syncthreads();
    }
}

extern "C" void kernel_launch(void* const* d_in, const int* in_sizes, int n_in,
                              void* d_out, int out_size)
{
    const float* x     = (const float*)d_in[0];
    const float* Wih0  = (const float*)d_in[1];
    const float* Whh0  = (const float*)d_in[2];
    const float* bih0  = (const float*)d_in[3];
    const float* bhh0  = (const float*)d_in[4];
    const float* eWih  = (const float*)d_in[5];
    const float* ebih  = (const float*)d_in[7];
    const float* ebhh  = (const float*)d_in[8];
    const float* dWih  = (const float*)d_in[9];
    const float* dbih  = (const float*)d_in[11];
    const float* dbhh  = (const float*)d_in[12];
    const float* linW  = (const float*)d_in[13];
    const float* linb  = (const float*)d_in[14];
    float* out = (float*)d_out;

    float *p_hfin, *p_h1, *p_scr;
    cudaGetSymbolAddress((void**)&p_hfin, g_hfin);
    cudaGetSymbolAddress((void**)&p_h1,   g_h1);
    cudaGetSymbolAddress((void**)&p_scr,  g_scr);

    __nv_bfloat16 *p_xhi, *p_xlo, *p_whi, *p_wlo;
    cudaGetSymbolAddress((void**)&p_xhi, g_xhi);
    cudaGetSymbolAddress((void**)&p_xlo, g_xlo);
    cudaGetSymbolAddress((void**)&p_whi, g_whi);
    cudaGetSymbolAddress((void**)&p_wlo, g_wlo);

    const int enc_smem = 2*RPB*WPAD*2 + 131072 + 2*RPB*66*4 + UPB*BATCH*4;
    const int xg_smem  = 131072 + 132*4;

    static int smem_set = 0;
    if (!smem_set) {
        cudaFuncSetAttribute(k_enc,    cudaFuncAttributeMaxDynamicSharedMemorySize, enc_smem);
        cudaFuncSetAttribute(k_xg_mma, cudaFuncAttributeMaxDynamicSharedMemorySize, xg_smem);
        cudaFuncSetAttribute(k_decp,   cudaFuncAttributeMaxDynamicSharedMemorySize, 90000);
        smem_set = 1;
    }

    k_init<<<192, 256>>>();
    k_cvt<<<(XM*FEAT + 511)/512, 512>>>(x, p_xhi, p_xlo, XM*FEAT);
    k_cvt<<<(GATES*FEAT + 511)/512, 512>>>(Wih0, p_whi, p_wlo, GATES*FEAT);
    k_xg_mma<<<dim3(24, 128), 256, xg_smem>>>(bih0, bhh0);

    k_enc<<<NB, 256, enc_smem>>>(Whh0);

    cudaMemcpyAsync(out + OUT_ENC_OFF, p_hfin, BATCH * HID * sizeof(float),
                    cudaMemcpyDeviceToDevice);
    k_cell<<<96, 256>>>(p_hfin, eWih, ebih, ebhh,
                        p_h1, out + OUT_ENC_OFF + BATCH * HID);
    k_cell<<<96, 256>>>(p_h1, eWih + (size_t)GATES * HID,
                        ebih + GATES, ebhh + GATES,
                        p_scr, out + OUT_ENC_OFF + 2 * BATCH * HID);

    k_decp<<<NB, 256, 90000>>>(dWih + (size_t)2 * GATES * HID,
                               dbih + 2 * GATES, dbhh + 2 * GATES,
                               linW, linb, out);
}

// round 8
// speedup vs baseline: 4.3490x; 1.2635x over previous
#include <cuda_runtime.h>
#include <cuda_bf16.h>
#include <math.h>
#include <stdint.h>

#define S_LEN 256
#define BATCH 64
#define FEAT  256
#define HID   768
#define GATES 3072
#define TLEN  32
#define OUT_ENC_OFF (TLEN*BATCH*FEAT)
#define XM    (S_LEN*BATCH)

#define NB   128
#define UPB  6
#define RPB  24
#define WPAD 776

// xg stored TRANSPOSED: [t][gate_row][batch]  (row-major, 64 floats per row)
static __device__ float g_xg[(size_t)S_LEN*GATES*BATCH];
static __device__ __nv_bfloat16 g_xhi[(size_t)XM*FEAT];
static __device__ __nv_bfloat16 g_xlo[(size_t)XM*FEAT];
static __device__ __nv_bfloat16 g_whi[(size_t)GATES*FEAT];
static __device__ __nv_bfloat16 g_wlo[(size_t)GATES*FEAT];
static __device__ __nv_bfloat16 g_hhi[2][BATCH*HID];
static __device__ __nv_bfloat16 g_hlo[2][BATCH*HID];
static __device__ float g_hd[2][HID];
static __device__ unsigned g_bar;

__device__ __forceinline__ float sigf(float x){ return 1.0f/(1.0f+expf(-x)); }

__device__ __forceinline__ void mma_bf16(float* c, const uint32_t* a, uint32_t b0, uint32_t b1){
    asm volatile(
        "mma.sync.aligned.m16n8k16.row.col.f32.bf16.bf16.f32 "
        "{%0,%1,%2,%3}, {%4,%5,%6,%7}, {%8,%9}, {%0,%1,%2,%3};"
        : "+f"(c[0]), "+f"(c[1]), "+f"(c[2]), "+f"(c[3])
        : "r"(a[0]), "r"(a[1]), "r"(a[2]), "r"(a[3]), "r"(b0), "r"(b1));
}
__device__ __forceinline__ void ldsm4(uint32_t* a, uint32_t addr){
    asm volatile("ldmatrix.sync.aligned.m8n8.x4.shared.b16 {%0,%1,%2,%3}, [%4];"
        : "=r"(a[0]), "=r"(a[1]), "=r"(a[2]), "=r"(a[3]) : "r"(addr));
}

__global__ void k_init() {
    int i = blockIdx.x*blockDim.x + threadIdx.x;
    if (i < BATCH*HID/2) {
        ((uint32_t*)g_hhi[0])[i] = 0u;
        ((uint32_t*)g_hlo[0])[i] = 0u;
    }
    if (i < HID) g_hd[0][i] = 0.f;
    if (i == 0) g_bar = 0u;
}

__global__ void k_cvt(const float* __restrict__ src,
                      __nv_bfloat16* __restrict__ dhi,
                      __nv_bfloat16* __restrict__ dlo, int n) {
    int i = blockIdx.x*blockDim.x + threadIdx.x;
    if (i < n) {
        float v = src[i];
        __nv_bfloat16 hi = __float2bfloat16(v);
        dhi[i] = hi;
        dlo[i] = __float2bfloat16(v - __bfloat162float(hi));
    }
}

// ---------------- tensor-core xg GEMM: xgT[t][r][b] = X @ Wih0^T + b -------
__global__ __launch_bounds__(256) void k_xg_mma(
    const float* __restrict__ b1, const float* __restrict__ b2)
{
    extern __shared__ char smraw[];
    uint32_t xs_base = (uint32_t)__cvta_generic_to_shared(smraw);
    uint32_t ws_base = xs_base + 65536;
    float* sbias = (float*)(smraw + 131072);

    const int tid  = threadIdx.x;
    const int wid  = tid >> 5;
    const int lane = tid & 31;
    const int mw   = wid & 3;
    const int nw   = wid >> 2;
    const int bn   = blockIdx.x * 128;
    const int bm   = blockIdx.y * 128;
    const int l4 = lane >> 2;
    const int l2 = lane & 3;
    const int r  = lane & 15;
    const int seg = lane >> 4;

    if (tid < 128) sbias[tid] = b1[bn+tid] + b2[bn+tid];

    float acc[2][8][4];
#pragma unroll
    for (int mt = 0; mt < 2; mt++)
#pragma unroll
        for (int nt = 0; nt < 8; nt++)
#pragma unroll
            for (int j = 0; j < 4; j++) acc[mt][nt][j] = 0.f;

    for (int ph = 0; ph < 2; ph++) {
        __syncthreads();
#pragma unroll
        for (int i = 0; i < 16; i++) {
            int g = tid + i*256;
            int s = g & 15, row = (g >> 4) & 127, pl = g >> 11;
            uint32_t dst = xs_base + (uint32_t)(pl*32768 + row*256 + ((s ^ (row&7))*16));
            const __nv_bfloat16* src = (pl ? g_xlo : g_xhi) + (size_t)(bm+row)*FEAT + ph*128 + s*8;
            asm volatile("cp.async.cg.shared.global [%0], [%1], 16;" :: "r"(dst), "l"(src));
        }
#pragma unroll
        for (int i = 0; i < 16; i++) {
            int g = tid + i*256;
            int s = g & 15, row = (g >> 4) & 127, pl = g >> 11;
            uint32_t dst = ws_base + (uint32_t)(pl*32768 + row*256 + ((s ^ (row&7))*16));
            const __nv_bfloat16* src = (pl ? g_wlo : g_whi) + (size_t)(bn+row)*FEAT + ph*128 + s*8;
            asm volatile("cp.async.cg.shared.global [%0], [%1], 16;" :: "r"(dst), "l"(src));
        }
        asm volatile("cp.async.commit_group;");
        asm volatile("cp.async.wait_group 0;");
        __syncthreads();

#pragma unroll
        for (int ks = 0; ks < 8; ks++) {
            uint32_t ahi[2][4], alo[2][4];
#pragma unroll
            for (int mt = 0; mt < 2; mt++) {
                uint32_t rowoff = (uint32_t)((mw*32 + mt*16 + r)*256);
                uint32_t coff = (uint32_t)((ks*32 + seg*16) ^ ((r&7)*16));
                ldsm4(ahi[mt], xs_base + rowoff + coff);
                ldsm4(alo[mt], xs_base + 32768 + rowoff + coff);
            }
#pragma unroll
            for (int nt = 0; nt < 8; nt++) {
                int wrow = nw*64 + nt*8 + l4;
                uint32_t wb = ws_base + (uint32_t)(wrow*256 + 4*l2);
                uint32_t s0 = (uint32_t)(((ks*2  ) ^ (wrow&7))*16);
                uint32_t s1 = (uint32_t)(((ks*2+1) ^ (wrow&7))*16);
                uint32_t bh0 = *(const uint32_t*)__cvta_shared_to_generic((size_t)(wb + s0));
                uint32_t bh1 = *(const uint32_t*)__cvta_shared_to_generic((size_t)(wb + s1));
                uint32_t bl0 = *(const uint32_t*)__cvta_shared_to_generic((size_t)(wb + 32768 + s0));
                uint32_t bl1 = *(const uint32_t*)__cvta_shared_to_generic((size_t)(wb + 32768 + s1));
#pragma unroll
                for (int mt = 0; mt < 2; mt++) {
                    mma_bf16(acc[mt][nt], ahi[mt], bh0, bh1);
                    mma_bf16(acc[mt][nt], ahi[mt], bl0, bl1);
                    mma_bf16(acc[mt][nt], alo[mt], bh0, bh1);
                }
            }
        }
    }

    // epilogue: transposed store xgT[t][r][b]
#pragma unroll
    for (int mt = 0; mt < 2; mt++) {
#pragma unroll
        for (int nt = 0; nt < 8; nt++) {
            int nloc = nw*64 + nt*8 + 2*l2;
            int n0 = bn + nloc;
            int m0 = bm + mw*32 + mt*16 + l4;
            int t = m0 >> 6, b = m0 & 63;
            size_t base = (size_t)t*GATES*BATCH;
            float bi0 = sbias[nloc], bi1 = sbias[nloc+1];
            g_xg[base + (size_t)n0*BATCH + b]         = acc[mt][nt][0] + bi0;
            g_xg[base + (size_t)(n0+1)*BATCH + b]     = acc[mt][nt][1] + bi1;
            g_xg[base + (size_t)n0*BATCH + b + 8]     = acc[mt][nt][2] + bi0;
            g_xg[base + (size_t)(n0+1)*BATCH + b + 8] = acc[mt][nt][3] + bi1;
        }
    }
}

// ---------------- persistent encoder: 256 LSTM steps + 2 tail layers ------
__device__ __forceinline__ void load_xv(int t, int kh, int bx0,
                                        const int growx[3][2], float xv[3][2][2],
                                        const float* __restrict__ eb1,
                                        const float* __restrict__ eb2)
{
    if (kh != 0 || t >= 258) return;
    if (t < 256) {
        const float* xg = g_xg + (size_t)t * GATES * BATCH;
#pragma unroll
        for (int nt = 0; nt < 3; nt++)
#pragma unroll
            for (int jj = 0; jj < 2; jj++) {
                const float* rowp = xg + (size_t)growx[nt][jj]*BATCH + bx0;
                xv[nt][jj][0] = __ldcg(rowp);
                xv[nt][jj][1] = __ldcg(rowp + 8);
            }
    } else {
        int l = t - 256;
#pragma unroll
        for (int nt = 0; nt < 3; nt++)
#pragma unroll
            for (int jj = 0; jj < 2; jj++) {
                float bb = __ldg(eb1 + l*GATES + growx[nt][jj]) +
                           __ldg(eb2 + l*GATES + growx[nt][jj]);
                xv[nt][jj][0] = bb;
                xv[nt][jj][1] = bb;
            }
    }
}

__global__ __launch_bounds__(256) void k_enc(
    const float* __restrict__ Whh, const float* __restrict__ eWih,
    const float* __restrict__ ebih, const float* __restrict__ ebhh,
    float* __restrict__ out)
{
    extern __shared__ char smraw[];
    __nv_bfloat16* Whi = (__nv_bfloat16*)smraw;
    __nv_bfloat16* Wlo = Whi + RPB*WPAD;
    __nv_bfloat16* hsm = Wlo + RPB*WPAD;
    float* gA  = (float*)(hsm + 65536);
    float* gB  = gA + RPB*66;
    float* c_s = gB + RPB*66;

    const int tid  = threadIdx.x;
    const int wid  = tid >> 5;
    const int lane = tid & 31;
    const int mw   = wid & 3;
    const int kh   = wid >> 2;
    const int u0   = blockIdx.x * UPB;

    for (int e = tid; e < RPB*HID; e += 256) {
        int rr = e / HID, k = e % HID;
        int grow = (rr/UPB)*HID + u0 + (rr%UPB);
        float w = Whh[(size_t)grow*HID + k];
        __nv_bfloat16 hi = __float2bfloat16(w);
        __nv_bfloat16 lo = __float2bfloat16(w - __bfloat162float(hi));
        Whi[rr*WPAD + k] = hi;
        Wlo[rr*WPAD + k] = lo;
    }
    for (int e = tid; e < UPB*BATCH; e += 256) c_s[e] = 0.f;

    uint32_t hs_base = (uint32_t)__cvta_generic_to_shared(hsm);

    const int l4 = lane >> 2;
    const int l2 = lane & 3;
    int growx[3][2];
#pragma unroll
    for (int nt = 0; nt < 3; nt++)
#pragma unroll
        for (int jj = 0; jj < 2; jj++) {
            int row = nt*8 + 2*l2 + jj;
            growx[nt][jj] = (row/UPB)*HID + u0 + (row%UPB);
        }
    const int bx0 = 16*mw + l4;

    float xv[3][2][2];
    load_xv(0, kh, bx0, growx, xv, ebih, ebhh);

    __syncthreads();

    for (int t = 0; t < 258; t++) {
        if (t >= 256) {
            // reload W planes from encoder layer t-256 weights
            const float* Wsrc = eWih + (size_t)(t - 256) * GATES * HID;
            for (int e = tid; e < RPB*HID; e += 256) {
                int rr = e / HID, k = e % HID;
                int grow = (rr/UPB)*HID + u0 + (rr%UPB);
                float w = Wsrc[(size_t)grow*HID + k];
                __nv_bfloat16 hi = __float2bfloat16(w);
                __nv_bfloat16 lo = __float2bfloat16(w - __bfloat162float(hi));
                Whi[rr*WPAD + k] = hi;
                Wlo[rr*WPAD + k] = lo;
            }
            __syncthreads();
        }

        const __nv_bfloat16* hhi = g_hhi[t & 1];
        const __nv_bfloat16* hlo = g_hlo[t & 1];

        float acc[3][4];
#pragma unroll
        for (int nt = 0; nt < 3; nt++)
#pragma unroll
            for (int j = 0; j < 4; j++) acc[nt][j] = 0.f;

        {
#pragma unroll
            for (int i = 0; i < 16; i++) {
                int g = tid + i*256;
                int s = g & 15, b = (g >> 4) & 63, pl = (g >> 10) & 1, k2 = g >> 11;
                uint32_t dst = hs_base + (uint32_t)((k2*2 + pl)*16384 + b*256 + ((s ^ (b&7))*16));
                const __nv_bfloat16* src = (pl ? hlo : hhi) + (size_t)b*HID + k2*384 + s*8;
                asm volatile("cp.async.cg.shared.global [%0], [%1], 16;" :: "r"(dst), "l"(src));
            }
            asm volatile("cp.async.commit_group;");
        }

        for (int ph = 0; ph < 3; ph++) {
            if (ph < 2) {
#pragma unroll
                for (int i = 0; i < 16; i++) {
                    int g = tid + i*256;
                    int s = g & 15, b = (g >> 4) & 63, pl = (g >> 10) & 1, k2 = g >> 11;
                    uint32_t dst = hs_base + (uint32_t)((((ph+1)&1)*4 + k2*2 + pl)*16384 + b*256 + ((s ^ (b&7))*16));
                    const __nv_bfloat16* src = (pl ? hlo : hhi) + (size_t)b*HID + k2*384 + (ph+1)*128 + s*8;
                    asm volatile("cp.async.cg.shared.global [%0], [%1], 16;" :: "r"(dst), "l"(src));
                }
                asm volatile("cp.async.commit_group;");
                asm volatile("cp.async.wait_group 1;");
            } else {
                asm volatile("cp.async.wait_group 0;");
            }
            __syncthreads();

            uint32_t subhi = hs_base + (uint32_t)(((ph&1)*4 + kh*2)*16384);
            uint32_t sublo = subhi + 16384;
            const int rr = lane & 15, sg = lane >> 4;
            const uint32_t rowoff = (uint32_t)((16*mw + rr)*256);
            const uint32_t swz = (uint32_t)((rr&7)*16);
#pragma unroll
            for (int ks = 0; ks < 8; ks++) {
                uint32_t coff = (uint32_t)(ks*32 + sg*16) ^ swz;
                uint32_t ahi[4], alo[4];
                ldsm4(ahi, subhi + rowoff + coff);
                ldsm4(alo, sublo + rowoff + coff);
                const int kcol = kh*384 + ph*128 + ks*16 + 2*l2;
#pragma unroll
                for (int nt = 0; nt < 3; nt++) {
                    const int widx = (nt*8 + l4)*WPAD + kcol;
                    uint32_t bh0 = *(const uint32_t*)&Whi[widx];
                    uint32_t bh1 = *(const uint32_t*)&Whi[widx + 8];
                    uint32_t bl0 = *(const uint32_t*)&Wlo[widx];
                    uint32_t bl1 = *(const uint32_t*)&Wlo[widx + 8];
                    mma_bf16(acc[nt], ahi, bh0, bh1);
                    mma_bf16(acc[nt], ahi, bl0, bl1);
                    mma_bf16(acc[nt], alo, bh0, bh1);
                }
            }
            __syncthreads();
        }

        float* dst = kh ? gB : gA;
#pragma unroll
        for (int nt = 0; nt < 3; nt++) {
            int r0 = nt*8 + 2*l2;
            if (kh == 0) {
                dst[(r0  )*66 + bx0    ] = acc[nt][0] + xv[nt][0][0];
                dst[(r0+1)*66 + bx0    ] = acc[nt][1] + xv[nt][1][0];
                dst[(r0  )*66 + bx0 + 8] = acc[nt][2] + xv[nt][0][1];
                dst[(r0+1)*66 + bx0 + 8] = acc[nt][3] + xv[nt][1][1];
            } else {
                dst[(r0  )*66 + bx0    ] = acc[nt][0];
                dst[(r0+1)*66 + bx0    ] = acc[nt][1];
                dst[(r0  )*66 + bx0 + 8] = acc[nt][2];
                dst[(r0+1)*66 + bx0 + 8] = acc[nt][3];
            }
        }
        __syncthreads();

        __nv_bfloat16* ohi = g_hhi[(t+1)&1];
        __nv_bfloat16* olo = g_hlo[(t+1)&1];
        for (int e = tid; e < UPB*BATCH; e += 256) {
            int u = e % UPB, b = e / UPB;
            float iv = gA[(u)       *66 + b] + gB[(u)       *66 + b];
            float fv = gA[(UPB  +u) *66 + b] + gB[(UPB  +u) *66 + b];
            float gv = gA[(2*UPB+u) *66 + b] + gB[(2*UPB+u) *66 + b];
            float ov = gA[(3*UPB+u) *66 + b] + gB[(3*UPB+u) *66 + b];
            float cn, hn;
            if (t < 256) {
                float cp = c_s[e];
                cn = sigf(fv) * cp + sigf(iv) * tanhf(gv);
                c_s[e] = cn;
            } else {
                cn = sigf(iv) * tanhf(gv);   // zero state: forget term drops
            }
            hn = sigf(ov) * tanhf(cn);
            int idx = b*HID + u0 + u;
            ohi[idx] = __float2bfloat16(hn);
            olo[idx] = __float2bfloat16(hn - __bfloat162float(__float2bfloat16(hn)));
            if (t == 255) out[OUT_ENC_OFF + idx] = hn;                 // layer 0
            else if (t == 256) out[OUT_ENC_OFF + BATCH*HID + idx] = hn; // layer 1
            else if (t == 257) out[OUT_ENC_OFF + 2*BATCH*HID + idx] = hn;
        }

        __threadfence();
        __syncthreads();
        if (tid == 0) atomicAdd(&g_bar, 1u);
        // prefetch next step's xv/bias into the barrier-wait shadow
        load_xv(t + 1, kh, bx0, growx, xv, ebih, ebhh);
        if (tid == 0) {
            unsigned target = (unsigned)(t + 1) * NB;
            while (*((volatile unsigned*)&g_bar) < target) {}
        }
        __syncthreads();
    }
}

// ---------------- persistent decoder ----------------
__global__ __launch_bounds__(256) void k_decp(
    const float* __restrict__ W2, const float* __restrict__ db1,
    const float* __restrict__ db2, const float* __restrict__ linW,
    const float* __restrict__ linb, float* __restrict__ out)
{
    extern __shared__ float sm[];
    float* W2s   = sm;
    float* linWs = W2s + RPB*HID;
    float* hbuf  = linWs + 2*HID;
    float* gs    = hbuf + HID;
    float* bs    = gs + 32;
    float* red   = bs + 32;
    float* osv   = red + 8;
    float* lbs   = osv + 2;

    const int tid = threadIdx.x;
    const int u0 = blockIdx.x * UPB;
    const int f0 = blockIdx.x * 2;

    for (int e = tid; e < RPB*(HID/4); e += 256) {
        int r = e / (HID/4), c4 = e % (HID/4);
        int grow = (r/UPB)*HID + u0 + (r%UPB);
        ((float4*)W2s)[e] = ((const float4*)(W2 + (size_t)grow*HID))[c4];
    }
    for (int e = tid; e < 2*(HID/4); e += 256)
        ((float4*)linWs)[e] = ((const float4*)(linW + (size_t)f0*HID))[e];
    if (tid < RPB) {
        int grow = (tid/UPB)*HID + u0 + (tid%UPB);
        bs[tid] = db1[grow] + db2[grow];
    }
    if (tid < 2) lbs[tid] = linb[f0 + tid];
    __syncthreads();

    for (int t = 0; t < TLEN; t++) {
        const float* h_in  = g_hd[t & 1];
        float*       h_out = g_hd[(t + 1) & 1];

        for (int e = tid; e < HID; e += 256) hbuf[e] = __ldcg(&h_in[e]);
        __syncthreads();

        if (tid < 192) {
            int r = tid >> 3, s = tid & 7;
            const float4* W4 = (const float4*)(W2s + r*HID + s*96);
            const float4* h4 = (const float4*)(hbuf + s*96);
            float sum = 0.f;
#pragma unroll
            for (int m = 0; m < 24; m++) {
                float4 wv = W4[m]; float4 hv = h4[m];
                sum += wv.x*hv.x + wv.y*hv.y + wv.z*hv.z + wv.w*hv.w;
            }
#pragma unroll
            for (int off = 4; off > 0; off >>= 1)
                sum += __shfl_down_sync(0xffffffffu, sum, off, 8);
            if (s == 0) gs[r] = sum + bs[r];
        }
        __syncthreads();
        if (tid < UPB) {
            float iv = gs[tid], gv = gs[2*UPB + tid], ov = gs[3*UPB + tid];
            float cn = sigf(iv) * tanhf(gv);
            float hn = sigf(ov) * tanhf(cn);
            __stcg(&h_out[u0 + tid], hn);
        }
        __threadfence();
        __syncthreads();
        if (tid == 0) {
            atomicAdd(&g_bar, 1u);
            unsigned target = (unsigned)(258u * NB) + (unsigned)(t + 1) * NB;
            while (*((volatile unsigned*)&g_bar) < target) {}
        }
        __syncthreads();

        for (int e = tid; e < HID; e += 256) hbuf[e] = __ldcg(&h_out[e]);
        __syncthreads();
        {
            int fl = tid >> 7;
            int i  = tid & 127;
            float p = 0.f;
#pragma unroll
            for (int m = 0; m < 6; m++)
                p += linWs[fl*HID + i + 128*m] * hbuf[i + 128*m];
#pragma unroll
            for (int off = 16; off > 0; off >>= 1)
                p += __shfl_down_sync(0xffffffffu, p, off);
            if ((tid & 31) == 0) red[tid >> 5] = p;
        }
        __syncthreads();
        if (tid < 2)
            osv[tid] = red[tid*4] + red[tid*4+1] + red[tid*4+2] + red[tid*4+3] + lbs[tid];
        __syncthreads();
        if (tid < 128) {
            int b = tid & 63, fl = tid >> 6;
            out[(size_t)t*BATCH*FEAT + b*FEAT + f0 + fl] = osv[fl];
        }
        __syncthreads();
    }
}

extern "C" void kernel_launch(void* const* d_in, const int* in_sizes, int n_in,
                              void* d_out, int out_size)
{
    const float* x     = (const float*)d_in[0];
    const float* Wih0  = (const float*)d_in[1];
    const float* Whh0  = (const float*)d_in[2];
    const float* bih0  = (const float*)d_in[3];
    const float* bhh0  = (const float*)d_in[4];
    const float* eWih  = (const float*)d_in[5];
    const float* ebih  = (const float*)d_in[7];
    const float* ebhh  = (const float*)d_in[8];
    const float* dWih  = (const float*)d_in[9];
    const float* dbih  = (const float*)d_in[11];
    const float* dbhh  = (const float*)d_in[12];
    const float* linW  = (const float*)d_in[13];
    const float* linb  = (const float*)d_in[14];
    float* out = (float*)d_out;

    __nv_bfloat16 *p_xhi, *p_xlo, *p_whi, *p_wlo;
    cudaGetSymbolAddress((void**)&p_xhi, g_xhi);
    cudaGetSymbolAddress((void**)&p_xlo, g_xlo);
    cudaGetSymbolAddress((void**)&p_whi, g_whi);
    cudaGetSymbolAddress((void**)&p_wlo, g_wlo);

    const int enc_smem = 2*RPB*WPAD*2 + 131072 + 2*RPB*66*4 + UPB*BATCH*4;
    const int xg_smem  = 131072 + 132*4;

    static int smem_set = 0;
    if (!smem_set) {
        cudaFuncSetAttribute(k_enc,    cudaFuncAttributeMaxDynamicSharedMemorySize, enc_smem);
        cudaFuncSetAttribute(k_xg_mma, cudaFuncAttributeMaxDynamicSharedMemorySize, xg_smem);
        cudaFuncSetAttribute(k_decp,   cudaFuncAttributeMaxDynamicSharedMemorySize, 90000);
        smem_set = 1;
    }

    k_init<<<192, 256>>>();
    k_cvt<<<(XM*FEAT + 511)/512, 512>>>(x, p_xhi, p_xlo, XM*FEAT);
    k_cvt<<<(GATES*FEAT + 511)/512, 512>>>(Wih0, p_whi, p_wlo, GATES*FEAT);
    k_xg_mma<<<dim3(24, 128), 256, xg_smem>>>(bih0, bhh0);

    k_enc<<<NB, 256, enc_smem>>>(Whh0, eWih, ebih, ebhh, out);

    k_decp<<<NB, 256, 90000>>>(dWih + (size_t)2 * GATES * HID,
                               dbih + 2 * GATES, dbhh + 2 * GATES,
                               linW, linb, out);
}

// round 9
// speedup vs baseline: 5.0702x; 1.1658x over previous
#include <cuda_runtime.h>
#include <cuda_fp16.h>
#include <math.h>
#include <stdint.h>

#define S_LEN 256
#define BATCH 64
#define FEAT  256
#define HID   768
#define GATES 3072
#define TLEN  32
#define OUT_ENC_OFF (TLEN*BATCH*FEAT)
#define XM    (S_LEN*BATCH)

#define NB   128
#define UPB  6
#define RPB  24
#define WPAD 776

// xg stored TRANSPOSED: [t][gate_row][batch]
static __device__ float g_xg[(size_t)S_LEN*GATES*BATCH];
static __device__ __half g_xh[(size_t)XM*FEAT];                 // X hi plane only
static __device__ __half g_whi[(size_t)GATES*FEAT];
static __device__ __half g_wlo[(size_t)GATES*FEAT];
static __device__ __half g_hh[2][BATCH*HID];                    // h single fp16 plane
static __device__ float g_hd[2][HID];
static __device__ unsigned g_bar;

__device__ __forceinline__ float sigf(float x){ return 1.0f/(1.0f+expf(-x)); }

__device__ __forceinline__ void mma_f16(float* c, const uint32_t* a, uint32_t b0, uint32_t b1){
    asm volatile(
        "mma.sync.aligned.m16n8k16.row.col.f32.f16.f16.f32 "
        "{%0,%1,%2,%3}, {%4,%5,%6,%7}, {%8,%9}, {%0,%1,%2,%3};"
        : "+f"(c[0]), "+f"(c[1]), "+f"(c[2]), "+f"(c[3])
        : "r"(a[0]), "r"(a[1]), "r"(a[2]), "r"(a[3]), "r"(b0), "r"(b1));
}
__device__ __forceinline__ void ldsm4(uint32_t* a, uint32_t addr){
    asm volatile("ldmatrix.sync.aligned.m8n8.x4.shared.b16 {%0,%1,%2,%3}, [%4];"
        : "=r"(a[0]), "=r"(a[1]), "=r"(a[2]), "=r"(a[3]) : "r"(addr));
}

__global__ void k_init() {
    int i = blockIdx.x*blockDim.x + threadIdx.x;
    if (i < BATCH*HID/2) ((uint32_t*)g_hh[0])[i] = 0u;
    if (i < HID) g_hd[0][i] = 0.f;
    if (i == 0) g_bar = 0u;
}

// fp32 -> fp16 hi plane only
__global__ void k_cvt1(const float* __restrict__ src, __half* __restrict__ dhi, int n) {
    int i = blockIdx.x*blockDim.x + threadIdx.x;
    if (i < n) dhi[i] = __float2half(src[i]);
}
// fp32 -> fp16 hi/lo planes
__global__ void k_cvt2(const float* __restrict__ src,
                       __half* __restrict__ dhi, __half* __restrict__ dlo, int n) {
    int i = blockIdx.x*blockDim.x + threadIdx.x;
    if (i < n) {
        float v = src[i];
        __half hi = __float2half(v);
        dhi[i] = hi;
        dlo[i] = __float2half(v - __half2float(hi));
    }
}

// ---------------- tensor-core xg GEMM: xgT[t][r][b] = X @ Wih0^T + b -------
// fp16: X hi-only (1 plane), W hi+lo (2 planes); 2 MMA per fragment.
__global__ __launch_bounds__(256) void k_xg_mma(
    const float* __restrict__ b1, const float* __restrict__ b2)
{
    extern __shared__ char smraw[];
    uint32_t xs_base = (uint32_t)__cvta_generic_to_shared(smraw);     // 32KB
    uint32_t ws_base = xs_base + 32768;                               // 64KB (2 planes)
    float* sbias = (float*)(smraw + 98304);

    const int tid  = threadIdx.x;
    const int wid  = tid >> 5;
    const int lane = tid & 31;
    const int mw   = wid & 3;
    const int nw   = wid >> 2;
    const int bn   = blockIdx.x * 128;
    const int bm   = blockIdx.y * 128;
    const int l4 = lane >> 2;
    const int l2 = lane & 3;
    const int r  = lane & 15;
    const int seg = lane >> 4;

    if (tid < 128) sbias[tid] = b1[bn+tid] + b2[bn+tid];

    float acc[2][8][4];
#pragma unroll
    for (int mt = 0; mt < 2; mt++)
#pragma unroll
        for (int nt = 0; nt < 8; nt++)
#pragma unroll
            for (int j = 0; j < 4; j++) acc[mt][nt][j] = 0.f;

    for (int ph = 0; ph < 2; ph++) {
        __syncthreads();
        // X: 2048 granules (8/thread)
#pragma unroll
        for (int i = 0; i < 8; i++) {
            int g = tid + i*256;
            int s = g & 15, row = g >> 4;
            uint32_t dst = xs_base + (uint32_t)(row*256 + ((s ^ (row&7))*16));
            const __half* src = g_xh + (size_t)(bm+row)*FEAT + ph*128 + s*8;
            asm volatile("cp.async.cg.shared.global [%0], [%1], 16;" :: "r"(dst), "l"(src));
        }
        // W: 4096 granules (16/thread), 2 planes
#pragma unroll
        for (int i = 0; i < 16; i++) {
            int g = tid + i*256;
            int s = g & 15, row = (g >> 4) & 127, pl = g >> 11;
            uint32_t dst = ws_base + (uint32_t)(pl*32768 + row*256 + ((s ^ (row&7))*16));
            const __half* src = (pl ? g_wlo : g_whi) + (size_t)(bn+row)*FEAT + ph*128 + s*8;
            asm volatile("cp.async.cg.shared.global [%0], [%1], 16;" :: "r"(dst), "l"(src));
        }
        asm volatile("cp.async.commit_group;");
        asm volatile("cp.async.wait_group 0;");
        __syncthreads();

#pragma unroll
        for (int ks = 0; ks < 8; ks++) {
            uint32_t ahi[2][4];
#pragma unroll
            for (int mt = 0; mt < 2; mt++) {
                uint32_t rowoff = (uint32_t)((mw*32 + mt*16 + r)*256);
                uint32_t coff = (uint32_t)((ks*32 + seg*16) ^ ((r&7)*16));
                ldsm4(ahi[mt], xs_base + rowoff + coff);
            }
#pragma unroll
            for (int nt = 0; nt < 8; nt++) {
                int wrow = nw*64 + nt*8 + l4;
                uint32_t wb = ws_base + (uint32_t)(wrow*256 + 4*l2);
                uint32_t s0 = (uint32_t)(((ks*2  ) ^ (wrow&7))*16);
                uint32_t s1 = (uint32_t)(((ks*2+1) ^ (wrow&7))*16);
                uint32_t bh0 = *(const uint32_t*)__cvta_shared_to_generic((size_t)(wb + s0));
                uint32_t bh1 = *(const uint32_t*)__cvta_shared_to_generic((size_t)(wb + s1));
                uint32_t bl0 = *(const uint32_t*)__cvta_shared_to_generic((size_t)(wb + 32768 + s0));
                uint32_t bl1 = *(const uint32_t*)__cvta_shared_to_generic((size_t)(wb + 32768 + s1));
#pragma unroll
                for (int mt = 0; mt < 2; mt++) {
                    mma_f16(acc[mt][nt], ahi[mt], bh0, bh1);
                    mma_f16(acc[mt][nt], ahi[mt], bl0, bl1);
                }
            }
        }
    }

#pragma unroll
    for (int mt = 0; mt < 2; mt++) {
#pragma unroll
        for (int nt = 0; nt < 8; nt++) {
            int nloc = nw*64 + nt*8 + 2*l2;
            int n0 = bn + nloc;
            int m0 = bm + mw*32 + mt*16 + l4;
            int t = m0 >> 6, b = m0 & 63;
            size_t base = (size_t)t*GATES*BATCH;
            float bi0 = sbias[nloc], bi1 = sbias[nloc+1];
            g_xg[base + (size_t)n0*BATCH + b]         = acc[mt][nt][0] + bi0;
            g_xg[base + (size_t)(n0+1)*BATCH + b]     = acc[mt][nt][1] + bi1;
            g_xg[base + (size_t)n0*BATCH + b + 8]     = acc[mt][nt][2] + bi0;
            g_xg[base + (size_t)(n0+1)*BATCH + b + 8] = acc[mt][nt][3] + bi1;
        }
    }
}

// ---------------- persistent encoder: 256 LSTM steps + 2 tail layers ------
__device__ __forceinline__ void load_xv(int t, int kh, int bx0,
                                        const int growx[3][2], float xv[3][2][2],
                                        const float* __restrict__ eb1,
                                        const float* __restrict__ eb2)
{
    if (kh != 0 || t >= 258) return;
    if (t < 256) {
        const float* xg = g_xg + (size_t)t * GATES * BATCH;
#pragma unroll
        for (int nt = 0; nt < 3; nt++)
#pragma unroll
            for (int jj = 0; jj < 2; jj++) {
                const float* rowp = xg + (size_t)growx[nt][jj]*BATCH + bx0;
                xv[nt][jj][0] = __ldcg(rowp);
                xv[nt][jj][1] = __ldcg(rowp + 8);
            }
    } else {
        int l = t - 256;
#pragma unroll
        for (int nt = 0; nt < 3; nt++)
#pragma unroll
            for (int jj = 0; jj < 2; jj++) {
                float bb = __ldg(eb1 + l*GATES + growx[nt][jj]) +
                           __ldg(eb2 + l*GATES + growx[nt][jj]);
                xv[nt][jj][0] = bb;
                xv[nt][jj][1] = bb;
            }
    }
}

__global__ __launch_bounds__(256) void k_enc(
    const float* __restrict__ Whh, const float* __restrict__ eWih,
    const float* __restrict__ ebih, const float* __restrict__ ebhh,
    float* __restrict__ out)
{
    extern __shared__ char smraw[];
    __half* Whi = (__half*)smraw;                     // 24*776
    __half* Wlo = Whi + RPB*WPAD;                     // 24*776
    __half* hsm = Wlo + RPB*WPAD;                     // 4 subtiles * 16KB = 65536B
    float* gA  = (float*)((char*)hsm + 65536);        // 24*66
    float* gB  = gA + RPB*66;
    float* c_s = gB + RPB*66;                         // 384

    const int tid  = threadIdx.x;
    const int wid  = tid >> 5;
    const int lane = tid & 31;
    const int mw   = wid & 3;
    const int kh   = wid >> 2;
    const int u0   = blockIdx.x * UPB;

    for (int e = tid; e < RPB*HID; e += 256) {
        int rr = e / HID, k = e % HID;
        int grow = (rr/UPB)*HID + u0 + (rr%UPB);
        float w = Whh[(size_t)grow*HID + k];
        __half hi = __float2half(w);
        Whi[rr*WPAD + k] = hi;
        Wlo[rr*WPAD + k] = __float2half(w - __half2float(hi));
    }
    for (int e = tid; e < UPB*BATCH; e += 256) c_s[e] = 0.f;

    uint32_t hs_base = (uint32_t)__cvta_generic_to_shared(hsm);

    const int l4 = lane >> 2;
    const int l2 = lane & 3;
    int growx[3][2];
#pragma unroll
    for (int nt = 0; nt < 3; nt++)
#pragma unroll
        for (int jj = 0; jj < 2; jj++) {
            int row = nt*8 + 2*l2 + jj;
            growx[nt][jj] = (row/UPB)*HID + u0 + (row%UPB);
        }
    const int bx0 = 16*mw + l4;

    float xv[3][2][2];
    load_xv(0, kh, bx0, growx, xv, ebih, ebhh);

    __syncthreads();

    for (int t = 0; t < 258; t++) {
        if (t >= 256) {
            const float* Wsrc = eWih + (size_t)(t - 256) * GATES * HID;
            for (int e = tid; e < RPB*HID; e += 256) {
                int rr = e / HID, k = e % HID;
                int grow = (rr/UPB)*HID + u0 + (rr%UPB);
                float w = Wsrc[(size_t)grow*HID + k];
                __half hi = __float2half(w);
                Whi[rr*WPAD + k] = hi;
                Wlo[rr*WPAD + k] = __float2half(w - __half2float(hi));
            }
            __syncthreads();
        }

        const __half* hh = g_hh[t & 1];

        float acc[3][4];
#pragma unroll
        for (int nt = 0; nt < 3; nt++)
#pragma unroll
            for (int j = 0; j < 4; j++) acc[nt][j] = 0.f;

        // stage phase 0: 2048 granules (8/thread)
        // decode: s=g&15, b=(g>>4)&63, k2=(g>>10)&1
        {
#pragma unroll
            for (int i = 0; i < 8; i++) {
                int g = tid + i*256;
                int s = g & 15, b = (g >> 4) & 63, k2 = (g >> 10) & 1;
                uint32_t dst = hs_base + (uint32_t)(k2*16384 + b*256 + ((s ^ (b&7))*16));
                const __half* src = hh + (size_t)b*HID + k2*384 + s*8;
                asm volatile("cp.async.cg.shared.global [%0], [%1], 16;" :: "r"(dst), "l"(src));
            }
            asm volatile("cp.async.commit_group;");
        }

        for (int ph = 0; ph < 3; ph++) {
            if (ph < 2) {
#pragma unroll
                for (int i = 0; i < 8; i++) {
                    int g = tid + i*256;
                    int s = g & 15, b = (g >> 4) & 63, k2 = (g >> 10) & 1;
                    uint32_t dst = hs_base + (uint32_t)((((ph+1)&1)*2 + k2)*16384 + b*256 + ((s ^ (b&7))*16));
                    const __half* src = hh + (size_t)b*HID + k2*384 + (ph+1)*128 + s*8;
                    asm volatile("cp.async.cg.shared.global [%0], [%1], 16;" :: "r"(dst), "l"(src));
                }
                asm volatile("cp.async.commit_group;");
                asm volatile("cp.async.wait_group 1;");
            } else {
                asm volatile("cp.async.wait_group 0;");
            }
            __syncthreads();

            uint32_t subhi = hs_base + (uint32_t)(((ph&1)*2 + kh)*16384);
            const int rr = lane & 15, sg = lane >> 4;
            const uint32_t rowoff = (uint32_t)((16*mw + rr)*256);
            const uint32_t swz = (uint32_t)((rr&7)*16);
#pragma unroll
            for (int ks = 0; ks < 8; ks++) {
                uint32_t coff = (uint32_t)(ks*32 + sg*16) ^ swz;
                uint32_t ahi[4];
                ldsm4(ahi, subhi + rowoff + coff);
                const int kcol = kh*384 + ph*128 + ks*16 + 2*l2;
#pragma unroll
                for (int nt = 0; nt < 3; nt++) {
                    const int widx = (nt*8 + l4)*WPAD + kcol;
                    uint32_t bh0 = *(const uint32_t*)&Whi[widx];
                    uint32_t bh1 = *(const uint32_t*)&Whi[widx + 8];
                    uint32_t bl0 = *(const uint32_t*)&Wlo[widx];
                    uint32_t bl1 = *(const uint32_t*)&Wlo[widx + 8];
                    mma_f16(acc[nt], ahi, bh0, bh1);
                    mma_f16(acc[nt], ahi, bl0, bl1);
                }
            }
            __syncthreads();
        }

        float* dst = kh ? gB : gA;
#pragma unroll
        for (int nt = 0; nt < 3; nt++) {
            int r0 = nt*8 + 2*l2;
            if (kh == 0) {
                dst[(r0  )*66 + bx0    ] = acc[nt][0] + xv[nt][0][0];
                dst[(r0+1)*66 + bx0    ] = acc[nt][1] + xv[nt][1][0];
                dst[(r0  )*66 + bx0 + 8] = acc[nt][2] + xv[nt][0][1];
                dst[(r0+1)*66 + bx0 + 8] = acc[nt][3] + xv[nt][1][1];
            } else {
                dst[(r0  )*66 + bx0    ] = acc[nt][0];
                dst[(r0+1)*66 + bx0    ] = acc[nt][1];
                dst[(r0  )*66 + bx0 + 8] = acc[nt][2];
                dst[(r0+1)*66 + bx0 + 8] = acc[nt][3];
            }
        }
        __syncthreads();

        __half* oh = g_hh[(t+1)&1];
        for (int e = tid; e < UPB*BATCH; e += 256) {
            int u = e % UPB, b = e / UPB;
            float iv = gA[(u)       *66 + b] + gB[(u)       *66 + b];
            float fv = gA[(UPB  +u) *66 + b] + gB[(UPB  +u) *66 + b];
            float gv = gA[(2*UPB+u) *66 + b] + gB[(2*UPB+u) *66 + b];
            float ov = gA[(3*UPB+u) *66 + b] + gB[(3*UPB+u) *66 + b];
            float cn, hn;
            if (t < 256) {
                float cp = c_s[e];
                cn = sigf(fv) * cp + sigf(iv) * tanhf(gv);
                c_s[e] = cn;
            } else {
                cn = sigf(iv) * tanhf(gv);
            }
            hn = sigf(ov) * tanhf(cn);
            int idx = b*HID + u0 + u;
            oh[idx] = __float2half(hn);
            if (t == 255) out[OUT_ENC_OFF + idx] = hn;
            else if (t == 256) out[OUT_ENC_OFF + BATCH*HID + idx] = hn;
            else if (t == 257) out[OUT_ENC_OFF + 2*BATCH*HID + idx] = hn;
        }

        __threadfence();
        __syncthreads();
        if (tid == 0) atomicAdd(&g_bar, 1u);
        load_xv(t + 1, kh, bx0, growx, xv, ebih, ebhh);
        if (tid == 0) {
            unsigned target = (unsigned)(t + 1) * NB;
            while (*((volatile unsigned*)&g_bar) < target) {}
        }
        __syncthreads();
    }
}

// ---------------- persistent decoder (fp32 exact) ----------------
__global__ __launch_bounds__(256) void k_decp(
    const float* __restrict__ W2, const float* __restrict__ db1,
    const float* __restrict__ db2, const float* __restrict__ linW,
    const float* __restrict__ linb, float* __restrict__ out)
{
    extern __shared__ float sm[];
    float* W2s   = sm;
    float* linWs = W2s + RPB*HID;
    float* hbuf  = linWs + 2*HID;
    float* gs    = hbuf + HID;
    float* bs    = gs + 32;
    float* red   = bs + 32;
    float* osv   = red + 8;
    float* lbs   = osv + 2;

    const int tid = threadIdx.x;
    const int u0 = blockIdx.x * UPB;
    const int f0 = blockIdx.x * 2;

    for (int e = tid; e < RPB*(HID/4); e += 256) {
        int r = e / (HID/4), c4 = e % (HID/4);
        int grow = (r/UPB)*HID + u0 + (r%UPB);
        ((float4*)W2s)[e] = ((const float4*)(W2 + (size_t)grow*HID))[c4];
    }
    for (int e = tid; e < 2*(HID/4); e += 256)
        ((float4*)linWs)[e] = ((const float4*)(linW + (size_t)f0*HID))[e];
    if (tid < RPB) {
        int grow = (tid/UPB)*HID + u0 + (tid%UPB);
        bs[tid] = db1[grow] + db2[grow];
    }
    if (tid < 2) lbs[tid] = linb[f0 + tid];
    __syncthreads();

    for (int t = 0; t < TLEN; t++) {
        const float* h_in  = g_hd[t & 1];
        float*       h_out = g_hd[(t + 1) & 1];

        for (int e = tid; e < HID; e += 256) hbuf[e] = __ldcg(&h_in[e]);
        __syncthreads();

        if (tid < 192) {
            int r = tid >> 3, s = tid & 7;
            const float4* W4 = (const float4*)(W2s + r*HID + s*96);
            const float4* h4 = (const float4*)(hbuf + s*96);
            float sum = 0.f;
#pragma unroll
            for (int m = 0; m < 24; m++) {
                float4 wv = W4[m]; float4 hv = h4[m];
                sum += wv.x*hv.x + wv.y*hv.y + wv.z*hv.z + wv.w*hv.w;
            }
#pragma unroll
            for (int off = 4; off > 0; off >>= 1)
                sum += __shfl_down_sync(0xffffffffu, sum, off, 8);
            if (s == 0) gs[r] = sum + bs[r];
        }
        __syncthreads();
        if (tid < UPB) {
            float iv = gs[tid], gv = gs[2*UPB + tid], ov = gs[3*UPB + tid];
            float cn = sigf(iv) * tanhf(gv);
            float hn = sigf(ov) * tanhf(cn);
            __stcg(&h_out[u0 + tid], hn);
        }
        __threadfence();
        __syncthreads();
        if (tid == 0) {
            atomicAdd(&g_bar, 1u);
            unsigned target = (unsigned)(258u * NB) + (unsigned)(t + 1) * NB;
            while (*((volatile unsigned*)&g_bar) < target) {}
        }
        __syncthreads();

        for (int e = tid; e < HID; e += 256) hbuf[e] = __ldcg(&h_out[e]);
        __syncthreads();
        {
            int fl = tid >> 7;
            int i  = tid & 127;
            float p = 0.f;
#pragma unroll
            for (int m = 0; m < 6; m++)
                p += linWs[fl*HID + i + 128*m] * hbuf[i + 128*m];
#pragma unroll
            for (int off = 16; off > 0; off >>= 1)
                p += __shfl_down_sync(0xffffffffu, p, off);
            if ((tid & 31) == 0) red[tid >> 5] = p;
        }
        __syncthreads();
        if (tid < 2)
            osv[tid] = red[tid*4] + red[tid*4+1] + red[tid*4+2] + red[tid*4+3] + lbs[tid];
        __syncthreads();
        if (tid < 128) {
            int b = tid & 63, fl = tid >> 6;
            out[(size_t)t*BATCH*FEAT + b*FEAT + f0 + fl] = osv[fl];
        }
        __syncthreads();
    }
}

extern "C" void kernel_launch(void* const* d_in, const int* in_sizes, int n_in,
                              void* d_out, int out_size)
{
    const float* x     = (const float*)d_in[0];
    const float* Wih0  = (const float*)d_in[1];
    const float* Whh0  = (const float*)d_in[2];
    const float* bih0  = (const float*)d_in[3];
    const float* bhh0  = (const float*)d_in[4];
    const float* eWih  = (const float*)d_in[5];
    const float* ebih  = (const float*)d_in[7];
    const float* ebhh  = (const float*)d_in[8];
    const float* dWih  = (const float*)d_in[9];
    const float* dbih  = (const float*)d_in[11];
    const float* dbhh  = (const float*)d_in[12];
    const float* linW  = (const float*)d_in[13];
    const float* linb  = (const float*)d_in[14];
    float* out = (float*)d_out;

    __half *p_xh, *p_whi, *p_wlo;
    cudaGetSymbolAddress((void**)&p_xh,  g_xh);
    cudaGetSymbolAddress((void**)&p_whi, g_whi);
    cudaGetSymbolAddress((void**)&p_wlo, g_wlo);

    const int enc_smem = 2*RPB*WPAD*2 + 65536 + 2*RPB*66*4 + UPB*BATCH*4;
    const int xg_smem  = 98304 + 132*4;

    static int smem_set = 0;
    if (!smem_set) {
        cudaFuncSetAttribute(k_enc,    cudaFuncAttributeMaxDynamicSharedMemorySize, enc_smem);
        cudaFuncSetAttribute(k_xg_mma, cudaFuncAttributeMaxDynamicSharedMemorySize, xg_smem);
        cudaFuncSetAttribute(k_decp,   cudaFuncAttributeMaxDynamicSharedMemorySize, 90000);
        smem_set = 1;
    }

    k_init<<<192, 256>>>();
    k_cvt1<<<(XM*FEAT + 511)/512, 512>>>(x, p_xh, XM*FEAT);
    k_cvt2<<<(GATES*FEAT + 511)/512, 512>>>(Wih0, p_whi, p_wlo, GATES*FEAT);
    k_xg_mma<<<dim3(24, 128), 256, xg_smem>>>(bih0, bhh0);

    k_enc<<<NB, 256, enc_smem>>>(Whh0, eWih, ebih, ebhh, out);

    k_decp<<<NB, 256, 90000>>>(dWih + (size_t)2 * GATES * HID,
                               dbih + 2 * GATES, dbhh + 2 * GATES,
                               linW, linb, out);
}

// round 10
// speedup vs baseline: 5.2869x; 1.0427x over previous
#include <cuda_runtime.h>
#include <cuda_fp16.h>
#include <math.h>
#include <stdint.h>

#define S_LEN 256
#define BATCH 64
#define FEAT  256
#define HID   768
#define GATES 3072
#define TLEN  32
#define OUT_ENC_OFF (TLEN*BATCH*FEAT)
#define XM    (S_LEN*BATCH)

#define NB   128
#define UPB  6
#define RPB  24
#define WPAD 776

// xg stored TRANSPOSED: [t][gate_row][batch]
static __device__ float g_xg[(size_t)S_LEN*GATES*BATCH];
static __device__ __half g_xh[(size_t)XM*FEAT];
static __device__ __half g_whi[(size_t)GATES*FEAT];
static __device__ __half g_wlo[(size_t)GATES*FEAT];
static __device__ __half g_hh[2][BATCH*HID];
static __device__ float g_hd[2][HID];
static __device__ unsigned g_bar;

// fast transcendentals (MUFU-direct); error ~1e-7 rel, safe at extremes
__device__ __forceinline__ float sigf(float x){
    return __fdividef(1.f, 1.f + __expf(-x));
}
__device__ __forceinline__ float tanhfast(float x){
    return 1.f - __fdividef(2.f, __expf(2.f*x) + 1.f);
}

__device__ __forceinline__ void mma_f16(float* c, const uint32_t* a, uint32_t b0, uint32_t b1){
    asm volatile(
        "mma.sync.aligned.m16n8k16.row.col.f32.f16.f16.f32 "
        "{%0,%1,%2,%3}, {%4,%5,%6,%7}, {%8,%9}, {%0,%1,%2,%3};"
        : "+f"(c[0]), "+f"(c[1]), "+f"(c[2]), "+f"(c[3])
        : "r"(a[0]), "r"(a[1]), "r"(a[2]), "r"(a[3]), "r"(b0), "r"(b1));
}
__device__ __forceinline__ void ldsm4(uint32_t* a, uint32_t addr){
    asm volatile("ldmatrix.sync.aligned.m8n8.x4.shared.b16 {%0,%1,%2,%3}, [%4];"
        : "=r"(a[0]), "=r"(a[1]), "=r"(a[2]), "=r"(a[3]) : "r"(addr));
}

__global__ void k_init() {
    int i = blockIdx.x*blockDim.x + threadIdx.x;
    if (i < BATCH*HID/2) ((uint32_t*)g_hh[0])[i] = 0u;
    if (i < HID) g_hd[0][i] = 0.f;
    if (i == 0) g_bar = 0u;
}

__global__ void k_cvt1(const float* __restrict__ src, __half* __restrict__ dhi, int n) {
    int i = blockIdx.x*blockDim.x + threadIdx.x;
    if (i < n) dhi[i] = __float2half(src[i]);
}
__global__ void k_cvt2(const float* __restrict__ src,
                       __half* __restrict__ dhi, __half* __restrict__ dlo, int n) {
    int i = blockIdx.x*blockDim.x + threadIdx.x;
    if (i < n) {
        float v = src[i];
        __half hi = __float2half(v);
        dhi[i] = hi;
        dlo[i] = __float2half(v - __half2float(hi));
    }
}

// ---------------- tensor-core xg GEMM: xgT[t][r][b] = X @ Wih0^T + b -------
__global__ __launch_bounds__(256) void k_xg_mma(
    const float* __restrict__ b1, const float* __restrict__ b2)
{
    extern __shared__ char smraw[];
    uint32_t xs_base = (uint32_t)__cvta_generic_to_shared(smraw);
    uint32_t ws_base = xs_base + 32768;
    float* sbias = (float*)(smraw + 98304);

    const int tid  = threadIdx.x;
    const int wid  = tid >> 5;
    const int lane = tid & 31;
    const int mw   = wid & 3;
    const int nw   = wid >> 2;
    const int bn   = blockIdx.x * 128;
    const int bm   = blockIdx.y * 128;
    const int l4 = lane >> 2;
    const int l2 = lane & 3;
    const int r  = lane & 15;
    const int seg = lane >> 4;

    if (tid < 128) sbias[tid] = b1[bn+tid] + b2[bn+tid];

    float acc[2][8][4];
#pragma unroll
    for (int mt = 0; mt < 2; mt++)
#pragma unroll
        for (int nt = 0; nt < 8; nt++)
#pragma unroll
            for (int j = 0; j < 4; j++) acc[mt][nt][j] = 0.f;

    for (int ph = 0; ph < 2; ph++) {
        __syncthreads();
#pragma unroll
        for (int i = 0; i < 8; i++) {
            int g = tid + i*256;
            int s = g & 15, row = g >> 4;
            uint32_t dst = xs_base + (uint32_t)(row*256 + ((s ^ (row&7))*16));
            const __half* src = g_xh + (size_t)(bm+row)*FEAT + ph*128 + s*8;
            asm volatile("cp.async.cg.shared.global [%0], [%1], 16;" :: "r"(dst), "l"(src));
        }
#pragma unroll
        for (int i = 0; i < 16; i++) {
            int g = tid + i*256;
            int s = g & 15, row = (g >> 4) & 127, pl = g >> 11;
            uint32_t dst = ws_base + (uint32_t)(pl*32768 + row*256 + ((s ^ (row&7))*16));
            const __half* src = (pl ? g_wlo : g_whi) + (size_t)(bn+row)*FEAT + ph*128 + s*8;
            asm volatile("cp.async.cg.shared.global [%0], [%1], 16;" :: "r"(dst), "l"(src));
        }
        asm volatile("cp.async.commit_group;");
        asm volatile("cp.async.wait_group 0;");
        __syncthreads();

#pragma unroll
        for (int ks = 0; ks < 8; ks++) {
            uint32_t ahi[2][4];
#pragma unroll
            for (int mt = 0; mt < 2; mt++) {
                uint32_t rowoff = (uint32_t)((mw*32 + mt*16 + r)*256);
                uint32_t coff = (uint32_t)((ks*32 + seg*16) ^ ((r&7)*16));
                ldsm4(ahi[mt], xs_base + rowoff + coff);
            }
#pragma unroll
            for (int nt = 0; nt < 8; nt++) {
                int wrow = nw*64 + nt*8 + l4;
                uint32_t wb = ws_base + (uint32_t)(wrow*256 + 4*l2);
                uint32_t s0 = (uint32_t)(((ks*2  ) ^ (wrow&7))*16);
                uint32_t s1 = (uint32_t)(((ks*2+1) ^ (wrow&7))*16);
                uint32_t bh0 = *(const uint32_t*)__cvta_shared_to_generic((size_t)(wb + s0));
                uint32_t bh1 = *(const uint32_t*)__cvta_shared_to_generic((size_t)(wb + s1));
                uint32_t bl0 = *(const uint32_t*)__cvta_shared_to_generic((size_t)(wb + 32768 + s0));
                uint32_t bl1 = *(const uint32_t*)__cvta_shared_to_generic((size_t)(wb + 32768 + s1));
#pragma unroll
                for (int mt = 0; mt < 2; mt++) {
                    mma_f16(acc[mt][nt], ahi[mt], bh0, bh1);
                    mma_f16(acc[mt][nt], ahi[mt], bl0, bl1);
                }
            }
        }
    }

#pragma unroll
    for (int mt = 0; mt < 2; mt++) {
#pragma unroll
        for (int nt = 0; nt < 8; nt++) {
            int nloc = nw*64 + nt*8 + 2*l2;
            int n0 = bn + nloc;
            int m0 = bm + mw*32 + mt*16 + l4;
            int t = m0 >> 6, b = m0 & 63;
            size_t base = (size_t)t*GATES*BATCH;
            float bi0 = sbias[nloc], bi1 = sbias[nloc+1];
            g_xg[base + (size_t)n0*BATCH + b]         = acc[mt][nt][0] + bi0;
            g_xg[base + (size_t)(n0+1)*BATCH + b]     = acc[mt][nt][1] + bi1;
            g_xg[base + (size_t)n0*BATCH + b + 8]     = acc[mt][nt][2] + bi0;
            g_xg[base + (size_t)(n0+1)*BATCH + b + 8] = acc[mt][nt][3] + bi1;
        }
    }
}

// ---------------- persistent encoder: 256 LSTM steps + 2 tail layers ------
__device__ __forceinline__ void load_xv(int t, int kh, int bx0,
                                        const int growx[3][2], float xv[3][2][2],
                                        const float* __restrict__ eb1,
                                        const float* __restrict__ eb2)
{
    if (kh != 0 || t >= 258) return;
    if (t < 256) {
        const float* xg = g_xg + (size_t)t * GATES * BATCH;
#pragma unroll
        for (int nt = 0; nt < 3; nt++)
#pragma unroll
            for (int jj = 0; jj < 2; jj++) {
                const float* rowp = xg + (size_t)growx[nt][jj]*BATCH + bx0;
                xv[nt][jj][0] = __ldcg(rowp);
                xv[nt][jj][1] = __ldcg(rowp + 8);
            }
    } else {
        int l = t - 256;
#pragma unroll
        for (int nt = 0; nt < 3; nt++)
#pragma unroll
            for (int jj = 0; jj < 2; jj++) {
                float bb = __ldg(eb1 + l*GATES + growx[nt][jj]) +
                           __ldg(eb2 + l*GATES + growx[nt][jj]);
                xv[nt][jj][0] = bb;
                xv[nt][jj][1] = bb;
            }
    }
}

__global__ __launch_bounds__(256) void k_enc(
    const float* __restrict__ Whh, const float* __restrict__ eWih,
    const float* __restrict__ ebih, const float* __restrict__ ebhh,
    float* __restrict__ out)
{
    extern __shared__ char smraw[];
    __half* Whi = (__half*)smraw;                     // 24*776
    __half* Wlo = Whi + RPB*WPAD;                     // 24*776
    __half* hsm = Wlo + RPB*WPAD;                     // 6 subtiles * 16KB = 98304B
    float* gA  = (float*)((char*)hsm + 98304);        // 24*66
    float* gB  = gA + RPB*66;
    float* c_s = gB + RPB*66;                         // 384

    const int tid  = threadIdx.x;
    const int wid  = tid >> 5;
    const int lane = tid & 31;
    const int mw   = wid & 3;
    const int kh   = wid >> 2;
    const int u0   = blockIdx.x * UPB;

    for (int e = tid; e < RPB*HID; e += 256) {
        int rr = e / HID, k = e % HID;
        int grow = (rr/UPB)*HID + u0 + (rr%UPB);
        float w = Whh[(size_t)grow*HID + k];
        __half hi = __float2half(w);
        Whi[rr*WPAD + k] = hi;
        Wlo[rr*WPAD + k] = __float2half(w - __half2float(hi));
    }
    for (int e = tid; e < UPB*BATCH; e += 256) c_s[e] = 0.f;

    uint32_t hs_base = (uint32_t)__cvta_generic_to_shared(hsm);

    const int l4 = lane >> 2;
    const int l2 = lane & 3;
    int growx[3][2];
#pragma unroll
    for (int nt = 0; nt < 3; nt++)
#pragma unroll
        for (int jj = 0; jj < 2; jj++) {
            int row = nt*8 + 2*l2 + jj;
            growx[nt][jj] = (row/UPB)*HID + u0 + (row%UPB);
        }
    const int bx0 = 16*mw + l4;

    float xv[3][2][2];
    load_xv(0, kh, bx0, growx, xv, ebih, ebhh);

    __syncthreads();

    for (int t = 0; t < 258; t++) {
        if (t >= 256) {
            const float* Wsrc = eWih + (size_t)(t - 256) * GATES * HID;
            for (int e = tid; e < RPB*HID; e += 256) {
                int rr = e / HID, k = e % HID;
                int grow = (rr/UPB)*HID + u0 + (rr%UPB);
                float w = Wsrc[(size_t)grow*HID + k];
                __half hi = __float2half(w);
                Whi[rr*WPAD + k] = hi;
                Wlo[rr*WPAD + k] = __float2half(w - __half2float(hi));
            }
            __syncthreads();
        }

        const __half* hh = g_hh[t & 1];

        // stage full h (96KB, 6 subtiles of 64b x 128k) in one volley
        // granule decode: s=g&15, b=(g>>4)&63, c=g>>10
#pragma unroll
        for (int i = 0; i < 24; i++) {
            int g = tid + i*256;
            int s = g & 15, b = (g >> 4) & 63, c = g >> 10;
            uint32_t dst = hs_base + (uint32_t)(c*16384 + b*256 + ((s ^ (b&7))*16));
            const __half* src = hh + (size_t)b*HID + c*128 + s*8;
            asm volatile("cp.async.cg.shared.global [%0], [%1], 16;" :: "r"(dst), "l"(src));
        }
        asm volatile("cp.async.commit_group;");
        asm volatile("cp.async.wait_group 0;");
        __syncthreads();

        float acc[3][4];
#pragma unroll
        for (int nt = 0; nt < 3; nt++)
#pragma unroll
            for (int j = 0; j < 4; j++) acc[nt][j] = 0.f;

        const int rr = lane & 15, sg = lane >> 4;
        const uint32_t rowoff = (uint32_t)((16*mw + rr)*256);
        const uint32_t swz = (uint32_t)((rr&7)*16);
#pragma unroll
        for (int p = 0; p < 3; p++) {
            const int c = 3*kh + p;
            uint32_t subb = hs_base + (uint32_t)(c*16384);
#pragma unroll
            for (int ks = 0; ks < 8; ks++) {
                uint32_t coff = (uint32_t)(ks*32 + sg*16) ^ swz;
                uint32_t ahi[4];
                ldsm4(ahi, subb + rowoff + coff);
                const int kcol = c*128 + ks*16 + 2*l2;
#pragma unroll
                for (int nt = 0; nt < 3; nt++) {
                    const int widx = (nt*8 + l4)*WPAD + kcol;
                    uint32_t bh0 = *(const uint32_t*)&Whi[widx];
                    uint32_t bh1 = *(const uint32_t*)&Whi[widx + 8];
                    uint32_t bl0 = *(const uint32_t*)&Wlo[widx];
                    uint32_t bl1 = *(const uint32_t*)&Wlo[widx + 8];
                    mma_f16(acc[nt], ahi, bh0, bh1);
                    mma_f16(acc[nt], ahi, bl0, bl1);
                }
            }
        }

        float* dst = kh ? gB : gA;
#pragma unroll
        for (int nt = 0; nt < 3; nt++) {
            int r0 = nt*8 + 2*l2;
            if (kh == 0) {
                dst[(r0  )*66 + bx0    ] = acc[nt][0] + xv[nt][0][0];
                dst[(r0+1)*66 + bx0    ] = acc[nt][1] + xv[nt][1][0];
                dst[(r0  )*66 + bx0 + 8] = acc[nt][2] + xv[nt][0][1];
                dst[(r0+1)*66 + bx0 + 8] = acc[nt][3] + xv[nt][1][1];
            } else {
                dst[(r0  )*66 + bx0    ] = acc[nt][0];
                dst[(r0+1)*66 + bx0    ] = acc[nt][1];
                dst[(r0  )*66 + bx0 + 8] = acc[nt][2];
                dst[(r0+1)*66 + bx0 + 8] = acc[nt][3];
            }
        }
        __syncthreads();

        __half* oh = g_hh[(t+1)&1];
        for (int e = tid; e < UPB*BATCH; e += 256) {
            int u = e % UPB, b = e / UPB;
            float iv = gA[(u)       *66 + b] + gB[(u)       *66 + b];
            float fv = gA[(UPB  +u) *66 + b] + gB[(UPB  +u) *66 + b];
            float gv = gA[(2*UPB+u) *66 + b] + gB[(2*UPB+u) *66 + b];
            float ov = gA[(3*UPB+u) *66 + b] + gB[(3*UPB+u) *66 + b];
            float cn, hn;
            if (t < 256) {
                float cp = c_s[e];
                cn = sigf(fv) * cp + sigf(iv) * tanhfast(gv);
                c_s[e] = cn;
            } else {
                cn = sigf(iv) * tanhfast(gv);
            }
            hn = sigf(ov) * tanhfast(cn);
            int idx = b*HID + u0 + u;
            oh[idx] = __float2half(hn);
            if (t == 255) out[OUT_ENC_OFF + idx] = hn;
            else if (t == 256) out[OUT_ENC_OFF + BATCH*HID + idx] = hn;
            else if (t == 257) out[OUT_ENC_OFF + 2*BATCH*HID + idx] = hn;
        }

        __threadfence();
        __syncthreads();
        if (tid == 0) atomicAdd(&g_bar, 1u);
        load_xv(t + 1, kh, bx0, growx, xv, ebih, ebhh);
        if (tid == 0) {
            unsigned target = (unsigned)(t + 1) * NB;
            while (*((volatile unsigned*)&g_bar) < target) {}
        }
        __syncthreads();
    }
}

// ---------------- persistent decoder (fp32) ----------------
__global__ __launch_bounds__(256) void k_decp(
    const float* __restrict__ W2, const float* __restrict__ db1,
    const float* __restrict__ db2, const float* __restrict__ linW,
    const float* __restrict__ linb, float* __restrict__ out)
{
    extern __shared__ float sm[];
    float* W2s   = sm;
    float* linWs = W2s + RPB*HID;
    float* hbuf  = linWs + 2*HID;
    float* gs    = hbuf + HID;
    float* bs    = gs + 32;
    float* red   = bs + 32;
    float* osv   = red + 8;
    float* lbs   = osv + 2;

    const int tid = threadIdx.x;
    const int u0 = blockIdx.x * UPB;
    const int f0 = blockIdx.x * 2;

    for (int e = tid; e < RPB*(HID/4); e += 256) {
        int r = e / (HID/4), c4 = e % (HID/4);
        int grow = (r/UPB)*HID + u0 + (r%UPB);
        ((float4*)W2s)[e] = ((const float4*)(W2 + (size_t)grow*HID))[c4];
    }
    for (int e = tid; e < 2*(HID/4); e += 256)
        ((float4*)linWs)[e] = ((const float4*)(linW + (size_t)f0*HID))[e];
    if (tid < RPB) {
        int grow = (tid/UPB)*HID + u0 + (tid%UPB);
        bs[tid] = db1[grow] + db2[grow];
    }
    if (tid < 2) lbs[tid] = linb[f0 + tid];
    __syncthreads();

    for (int t = 0; t < TLEN; t++) {
        const float* h_in  = g_hd[t & 1];
        float*       h_out = g_hd[(t + 1) & 1];

        for (int e = tid; e < HID; e += 256) hbuf[e] = __ldcg(&h_in[e]);
        __syncthreads();

        if (tid < 192) {
            int r = tid >> 3, s = tid & 7;
            const float4* W4 = (const float4*)(W2s + r*HID + s*96);
            const float4* h4 = (const float4*)(hbuf + s*96);
            float sum = 0.f;
#pragma unroll
            for (int m = 0; m < 24; m++) {
                float4 wv = W4[m]; float4 hv = h4[m];
                sum += wv.x*hv.x + wv.y*hv.y + wv.z*hv.z + wv.w*hv.w;
            }
#pragma unroll
            for (int off = 4; off > 0; off >>= 1)
                sum += __shfl_down_sync(0xffffffffu, sum, off, 8);
            if (s == 0) gs[r] = sum + bs[r];
        }
        __syncthreads();
        if (tid < UPB) {
            float iv = gs[tid], gv = gs[2*UPB + tid], ov = gs[3*UPB + tid];
            float cn = sigf(iv) * tanhfast(gv);
            float hn = sigf(ov) * tanhfast(cn);
            __stcg(&h_out[u0 + tid], hn);
        }
        __threadfence();
        __syncthreads();
        if (tid == 0) {
            atomicAdd(&g_bar, 1u);
            unsigned target = (unsigned)(258u * NB) + (unsigned)(t + 1) * NB;
            while (*((volatile unsigned*)&g_bar) < target) {}
        }
        __syncthreads();

        for (int e = tid; e < HID; e += 256) hbuf[e] = __ldcg(&h_out[e]);
        __syncthreads();
        {
            int fl = tid >> 7;
            int i  = tid & 127;
            float p = 0.f;
#pragma unroll
            for (int m = 0; m < 6; m++)
                p += linWs[fl*HID + i + 128*m] * hbuf[i + 128*m];
#pragma unroll
            for (int off = 16; off > 0; off >>= 1)
                p += __shfl_down_sync(0xffffffffu, p, off);
            if ((tid & 31) == 0) red[tid >> 5] = p;
        }
        __syncthreads();
        if (tid < 2)
            osv[tid] = red[tid*4] + red[tid*4+1] + red[tid*4+2] + red[tid*4+3] + lbs[tid];
        __syncthreads();
        if (tid < 128) {
            int b = tid & 63, fl = tid >> 6;
            out[(size_t)t*BATCH*FEAT + b*FEAT + f0 + fl] = osv[fl];
        }
        __syncthreads();
    }
}

extern "C" void kernel_launch(void* const* d_in, const int* in_sizes, int n_in,
                              void* d_out, int out_size)
{
    const float* x     = (const float*)d_in[0];
    const float* Wih0  = (const float*)d_in[1];
    const float* Whh0  = (const float*)d_in[2];
    const float* bih0  = (const float*)d_in[3];
    const float* bhh0  = (const float*)d_in[4];
    const float* eWih  = (const float*)d_in[5];
    const float* ebih  = (const float*)d_in[7];
    const float* ebhh  = (const float*)d_in[8];
    const float* dWih  = (const float*)d_in[9];
    const float* dbih  = (const float*)d_in[11];
    const float* dbhh  = (const float*)d_in[12];
    const float* linW  = (const float*)d_in[13];
    const float* linb  = (const float*)d_in[14];
    float* out = (float*)d_out;

    __half *p_xh, *p_whi, *p_wlo;
    cudaGetSymbolAddress((void**)&p_xh,  g_xh);
    cudaGetSymbolAddress((void**)&p_whi, g_whi);
    cudaGetSymbolAddress((void**)&p_wlo, g_wlo);

    const int enc_smem = 2*RPB*WPAD*2 + 98304 + 2*RPB*66*4 + UPB*BATCH*4;
    const int xg_smem  = 98304 + 132*4;

    static int smem_set = 0;
    if (!smem_set) {
        cudaFuncSetAttribute(k_enc,    cudaFuncAttributeMaxDynamicSharedMemorySize, enc_smem);
        cudaFuncSetAttribute(k_xg_mma, cudaFuncAttributeMaxDynamicSharedMemorySize, xg_smem);
        cudaFuncSetAttribute(k_decp,   cudaFuncAttributeMaxDynamicSharedMemorySize, 90000);
        smem_set = 1;
    }

    k_init<<<192, 256>>>();
    k_cvt1<<<(XM*FEAT + 511)/512, 512>>>(x, p_xh, XM*FEAT);
    k_cvt2<<<(GATES*FEAT + 511)/512, 512>>>(Wih0, p_whi, p_wlo, GATES*FEAT);
    k_xg_mma<<<dim3(24, 128), 256, xg_smem>>>(bih0, bhh0);

    k_enc<<<NB, 256, enc_smem>>>(Whh0, eWih, ebih, ebhh, out);

    k_decp<<<NB, 256, 90000>>>(dWih + (size_t)2 * GATES * HID,
                               dbih + 2 * GATES, dbhh + 2 * GATES,
                               linW, linb, out);
}

// round 11
// speedup vs baseline: 5.5364x; 1.0472x over previous
#include <cuda_runtime.h>
#include <cuda_fp16.h>
#include <math.h>
#include <stdint.h>

#define S_LEN 256
#define BATCH 64
#define FEAT  256
#define HID   768
#define GATES 3072
#define TLEN  32
#define OUT_ENC_OFF (TLEN*BATCH*FEAT)
#define XM    (S_LEN*BATCH)

#define NB   128
#define UPB  6
#define RPB  24
#define WPAD 776

// xg stored TRANSPOSED: [t][gate_row][batch]
static __device__ float g_xg[(size_t)S_LEN*GATES*BATCH];
static __device__ __half g_xh[(size_t)XM*FEAT];
static __device__ __half g_whi[(size_t)GATES*FEAT];
static __device__ __half g_wlo[(size_t)GATES*FEAT];
static __device__ __half g_hh[2][BATCH*HID];
static __device__ float g_hd[2][HID];
static __device__ unsigned g_bar;

__device__ __forceinline__ float sigf(float x){
    return __fdividef(1.f, 1.f + __expf(-x));
}
__device__ __forceinline__ float tanhfast(float x){
    return 1.f - __fdividef(2.f, __expf(2.f*x) + 1.f);
}

__device__ __forceinline__ void mma_f16(float* c, const uint32_t* a, uint32_t b0, uint32_t b1){
    asm volatile(
        "mma.sync.aligned.m16n8k16.row.col.f32.f16.f16.f32 "
        "{%0,%1,%2,%3}, {%4,%5,%6,%7}, {%8,%9}, {%0,%1,%2,%3};"
        : "+f"(c[0]), "+f"(c[1]), "+f"(c[2]), "+f"(c[3])
        : "r"(a[0]), "r"(a[1]), "r"(a[2]), "r"(a[3]), "r"(b0), "r"(b1));
}
__device__ __forceinline__ void ldsm4(uint32_t* a, uint32_t addr){
    asm volatile("ldmatrix.sync.aligned.m8n8.x4.shared.b16 {%0,%1,%2,%3}, [%4];"
        : "=r"(a[0]), "=r"(a[1]), "=r"(a[2]), "=r"(a[3]) : "r"(addr));
}
__device__ __forceinline__ void bar_arrive(unsigned* p){
    asm volatile("red.release.gpu.global.add.u32 [%0], %1;" :: "l"(p), "r"(1u) : "memory");
}
__device__ __forceinline__ unsigned bar_poll(unsigned* p){
    unsigned v;
    asm volatile("ld.acquire.gpu.global.u32 %0, [%1];" : "=r"(v) : "l"(p) : "memory");
    return v;
}

__global__ void k_init() {
    int i = blockIdx.x*blockDim.x + threadIdx.x;
    if (i < BATCH*HID/2) ((uint32_t*)g_hh[0])[i] = 0u;
    if (i < HID) g_hd[0][i] = 0.f;
    if (i == 0) g_bar = 0u;
}

__global__ void k_cvt1(const float* __restrict__ src, __half* __restrict__ dhi, int n) {
    int i = blockIdx.x*blockDim.x + threadIdx.x;
    if (i < n) dhi[i] = __float2half(src[i]);
}
__global__ void k_cvt2(const float* __restrict__ src,
                       __half* __restrict__ dhi, __half* __restrict__ dlo, int n) {
    int i = blockIdx.x*blockDim.x + threadIdx.x;
    if (i < n) {
        float v = src[i];
        __half hi = __float2half(v);
        dhi[i] = hi;
        dlo[i] = __float2half(v - __half2float(hi));
    }
}

// ---------------- tensor-core xg GEMM (double-buffered, ldsm-B) -----------
__global__ __launch_bounds__(256) void k_xg_mma(
    const float* __restrict__ b1, const float* __restrict__ b2)
{
    extern __shared__ char smraw[];
    uint32_t xs_base = (uint32_t)__cvta_generic_to_shared(smraw);      // 2*32KB
    uint32_t ws_base = xs_base + 65536;                                // 2*64KB
    float* sbias = (float*)(smraw + 196608);

    const int tid  = threadIdx.x;
    const int wid  = tid >> 5;
    const int lane = tid & 31;
    const int mw   = wid & 3;
    const int nw   = wid >> 2;
    const int bn   = blockIdx.x * 128;
    const int bm   = blockIdx.y * 128;
    const int l4 = lane >> 2;
    const int l2 = lane & 3;
    const int r  = lane & 15;
    const int seg = lane >> 4;
    const int bmid = lane >> 3;      // B-matrix id 0..3
    const int brow = lane & 7;

    if (tid < 128) sbias[tid] = b1[bn+tid] + b2[bn+tid];

    float acc[2][8][4];
#pragma unroll
    for (int mt = 0; mt < 2; mt++)
#pragma unroll
        for (int nt = 0; nt < 8; nt++)
#pragma unroll
            for (int j = 0; j < 4; j++) acc[mt][nt][j] = 0.f;

    // stage BOTH phases up front
#pragma unroll
    for (int ph = 0; ph < 2; ph++) {
#pragma unroll
        for (int i = 0; i < 8; i++) {
            int g = tid + i*256;
            int s = g & 15, row = g >> 4;
            uint32_t dst = xs_base + (uint32_t)(ph*32768 + row*256 + ((s ^ (row&7))*16));
            const __half* src = g_xh + (size_t)(bm+row)*FEAT + ph*128 + s*8;
            asm volatile("cp.async.cg.shared.global [%0], [%1], 16;" :: "r"(dst), "l"(src));
        }
#pragma unroll
        for (int i = 0; i < 16; i++) {
            int g = tid + i*256;
            int s = g & 15, row = (g >> 4) & 127, pl = g >> 11;
            uint32_t dst = ws_base + (uint32_t)(ph*65536 + pl*32768 + row*256 + ((s ^ (row&7))*16));
            const __half* src = (pl ? g_wlo : g_whi) + (size_t)(bn+row)*FEAT + ph*128 + s*8;
            asm volatile("cp.async.cg.shared.global [%0], [%1], 16;" :: "r"(dst), "l"(src));
        }
        asm volatile("cp.async.commit_group;");
    }

#pragma unroll
    for (int ph = 0; ph < 2; ph++) {
        if (ph == 0) asm volatile("cp.async.wait_group 1;");
        else         asm volatile("cp.async.wait_group 0;");
        __syncthreads();
        uint32_t xs_ph = xs_base + (uint32_t)(ph*32768);
        uint32_t ws_ph = ws_base + (uint32_t)(ph*65536);

#pragma unroll
        for (int ks = 0; ks < 8; ks++) {
            uint32_t ahi[2][4];
#pragma unroll
            for (int mt = 0; mt < 2; mt++) {
                uint32_t rowoff = (uint32_t)((mw*32 + mt*16 + r)*256);
                uint32_t coff = (uint32_t)((ks*32 + seg*16) ^ ((r&7)*16));
                ldsm4(ahi[mt], xs_ph + rowoff + coff);
            }
#pragma unroll
            for (int nt = 0; nt < 8; nt++) {
                // ldsm B: matrices {Whi k0, Whi k8, Wlo k0, Wlo k8}
                int wrow = nw*64 + nt*8 + brow;
                uint32_t baddr = ws_ph + (uint32_t)((bmid>>1)*32768 + wrow*256
                                 + (((ks*2 + (bmid&1)) ^ brow)*16));
                uint32_t bf[4];
                ldsm4(bf, baddr);
#pragma unroll
                for (int mt = 0; mt < 2; mt++) {
                    mma_f16(acc[mt][nt], ahi[mt], bf[0], bf[1]);
                    mma_f16(acc[mt][nt], ahi[mt], bf[2], bf[3]);
                }
            }
        }
    }

#pragma unroll
    for (int mt = 0; mt < 2; mt++) {
#pragma unroll
        for (int nt = 0; nt < 8; nt++) {
            int nloc = nw*64 + nt*8 + 2*l2;
            int n0 = bn + nloc;
            int m0 = bm + mw*32 + mt*16 + l4;
            int t = m0 >> 6, b = m0 & 63;
            size_t base = (size_t)t*GATES*BATCH;
            float bi0 = sbias[nloc], bi1 = sbias[nloc+1];
            g_xg[base + (size_t)n0*BATCH + b]         = acc[mt][nt][0] + bi0;
            g_xg[base + (size_t)(n0+1)*BATCH + b]     = acc[mt][nt][1] + bi1;
            g_xg[base + (size_t)n0*BATCH + b + 8]     = acc[mt][nt][2] + bi0;
            g_xg[base + (size_t)(n0+1)*BATCH + b + 8] = acc[mt][nt][3] + bi1;
        }
    }
}

// ---------------- persistent encoder: 256 LSTM steps + 2 tail layers ------
__device__ __forceinline__ void load_xv(int t, int kh, int bx0,
                                        const int growx[3][2], float xv[3][2][2],
                                        const float* __restrict__ eb1,
                                        const float* __restrict__ eb2)
{
    if (kh != 0 || t >= 258) return;
    if (t < 256) {
        const float* xg = g_xg + (size_t)t * GATES * BATCH;
#pragma unroll
        for (int nt = 0; nt < 3; nt++)
#pragma unroll
            for (int jj = 0; jj < 2; jj++) {
                const float* rowp = xg + (size_t)growx[nt][jj]*BATCH + bx0;
                xv[nt][jj][0] = __ldcg(rowp);
                xv[nt][jj][1] = __ldcg(rowp + 8);
            }
    } else {
        int l = t - 256;
#pragma unroll
        for (int nt = 0; nt < 3; nt++)
#pragma unroll
            for (int jj = 0; jj < 2; jj++) {
                float bb = __ldg(eb1 + l*GATES + growx[nt][jj]) +
                           __ldg(eb2 + l*GATES + growx[nt][jj]);
                xv[nt][jj][0] = bb;
                xv[nt][jj][1] = bb;
            }
    }
}

__global__ __launch_bounds__(256) void k_enc(
    const float* __restrict__ Whh, const float* __restrict__ eWih,
    const float* __restrict__ ebih, const float* __restrict__ ebhh,
    float* __restrict__ out)
{
    extern __shared__ char smraw[];
    __half* Whi = (__half*)smraw;                     // 24*776
    __half* Wlo = Whi + RPB*WPAD;                     // 24*776
    __half* hsm = Wlo + RPB*WPAD;                     // 6 subtiles * 16KB
    float* gA  = (float*)((char*)hsm + 98304);
    float* gB  = gA + RPB*66;
    float* c_s = gB + RPB*66;

    const int tid  = threadIdx.x;
    const int wid  = tid >> 5;
    const int lane = tid & 31;
    const int mw   = wid & 3;
    const int kh   = wid >> 2;
    const int u0   = blockIdx.x * UPB;

    for (int e = tid; e < RPB*HID; e += 256) {
        int rr = e / HID, k = e % HID;
        int grow = (rr/UPB)*HID + u0 + (rr%UPB);
        float w = Whh[(size_t)grow*HID + k];
        __half hi = __float2half(w);
        Whi[rr*WPAD + k] = hi;
        Wlo[rr*WPAD + k] = __float2half(w - __half2float(hi));
    }
    for (int e = tid; e < UPB*BATCH; e += 256) c_s[e] = 0.f;

    uint32_t hs_base = (uint32_t)__cvta_generic_to_shared(hsm);

    const int l4 = lane >> 2;
    const int l2 = lane & 3;
    const int bmid = lane >> 3;
    const int brow = lane & 7;
    // per-lane ldsm-B base: plane (Whi/Wlo) + row brow, +16B for odd matrix
    uint32_t wsmB = (uint32_t)__cvta_generic_to_shared(
                        ((bmid < 2) ? Whi : Wlo) + (size_t)brow*WPAD)
                    + (uint32_t)((bmid & 1) * 16);

    int growx[3][2];
#pragma unroll
    for (int nt = 0; nt < 3; nt++)
#pragma unroll
        for (int jj = 0; jj < 2; jj++) {
            int row = nt*8 + 2*l2 + jj;
            growx[nt][jj] = (row/UPB)*HID + u0 + (row%UPB);
        }
    const int bx0 = 16*mw + l4;

    float xv[3][2][2];
    load_xv(0, kh, bx0, growx, xv, ebih, ebhh);

    __syncthreads();

    for (int t = 0; t < 258; t++) {
        if (t >= 256) {
            const float* Wsrc = eWih + (size_t)(t - 256) * GATES * HID;
            for (int e = tid; e < RPB*HID; e += 256) {
                int rr = e / HID, k = e % HID;
                int grow = (rr/UPB)*HID + u0 + (rr%UPB);
                float w = Wsrc[(size_t)grow*HID + k];
                __half hi = __float2half(w);
                Whi[rr*WPAD + k] = hi;
                Wlo[rr*WPAD + k] = __float2half(w - __half2float(hi));
            }
            __syncthreads();
        }

        const __half* hh = g_hh[t & 1];

        // stage full h (96KB) in one volley
#pragma unroll
        for (int i = 0; i < 24; i++) {
            int g = tid + i*256;
            int s = g & 15, b = (g >> 4) & 63, c = g >> 10;
            uint32_t dst = hs_base + (uint32_t)(c*16384 + b*256 + ((s ^ (b&7))*16));
            const __half* src = hh + (size_t)b*HID + c*128 + s*8;
            asm volatile("cp.async.cg.shared.global [%0], [%1], 16;" :: "r"(dst), "l"(src));
        }
        asm volatile("cp.async.commit_group;");
        asm volatile("cp.async.wait_group 0;");
        __syncthreads();

        float acc[3][4];
#pragma unroll
        for (int nt = 0; nt < 3; nt++)
#pragma unroll
            for (int j = 0; j < 4; j++) acc[nt][j] = 0.f;

        const int rr = lane & 15, sg = lane >> 4;
        const uint32_t rowoff = (uint32_t)((16*mw + rr)*256);
        const uint32_t swz = (uint32_t)((rr&7)*16);
#pragma unroll
        for (int p = 0; p < 3; p++) {
            const int c = 3*kh + p;
            uint32_t subb = hs_base + (uint32_t)(c*16384);
            uint32_t kbyte0 = (uint32_t)(c*256);        // c*128 halfs
#pragma unroll
            for (int ks = 0; ks < 8; ks++) {
                uint32_t coff = (uint32_t)(ks*32 + sg*16) ^ swz;
                uint32_t ahi[4];
                ldsm4(ahi, subb + rowoff + coff);
                uint32_t kb = kbyte0 + (uint32_t)(ks*32);
#pragma unroll
                for (int nt = 0; nt < 3; nt++) {
                    uint32_t bf[4];
                    ldsm4(bf, wsmB + (uint32_t)(nt*8*WPAD*2) + kb);
                    mma_f16(acc[nt], ahi, bf[0], bf[1]);
                    mma_f16(acc[nt], ahi, bf[2], bf[3]);
                }
            }
        }

        float* dst = kh ? gB : gA;
#pragma unroll
        for (int nt = 0; nt < 3; nt++) {
            int r0 = nt*8 + 2*l2;
            if (kh == 0) {
                dst[(r0  )*66 + bx0    ] = acc[nt][0] + xv[nt][0][0];
                dst[(r0+1)*66 + bx0    ] = acc[nt][1] + xv[nt][1][0];
                dst[(r0  )*66 + bx0 + 8] = acc[nt][2] + xv[nt][0][1];
                dst[(r0+1)*66 + bx0 + 8] = acc[nt][3] + xv[nt][1][1];
            } else {
                dst[(r0  )*66 + bx0    ] = acc[nt][0];
                dst[(r0+1)*66 + bx0    ] = acc[nt][1];
                dst[(r0  )*66 + bx0 + 8] = acc[nt][2];
                dst[(r0+1)*66 + bx0 + 8] = acc[nt][3];
            }
        }
        __syncthreads();

        __half* oh = g_hh[(t+1)&1];
        for (int e = tid; e < UPB*BATCH; e += 256) {
            int u = e % UPB, b = e / UPB;
            float iv = gA[(u)       *66 + b] + gB[(u)       *66 + b];
            float fv = gA[(UPB  +u) *66 + b] + gB[(UPB  +u) *66 + b];
            float gv = gA[(2*UPB+u) *66 + b] + gB[(2*UPB+u) *66 + b];
            float ov = gA[(3*UPB+u) *66 + b] + gB[(3*UPB+u) *66 + b];
            float cn, hn;
            if (t < 256) {
                float cp = c_s[e];
                cn = sigf(fv) * cp + sigf(iv) * tanhfast(gv);
                c_s[e] = cn;
            } else {
                cn = sigf(iv) * tanhfast(gv);
            }
            hn = sigf(ov) * tanhfast(cn);
            int idx = b*HID + u0 + u;
            oh[idx] = __float2half(hn);
            if (t == 255) out[OUT_ENC_OFF + idx] = hn;
            else if (t == 256) out[OUT_ENC_OFF + BATCH*HID + idx] = hn;
            else if (t == 257) out[OUT_ENC_OFF + 2*BATCH*HID + idx] = hn;
        }

        __syncthreads();
        if (tid == 0) bar_arrive(&g_bar);
        load_xv(t + 1, kh, bx0, growx, xv, ebih, ebhh);
        if (tid == 0) {
            unsigned target = (unsigned)(t + 1) * NB;
            while (bar_poll(&g_bar) < target) {}
        }
        __syncthreads();
    }
}

// ---------------- persistent decoder (fp32) ----------------
__global__ __launch_bounds__(256) void k_decp(
    const float* __restrict__ W2, const float* __restrict__ db1,
    const float* __restrict__ db2, const float* __restrict__ linW,
    const float* __restrict__ linb, float* __restrict__ out)
{
    extern __shared__ float sm[];
    float* W2s   = sm;
    float* linWs = W2s + RPB*HID;
    float* hbuf  = linWs + 2*HID;
    float* gs    = hbuf + HID;
    float* bs    = gs + 32;
    float* red   = bs + 32;
    float* osv   = red + 8;
    float* lbs   = osv + 2;

    const int tid = threadIdx.x;
    const int u0 = blockIdx.x * UPB;
    const int f0 = blockIdx.x * 2;

    for (int e = tid; e < RPB*(HID/4); e += 256) {
        int r = e / (HID/4), c4 = e % (HID/4);
        int grow = (r/UPB)*HID + u0 + (r%UPB);
        ((float4*)W2s)[e] = ((const float4*)(W2 + (size_t)grow*HID))[c4];
    }
    for (int e = tid; e < 2*(HID/4); e += 256)
        ((float4*)linWs)[e] = ((const float4*)(linW + (size_t)f0*HID))[e];
    if (tid < RPB) {
        int grow = (tid/UPB)*HID + u0 + (tid%UPB);
        bs[tid] = db1[grow] + db2[grow];
    }
    if (tid < 2) lbs[tid] = linb[f0 + tid];
    __syncthreads();

    for (int t = 0; t < TLEN; t++) {
        const float* h_in  = g_hd[t & 1];
        float*       h_out = g_hd[(t + 1) & 1];

        for (int e = tid; e < HID; e += 256) hbuf[e] = __ldcg(&h_in[e]);
        __syncthreads();

        if (tid < 192) {
            int r = tid >> 3, s = tid & 7;
            const float4* W4 = (const float4*)(W2s + r*HID + s*96);
            const float4* h4 = (const float4*)(hbuf + s*96);
            float sum = 0.f;
#pragma unroll
            for (int m = 0; m < 24; m++) {
                float4 wv = W4[m]; float4 hv = h4[m];
                sum += wv.x*hv.x + wv.y*hv.y + wv.z*hv.z + wv.w*hv.w;
            }
#pragma unroll
            for (int off = 4; off > 0; off >>= 1)
                sum += __shfl_down_sync(0xffffffffu, sum, off, 8);
            if (s == 0) gs[r] = sum + bs[r];
        }
        __syncthreads();
        if (tid < UPB) {
            float iv = gs[tid], gv = gs[2*UPB + tid], ov = gs[3*UPB + tid];
            float cn = sigf(iv) * tanhfast(gv);
            float hn = sigf(ov) * tanhfast(cn);
            __stcg(&h_out[u0 + tid], hn);
        }
        __syncthreads();
        if (tid == 0) {
            bar_arrive(&g_bar);
            unsigned target = (unsigned)(258u * NB) + (unsigned)(t + 1) * NB;
            while (bar_poll(&g_bar) < target) {}
        }
        __syncthreads();

        for (int e = tid; e < HID; e += 256) hbuf[e] = __ldcg(&h_out[e]);
        __syncthreads();
        {
            int fl = tid >> 7;
            int i  = tid & 127;
            float p = 0.f;
#pragma unroll
            for (int m = 0; m < 6; m++)
                p += linWs[fl*HID + i + 128*m] * hbuf[i + 128*m];
#pragma unroll
            for (int off = 16; off > 0; off >>= 1)
                p += __shfl_down_sync(0xffffffffu, p, off);
            if ((tid & 31) == 0) red[tid >> 5] = p;
        }
        __syncthreads();
        if (tid < 2)
            osv[tid] = red[tid*4] + red[tid*4+1] + red[tid*4+2] + red[tid*4+3] + lbs[tid];
        __syncthreads();
        if (tid < 128) {
            int b = tid & 63, fl = tid >> 6;
            out[(size_t)t*BATCH*FEAT + b*FEAT + f0 + fl] = osv[fl];
        }
        __syncthreads();
    }
}

extern "C" void kernel_launch(void* const* d_in, const int* in_sizes, int n_in,
                              void* d_out, int out_size)
{
    const float* x     = (const float*)d_in[0];
    const float* Wih0  = (const float*)d_in[1];
    const float* Whh0  = (const float*)d_in[2];
    const float* bih0  = (const float*)d_in[3];
    const float* bhh0  = (const float*)d_in[4];
    const float* eWih  = (const float*)d_in[5];
    const float* ebih  = (const float*)d_in[7];
    const float* ebhh  = (const float*)d_in[8];
    const float* dWih  = (const float*)d_in[9];
    const float* dbih  = (const float*)d_in[11];
    const float* dbhh  = (const float*)d_in[12];
    const float* linW  = (const float*)d_in[13];
    const float* linb  = (const float*)d_in[14];
    float* out = (float*)d_out;

    __half *p_xh, *p_whi, *p_wlo;
    cudaGetSymbolAddress((void**)&p_xh,  g_xh);
    cudaGetSymbolAddress((void**)&p_whi, g_whi);
    cudaGetSymbolAddress((void**)&p_wlo, g_wlo);

    const int enc_smem = 2*RPB*WPAD*2 + 98304 + 2*RPB*66*4 + UPB*BATCH*4;
    const int xg_smem  = 196608 + 132*4;

    static int smem_set = 0;
    if (!smem_set) {
        cudaFuncSetAttribute(k_enc,    cudaFuncAttributeMaxDynamicSharedMemorySize, enc_smem);
        cudaFuncSetAttribute(k_xg_mma, cudaFuncAttributeMaxDynamicSharedMemorySize, xg_smem);
        cudaFuncSetAttribute(k_decp,   cudaFuncAttributeMaxDynamicSharedMemorySize, 90000);
        smem_set = 1;
    }

    k_init<<<192, 256>>>();
    k_cvt1<<<(XM*FEAT + 511)/512, 512>>>(x, p_xh, XM*FEAT);
    k_cvt2<<<(GATES*FEAT + 511)/512, 512>>>(Wih0, p_whi, p_wlo, GATES*FEAT);
    k_xg_mma<<<dim3(24, 128), 256, xg_smem>>>(bih0, bhh0);

    k_enc<<<NB, 256, enc_smem>>>(Whh0, eWih, ebih, ebhh, out);

    k_decp<<<NB, 256, 90000>>>(dWih + (size_t)2 * GATES * HID,
                               dbih + 2 * GATES, dbhh + 2 * GATES,
                               linW, linb, out);
}

// round 12
// speedup vs baseline: 5.8496x; 1.0566x over previous
#include <cuda_runtime.h>
#include <cuda_fp16.h>
#include <math.h>
#include <stdint.h>

#define S_LEN 256
#define BATCH 64
#define FEAT  256
#define HID   768
#define GATES 3072
#define TLEN  32
#define OUT_ENC_OFF (TLEN*BATCH*FEAT)
#define XM    (S_LEN*BATCH)

#define NB   128      // encoder blocks
#define DNB  16       // decoder blocks (fused: blockIdx 128..143)
#define DUPB 48       // decoder units per block
#define SROWS 72      // decoder gate rows resident in smem (of 144)
#define UPB  6
#define RPB  24
#define WPAD 776

// xg stored TRANSPOSED: [t][gate_row][batch]
static __device__ float g_xg[(size_t)S_LEN*GATES*BATCH];
static __device__ __half g_xh[(size_t)XM*FEAT];
static __device__ __half g_whi[(size_t)GATES*FEAT];
static __device__ __half g_wlo[(size_t)GATES*FEAT];
static __device__ __half g_hh[2][BATCH*HID];
static __device__ float g_hd[2][HID];
static __device__ unsigned g_bar;
static __device__ unsigned g_bar2;

__device__ __forceinline__ float sigf(float x){
    return __fdividef(1.f, 1.f + __expf(-x));
}
__device__ __forceinline__ float tanhfast(float x){
    return 1.f - __fdividef(2.f, __expf(2.f*x) + 1.f);
}

__device__ __forceinline__ void mma_f16(float* c, const uint32_t* a, uint32_t b0, uint32_t b1){
    asm volatile(
        "mma.sync.aligned.m16n8k16.row.col.f32.f16.f16.f32 "
        "{%0,%1,%2,%3}, {%4,%5,%6,%7}, {%8,%9}, {%0,%1,%2,%3};"
        : "+f"(c[0]), "+f"(c[1]), "+f"(c[2]), "+f"(c[3])
        : "r"(a[0]), "r"(a[1]), "r"(a[2]), "r"(a[3]), "r"(b0), "r"(b1));
}
__device__ __forceinline__ void ldsm4(uint32_t* a, uint32_t addr){
    asm volatile("ldmatrix.sync.aligned.m8n8.x4.shared.b16 {%0,%1,%2,%3}, [%4];"
        : "=r"(a[0]), "=r"(a[1]), "=r"(a[2]), "=r"(a[3]) : "r"(addr));
}
__device__ __forceinline__ void bar_arrive(unsigned* p){
    asm volatile("red.release.gpu.global.add.u32 [%0], %1;" :: "l"(p), "r"(1u) : "memory");
}
__device__ __forceinline__ unsigned bar_poll(unsigned* p){
    unsigned v;
    asm volatile("ld.acquire.gpu.global.u32 %0, [%1];" : "=r"(v) : "l"(p) : "memory");
    return v;
}

__global__ void k_init() {
    int i = blockIdx.x*blockDim.x + threadIdx.x;
    if (i < BATCH*HID/2) ((uint32_t*)g_hh[0])[i] = 0u;
    if (i < HID) g_hd[0][i] = 0.f;
    if (i == 0) { g_bar = 0u; g_bar2 = 0u; }
}

__global__ void k_cvt1(const float* __restrict__ src, __half* __restrict__ dhi, int n) {
    int i = blockIdx.x*blockDim.x + threadIdx.x;
    if (i < n) dhi[i] = __float2half(src[i]);
}
__global__ void k_cvt2(const float* __restrict__ src,
                       __half* __restrict__ dhi, __half* __restrict__ dlo, int n) {
    int i = blockIdx.x*blockDim.x + threadIdx.x;
    if (i < n) {
        float v = src[i];
        __half hi = __float2half(v);
        dhi[i] = hi;
        dlo[i] = __float2half(v - __half2float(hi));
    }
}

// ---------------- tensor-core xg GEMM (single-buffer, ldsm-B) -------------
__global__ __launch_bounds__(256, 2) void k_xg_mma(
    const float* __restrict__ b1, const float* __restrict__ b2)
{
    extern __shared__ char smraw[];
    uint32_t xs_base = (uint32_t)__cvta_generic_to_shared(smraw);     // 32KB
    uint32_t ws_base = xs_base + 32768;                               // 64KB
    float* sbias = (float*)(smraw + 98304);

    const int tid  = threadIdx.x;
    const int wid  = tid >> 5;
    const int lane = tid & 31;
    const int mw   = wid & 3;
    const int nw   = wid >> 2;
    const int bn   = blockIdx.x * 128;
    const int bm   = blockIdx.y * 128;
    const int l4 = lane >> 2;
    const int l2 = lane & 3;
    const int r  = lane & 15;
    const int seg = lane >> 4;
    const int bmid = lane >> 3;
    const int brow = lane & 7;

    if (tid < 128) sbias[tid] = b1[bn+tid] + b2[bn+tid];

    float acc[2][8][4];
#pragma unroll
    for (int mt = 0; mt < 2; mt++)
#pragma unroll
        for (int nt = 0; nt < 8; nt++)
#pragma unroll
            for (int j = 0; j < 4; j++) acc[mt][nt][j] = 0.f;

    for (int ph = 0; ph < 2; ph++) {
        __syncthreads();
#pragma unroll
        for (int i = 0; i < 8; i++) {
            int g = tid + i*256;
            int s = g & 15, row = g >> 4;
            uint32_t dst = xs_base + (uint32_t)(row*256 + ((s ^ (row&7))*16));
            const __half* src = g_xh + (size_t)(bm+row)*FEAT + ph*128 + s*8;
            asm volatile("cp.async.cg.shared.global [%0], [%1], 16;" :: "r"(dst), "l"(src));
        }
#pragma unroll
        for (int i = 0; i < 16; i++) {
            int g = tid + i*256;
            int s = g & 15, row = (g >> 4) & 127, pl = g >> 11;
            uint32_t dst = ws_base + (uint32_t)(pl*32768 + row*256 + ((s ^ (row&7))*16));
            const __half* src = (pl ? g_wlo : g_whi) + (size_t)(bn+row)*FEAT + ph*128 + s*8;
            asm volatile("cp.async.cg.shared.global [%0], [%1], 16;" :: "r"(dst), "l"(src));
        }
        asm volatile("cp.async.commit_group;");
        asm volatile("cp.async.wait_group 0;");
        __syncthreads();

#pragma unroll
        for (int ks = 0; ks < 8; ks++) {
            uint32_t ahi[2][4];
#pragma unroll
            for (int mt = 0; mt < 2; mt++) {
                uint32_t rowoff = (uint32_t)((mw*32 + mt*16 + r)*256);
                uint32_t coff = (uint32_t)((ks*32 + seg*16) ^ ((r&7)*16));
                ldsm4(ahi[mt], xs_base + rowoff + coff);
            }
#pragma unroll
            for (int nt = 0; nt < 8; nt++) {
                int wrow = nw*64 + nt*8 + brow;
                uint32_t baddr = ws_base + (uint32_t)((bmid>>1)*32768 + wrow*256
                                 + (((ks*2 + (bmid&1)) ^ brow)*16));
                uint32_t bf[4];
                ldsm4(bf, baddr);
#pragma unroll
                for (int mt = 0; mt < 2; mt++) {
                    mma_f16(acc[mt][nt], ahi[mt], bf[0], bf[1]);
                    mma_f16(acc[mt][nt], ahi[mt], bf[2], bf[3]);
                }
            }
        }
    }

#pragma unroll
    for (int mt = 0; mt < 2; mt++) {
#pragma unroll
        for (int nt = 0; nt < 8; nt++) {
            int nloc = nw*64 + nt*8 + 2*l2;
            int n0 = bn + nloc;
            int m0 = bm + mw*32 + mt*16 + l4;
            int t = m0 >> 6, b = m0 & 63;
            size_t base = (size_t)t*GATES*BATCH;
            float bi0 = sbias[nloc], bi1 = sbias[nloc+1];
            g_xg[base + (size_t)n0*BATCH + b]         = acc[mt][nt][0] + bi0;
            g_xg[base + (size_t)(n0+1)*BATCH + b]     = acc[mt][nt][1] + bi1;
            g_xg[base + (size_t)n0*BATCH + b + 8]     = acc[mt][nt][2] + bi0;
            g_xg[base + (size_t)(n0+1)*BATCH + b + 8] = acc[mt][nt][3] + bi1;
        }
    }
}

// ---------------- fused persistent kernel: encoder (blocks 0..127) +
//                  decoder (blocks 128..143, independent, overlapped) ------
__device__ __forceinline__ void load_xv(int t, int kh, int bx0,
                                        const int growx[3][2], float xv[3][2][2],
                                        const float* __restrict__ eb1,
                                        const float* __restrict__ eb2)
{
    if (kh != 0 || t >= 258) return;
    if (t < 256) {
        const float* xg = g_xg + (size_t)t * GATES * BATCH;
#pragma unroll
        for (int nt = 0; nt < 3; nt++)
#pragma unroll
            for (int jj = 0; jj < 2; jj++) {
                const float* rowp = xg + (size_t)growx[nt][jj]*BATCH + bx0;
                xv[nt][jj][0] = __ldcg(rowp);
                xv[nt][jj][1] = __ldcg(rowp + 8);
            }
    } else {
        int l = t - 256;
#pragma unroll
        for (int nt = 0; nt < 3; nt++)
#pragma unroll
            for (int jj = 0; jj < 2; jj++) {
                float bb = __ldg(eb1 + l*GATES + growx[nt][jj]) +
                           __ldg(eb2 + l*GATES + growx[nt][jj]);
                xv[nt][jj][0] = bb;
                xv[nt][jj][1] = bb;
            }
    }
}

__device__ void enc_path(
    const float* __restrict__ Whh, const float* __restrict__ eWih,
    const float* __restrict__ ebih, const float* __restrict__ ebhh,
    float* __restrict__ out, char* smraw)
{
    __half* Whi = (__half*)smraw;
    __half* Wlo = Whi + RPB*WPAD;
    __half* hsm = Wlo + RPB*WPAD;
    float* gA  = (float*)((char*)hsm + 98304);
    float* gB  = gA + RPB*66;
    float* c_s = gB + RPB*66;

    const int tid  = threadIdx.x;
    const int wid  = tid >> 5;
    const int lane = tid & 31;
    const int mw   = wid & 3;
    const int kh   = wid >> 2;
    const int u0   = blockIdx.x * UPB;

    for (int e = tid; e < RPB*HID; e += 256) {
        int rr = e / HID, k = e % HID;
        int grow = (rr/UPB)*HID + u0 + (rr%UPB);
        float w = Whh[(size_t)grow*HID + k];
        __half hi = __float2half(w);
        Whi[rr*WPAD + k] = hi;
        Wlo[rr*WPAD + k] = __float2half(w - __half2float(hi));
    }
    for (int e = tid; e < UPB*BATCH; e += 256) c_s[e] = 0.f;

    uint32_t hs_base = (uint32_t)__cvta_generic_to_shared(hsm);

    const int l4 = lane >> 2;
    const int l2 = lane & 3;
    const int bmid = lane >> 3;
    const int brow = lane & 7;
    uint32_t wsmB = (uint32_t)__cvta_generic_to_shared(
                        ((bmid < 2) ? Whi : Wlo) + (size_t)brow*WPAD)
                    + (uint32_t)((bmid & 1) * 16);

    int growx[3][2];
#pragma unroll
    for (int nt = 0; nt < 3; nt++)
#pragma unroll
        for (int jj = 0; jj < 2; jj++) {
            int row = nt*8 + 2*l2 + jj;
            growx[nt][jj] = (row/UPB)*HID + u0 + (row%UPB);
        }
    const int bx0 = 16*mw + l4;

    float xv[3][2][2];
    load_xv(0, kh, bx0, growx, xv, ebih, ebhh);

    __syncthreads();

    for (int t = 0; t < 258; t++) {
        if (t >= 256) {
            const float* Wsrc = eWih + (size_t)(t - 256) * GATES * HID;
            for (int e = tid; e < RPB*HID; e += 256) {
                int rr = e / HID, k = e % HID;
                int grow = (rr/UPB)*HID + u0 + (rr%UPB);
                float w = Wsrc[(size_t)grow*HID + k];
                __half hi = __float2half(w);
                Whi[rr*WPAD + k] = hi;
                Wlo[rr*WPAD + k] = __float2half(w - __half2float(hi));
            }
            __syncthreads();
        }

        const __half* hh = g_hh[t & 1];

#pragma unroll
        for (int i = 0; i < 24; i++) {
            int g = tid + i*256;
            int s = g & 15, b = (g >> 4) & 63, c = g >> 10;
            uint32_t dst = hs_base + (uint32_t)(c*16384 + b*256 + ((s ^ (b&7))*16));
            const __half* src = hh + (size_t)b*HID + c*128 + s*8;
            asm volatile("cp.async.cg.shared.global [%0], [%1], 16;" :: "r"(dst), "l"(src));
        }
        asm volatile("cp.async.commit_group;");
        asm volatile("cp.async.wait_group 0;");
        __syncthreads();

        float acc[3][4];
#pragma unroll
        for (int nt = 0; nt < 3; nt++)
#pragma unroll
            for (int j = 0; j < 4; j++) acc[nt][j] = 0.f;

        const int rr = lane & 15, sg = lane >> 4;
        const uint32_t rowoff = (uint32_t)((16*mw + rr)*256);
        const uint32_t swz = (uint32_t)((rr&7)*16);
#pragma unroll
        for (int p = 0; p < 3; p++) {
            const int c = 3*kh + p;
            uint32_t subb = hs_base + (uint32_t)(c*16384);
            uint32_t kbyte0 = (uint32_t)(c*256);
#pragma unroll
            for (int ks = 0; ks < 8; ks++) {
                uint32_t coff = (uint32_t)(ks*32 + sg*16) ^ swz;
                uint32_t ahi[4];
                ldsm4(ahi, subb + rowoff + coff);
                uint32_t kb = kbyte0 + (uint32_t)(ks*32);
#pragma unroll
                for (int nt = 0; nt < 3; nt++) {
                    uint32_t bf[4];
                    ldsm4(bf, wsmB + (uint32_t)(nt*8*WPAD*2) + kb);
                    mma_f16(acc[nt], ahi, bf[0], bf[1]);
                    mma_f16(acc[nt], ahi, bf[2], bf[3]);
                }
            }
        }

        float* dst = kh ? gB : gA;
#pragma unroll
        for (int nt = 0; nt < 3; nt++) {
            int r0 = nt*8 + 2*l2;
            if (kh == 0) {
                dst[(r0  )*66 + bx0    ] = acc[nt][0] + xv[nt][0][0];
                dst[(r0+1)*66 + bx0    ] = acc[nt][1] + xv[nt][1][0];
                dst[(r0  )*66 + bx0 + 8] = acc[nt][2] + xv[nt][0][1];
                dst[(r0+1)*66 + bx0 + 8] = acc[nt][3] + xv[nt][1][1];
            } else {
                dst[(r0  )*66 + bx0    ] = acc[nt][0];
                dst[(r0+1)*66 + bx0    ] = acc[nt][1];
                dst[(r0  )*66 + bx0 + 8] = acc[nt][2];
                dst[(r0+1)*66 + bx0 + 8] = acc[nt][3];
            }
        }
        __syncthreads();

        __half* oh = g_hh[(t+1)&1];
        for (int e = tid; e < UPB*BATCH; e += 256) {
            int u = e % UPB, b = e / UPB;
            float iv = gA[(u)       *66 + b] + gB[(u)       *66 + b];
            float fv = gA[(UPB  +u) *66 + b] + gB[(UPB  +u) *66 + b];
            float gv = gA[(2*UPB+u) *66 + b] + gB[(2*UPB+u) *66 + b];
            float ov = gA[(3*UPB+u) *66 + b] + gB[(3*UPB+u) *66 + b];
            float cn, hn;
            if (t < 256) {
                float cp = c_s[e];
                cn = sigf(fv) * cp + sigf(iv) * tanhfast(gv);
                c_s[e] = cn;
            } else {
                cn = sigf(iv) * tanhfast(gv);
            }
            hn = sigf(ov) * tanhfast(cn);
            int idx = b*HID + u0 + u;
            oh[idx] = __float2half(hn);
            if (t == 255) out[OUT_ENC_OFF + idx] = hn;
            else if (t == 256) out[OUT_ENC_OFF + BATCH*HID + idx] = hn;
            else if (t == 257) out[OUT_ENC_OFF + 2*BATCH*HID + idx] = hn;
        }

        __syncthreads();
        if (tid == 0) bar_arrive(&g_bar);
        load_xv(t + 1, kh, bx0, growx, xv, ebih, ebhh);
        if (tid == 0) {
            unsigned target = (unsigned)(t + 1) * NB;
            while (bar_poll(&g_bar) < target) {}
        }
        __syncthreads();
    }
}

// decoder path: 16 blocks, 48 units each; gate rows {i,g,o} = 144/block.
// 72 rows smem-resident fp32, 72 streamed from L2. fp32-exact.
__device__ void dec_path(
    const float* __restrict__ W2, const float* __restrict__ db1,
    const float* __restrict__ db2, const float* __restrict__ linW,
    const float* __restrict__ linb, float* __restrict__ out, char* smraw)
{
    float* Ws   = (float*)smraw;            // 72*768
    float* hbuf = Ws + SROWS*HID;           // 768
    float* gs   = hbuf + HID;               // 144
    float* bs   = gs + 144;                 // 144
    float* osv  = bs + 144;                 // 16
    float* lbs  = osv + 16;                 // 16

    const int tid = threadIdx.x;
    const int blk = blockIdx.x - NB;        // 0..15
    const int u0 = blk * DUPB;
    const int f0 = blk * 16;

    // local row e<144: gate G[e/48] in {0,2,3}, unit j=e%48
    for (int e = tid; e < SROWS*(HID/4); e += 256) {
        int r = e / (HID/4), c4 = e % (HID/4);
        int gi = r / DUPB;                  // 0 or 1
        int grow = (gi == 0 ? 0 : 2)*HID + u0 + (r % DUPB);
        ((float4*)Ws)[e] = ((const float4*)(W2 + (size_t)grow*HID))[c4];
    }
    if (tid < 144) {
        int gi = tid / DUPB;
        int gg = (gi == 0) ? 0 : (gi == 1 ? 2 : 3);
        int grow = gg*HID + u0 + (tid % DUPB);
        bs[tid] = db1[grow] + db2[grow];
    }
    if (tid < 16) lbs[tid] = linb[f0 + tid];
    __syncthreads();

    for (int t = 0; t < TLEN; t++) {
        for (int e = tid; e < HID; e += 256) hbuf[e] = __ldcg(&g_hd[t&1][e]);
        __syncthreads();

        if (tid < 144) {
            float sum = 0.f;
            const float4* h4 = (const float4*)hbuf;
            if (tid < SROWS) {
                const float4* W4 = (const float4*)(Ws + tid*HID);
#pragma unroll 8
                for (int m = 0; m < HID/4; m++) {
                    float4 wv = W4[m]; float4 hv = h4[m];
                    sum += wv.x*hv.x + wv.y*hv.y + wv.z*hv.z + wv.w*hv.w;
                }
            } else {
                int gi = tid / DUPB;        // 1 or 2
                int gg = (gi == 1) ? 2 : 3;
                int grow = gg*HID + u0 + (tid % DUPB);
                const float4* W4 = (const float4*)(W2 + (size_t)grow*HID);
#pragma unroll 8
                for (int m = 0; m < HID/4; m++) {
                    float4 wv = __ldg(&W4[m]); float4 hv = h4[m];
                    sum += wv.x*hv.x + wv.y*hv.y + wv.z*hv.z + wv.w*hv.w;
                }
            }
            gs[tid] = sum + bs[tid];
        }
        __syncthreads();
        if (tid < DUPB) {
            float cn = sigf(gs[tid]) * tanhfast(gs[48 + tid]);
            float hn = sigf(gs[96 + tid]) * tanhfast(cn);
            __stcg(&g_hd[(t+1)&1][u0 + tid], hn);
        }
        __syncthreads();
        if (tid == 0) {
            bar_arrive(&g_bar2);
            unsigned target = (unsigned)(t + 1) * DNB;
            while (bar_poll(&g_bar2) < target) {}
        }
        __syncthreads();

        for (int e = tid; e < HID; e += 256) hbuf[e] = __ldcg(&g_hd[(t+1)&1][e]);
        __syncthreads();
        {
            int fl = tid >> 4, s = tid & 15;
            const float4* W4 = (const float4*)(linW + (size_t)(f0 + fl)*HID);
            const float4* h4 = (const float4*)hbuf;
            float p = 0.f;
#pragma unroll
            for (int m = 0; m < 12; m++) {
                float4 wv = __ldg(&W4[s + 16*m]); float4 hv = h4[s + 16*m];
                p += wv.x*hv.x + wv.y*hv.y + wv.z*hv.z + wv.w*hv.w;
            }
#pragma unroll
            for (int off = 8; off > 0; off >>= 1)
                p += __shfl_down_sync(0xffffffffu, p, off, 16);
            if (s == 0) osv[fl] = p + lbs[fl];
        }
        __syncthreads();
        for (int e = tid; e < BATCH*16; e += 256) {
            int b = e >> 4, fl = e & 15;
            out[(size_t)t*BATCH*FEAT + b*FEAT + f0 + fl] = osv[fl];
        }
        __syncthreads();
    }
}

__global__ __launch_bounds__(256) void k_encdec(
    const float* __restrict__ Whh, const float* __restrict__ eWih,
    const float* __restrict__ ebih, const float* __restrict__ ebhh,
    const float* __restrict__ W2, const float* __restrict__ db1,
    const float* __restrict__ db2, const float* __restrict__ linW,
    const float* __restrict__ linb, float* __restrict__ out)
{
    extern __shared__ char smraw[];
    if (blockIdx.x < NB)
        enc_path(Whh, eWih, ebih, ebhh, out, smraw);
    else
        dec_path(W2, db1, db2, linW, linb, out, smraw);
}

extern "C" void kernel_launch(void* const* d_in, const int* in_sizes, int n_in,
                              void* d_out, int out_size)
{
    const float* x     = (const float*)d_in[0];
    const float* Wih0  = (const float*)d_in[1];
    const float* Whh0  = (const float*)d_in[2];
    const float* bih0  = (const float*)d_in[3];
    const float* bhh0  = (const float*)d_in[4];
    const float* eWih  = (const float*)d_in[5];
    const float* ebih  = (const float*)d_in[7];
    const float* ebhh  = (const float*)d_in[8];
    const float* dWih  = (const float*)d_in[9];
    const float* dbih  = (const float*)d_in[11];
    const float* dbhh  = (const float*)d_in[12];
    const float* linW  = (const float*)d_in[13];
    const float* linb  = (const float*)d_in[14];
    float* out = (float*)d_out;

    __half *p_xh, *p_whi, *p_wlo;
    cudaGetSymbolAddress((void**)&p_xh,  g_xh);
    cudaGetSymbolAddress((void**)&p_whi, g_whi);
    cudaGetSymbolAddress((void**)&p_wlo, g_wlo);

    // enc layout 187008 B; dec layout 225536 B -> request max
    const int fused_smem = (SROWS*HID + HID + 144 + 144 + 16 + 16) * 4;
    const int xg_smem  = 98304 + 132*4;

    static int smem_set = 0;
    if (!smem_set) {
        cudaFuncSetAttribute(k_encdec, cudaFuncAttributeMaxDynamicSharedMemorySize, fused_smem);
        cudaFuncSetAttribute(k_xg_mma, cudaFuncAttributeMaxDynamicSharedMemorySize, xg_smem);
        smem_set = 1;
    }

    k_init<<<192, 256>>>();
    k_cvt1<<<(XM*FEAT + 511)/512, 512>>>(x, p_xh, XM*FEAT);
    k_cvt2<<<(GATES*FEAT + 511)/512, 512>>>(Wih0, p_whi, p_wlo, GATES*FEAT);
    k_xg_mma<<<dim3(24, 128), 256, xg_smem>>>(bih0, bhh0);

    k_encdec<<<NB + DNB, 256, fused_smem>>>(
        Whh0, eWih, ebih, ebhh,
        dWih + (size_t)2 * GATES * HID, dbih + 2 * GATES, dbhh + 2 * GATES,
        linW, linb, out);
}